// round 1
// baseline (speedup 1.0000x reference)
#include <cuda_runtime.h>
#include <math.h>

#define BB 2
#define LL 4
#define SS 2048
#define DD 1024
#define HH 16
#define HDD 64
#define MLPD 4096
#define EPSV 1e-5f
#define BSR (BB*SS)      /* 4096 rows (b,s) */
#define BLSR (BB*LL*SS)  /* 16384 rows (b,l,s) */

// ---------------- scratch (static device globals; no allocation) ----------------
static __device__ float g_normsum[(size_t)BSR*DD];          // 16 MB
static __device__ float g_Y[(size_t)3*BLSR*DD];             // 192 MB (raw qkv GEMM out)
static __device__ float g_qh[(size_t)BSR*DD];               // [B,H,S,HD]
static __device__ float g_kh[(size_t)BSR*DD];
static __device__ float g_vh[(size_t)BSR*DD];
static __device__ float g_ctx[(size_t)BSR*DD];              // attn out in [B,S,D]
static __device__ float g_proj[(size_t)BSR*DD];
static __device__ float g_out1[(size_t)BSR*DD];
static __device__ float g_ffn1[(size_t)BSR*MLPD];           // 64 MB
static __device__ float g_ffn2[(size_t)BSR*DD];

// ---------------- helpers ----------------
__device__ __forceinline__ float2 blockReduce2(float s1, float s2, float* sh) {
    const unsigned FULL = 0xffffffffu;
#pragma unroll
    for (int o = 16; o; o >>= 1) {
        s1 += __shfl_xor_sync(FULL, s1, o);
        s2 += __shfl_xor_sync(FULL, s2, o);
    }
    int lane = threadIdx.x & 31, w = threadIdx.x >> 5;
    if (lane == 0) { sh[w] = s1; sh[8 + w] = s2; }
    __syncthreads();
    float t1 = 0.f, t2 = 0.f;
#pragma unroll
    for (int i = 0; i < 8; i++) { t1 += sh[i]; t2 += sh[8 + i]; }
    __syncthreads();
    return make_float2(t1, t2);
}

// ---------------- K1: sum over L of layernorm-core (no g/be) ----------------
__global__ __launch_bounds__(256) void normsum_kernel(const float* __restrict__ lo) {
    __shared__ float sh[16];
    int row = blockIdx.x;            // b*S+s
    int b = row / SS, s = row % SS;
    int t = threadIdx.x;
    float4 acc = make_float4(0.f, 0.f, 0.f, 0.f);
    for (int l = 0; l < LL; l++) {
        const float4* p = (const float4*)(lo + ((size_t)((b*LL + l)*SS + s))*DD);
        float4 v = p[t];
        float s1 = v.x + v.y + v.z + v.w;
        float s2 = v.x*v.x + v.y*v.y + v.z*v.z + v.w*v.w;
        float2 tot = blockReduce2(s1, s2, sh);
        float mu = tot.x * (1.f/DD);
        float var = tot.y * (1.f/DD) - mu*mu;
        float r = rsqrtf(var + EPSV);
        acc.x += (v.x - mu)*r;
        acc.y += (v.y - mu)*r;
        acc.z += (v.z - mu)*r;
        acc.w += (v.w - mu)*r;
    }
    ((float4*)(g_normsum + (size_t)row*DD))[t] = acc;
}

// ---------------- SGEMM: C[M,N] = A[M,K] @ B[K,N], all row-major; M,N%128==0, K%8==0 ----------------
__global__ __launch_bounds__(256) void sgemm128(const float* __restrict__ A,
                                                const float* __restrict__ Bm,
                                                float* __restrict__ C,
                                                int M, int N, int K) {
    __shared__ float As[8][128];
    __shared__ float Bs[8][128];
    int tid = threadIdx.x;
    int bx = blockIdx.x, by = blockIdx.y;
    int a_row = tid >> 1, a_col = (tid & 1) << 2;
    int b_row = tid >> 5, b_col = (tid & 31) << 2;
    int ty = tid >> 4, tx = tid & 15;
    const float* Ap = A + (size_t)(by*128 + a_row)*K + a_col;
    const float* Bp = Bm + (size_t)b_row*N + bx*128 + b_col;
    float acc[8][8];
#pragma unroll
    for (int i = 0; i < 8; i++)
#pragma unroll
        for (int j = 0; j < 8; j++) acc[i][j] = 0.f;

    for (int k0 = 0; k0 < K; k0 += 8) {
        float4 av = *(const float4*)(Ap + k0);
        As[a_col + 0][a_row] = av.x;
        As[a_col + 1][a_row] = av.y;
        As[a_col + 2][a_row] = av.z;
        As[a_col + 3][a_row] = av.w;
        *(float4*)&Bs[b_row][b_col] = *(const float4*)(Bp + (size_t)k0*N);
        __syncthreads();
#pragma unroll
        for (int kk = 0; kk < 8; kk++) {
            float ar[8], br[8];
            *(float4*)(ar)     = *(const float4*)&As[kk][ty*8];
            *(float4*)(ar + 4) = *(const float4*)&As[kk][ty*8 + 4];
            *(float4*)(br)     = *(const float4*)&Bs[kk][tx*8];
            *(float4*)(br + 4) = *(const float4*)&Bs[kk][tx*8 + 4];
#pragma unroll
            for (int i = 0; i < 8; i++)
#pragma unroll
                for (int j = 0; j < 8; j++)
                    acc[i][j] += ar[i]*br[j];
        }
        __syncthreads();
    }
    float* Cp = C + (size_t)(by*128 + ty*8)*N + bx*128 + tx*8;
#pragma unroll
    for (int i = 0; i < 8; i++) {
        *(float4*)(Cp + (size_t)i*N)     = make_float4(acc[i][0], acc[i][1], acc[i][2], acc[i][3]);
        *(float4*)(Cp + (size_t)i*N + 4) = make_float4(acc[i][4], acc[i][5], acc[i][6], acc[i][7]);
    }
}

// ---------------- K3: relu-sum over L + g*normsum + L*be; write q/k/v in [B,H,S,HD] ----------------
__global__ __launch_bounds__(256) void grn_reduce_kernel(
        const float* __restrict__ bq, const float* __restrict__ gq, const float* __restrict__ beq,
        const float* __restrict__ bk, const float* __restrict__ gk, const float* __restrict__ bek,
        const float* __restrict__ bv, const float* __restrict__ gv, const float* __restrict__ bev) {
    int row = blockIdx.x;            // b*S+s
    int b = row / SS, s = row % SS;
    int t = threadIdx.x;
    int d0 = t * 4;
    float4 ns = ((const float4*)(g_normsum + (size_t)row*DD))[t];
    int h = d0 >> 6, hd = d0 & 63;
    size_t outIdx = (((size_t)(b*HH + h)*SS + s)*HDD + hd) >> 2;

    const float* Ybase[3] = { g_Y, g_Y + (size_t)BLSR*DD, g_Y + (size_t)2*BLSR*DD };
    float* outs[3] = { g_qh, g_kh, g_vh };
    const float* bias_[3] = { bq, bk, bv };
    const float* gain_[3] = { gq, gk, gv };
    const float* beta_[3] = { beq, bek, bev };

#pragma unroll
    for (int c = 0; c < 3; c++) {
        float4 bb = ((const float4*)bias_[c])[t];
        float4 gg = ((const float4*)gain_[c])[t];
        float4 ee = ((const float4*)beta_[c])[t];
        float4 a = make_float4(0.f, 0.f, 0.f, 0.f);
        for (int l = 0; l < LL; l++) {
            const float4* Yp = (const float4*)(Ybase[c] + ((size_t)((b*LL + l)*SS + s))*DD);
            float4 y = Yp[t];
            a.x += fmaxf(y.x + bb.x, 0.f);
            a.y += fmaxf(y.y + bb.y, 0.f);
            a.z += fmaxf(y.z + bb.z, 0.f);
            a.w += fmaxf(y.w + bb.w, 0.f);
        }
        float4 o;
        o.x = a.x + gg.x*ns.x + LL*ee.x;
        o.y = a.y + gg.y*ns.y + LL*ee.y;
        o.z = a.z + gg.z*ns.z + LL*ee.z;
        o.w = a.w + gg.w*ns.w + LL*ee.w;
        ((float4*)outs[c])[outIdx] = o;
    }
}

// ---------------- K4: flash attention (64 q rows x full K), write [B,S,D] directly ----------------
#define ATTN_SMEM ((3*4096 + 64*65) * (int)sizeof(float))
__global__ __launch_bounds__(256) void attn_kernel() {
    extern __shared__ float sm[];
    float* Qs = sm;               // 64x64
    float* Ks = sm + 4096;        // 64x64
    float* Vs = sm + 8192;        // 64x64
    float* Ps = sm + 12288;       // 64x65

    int qt = blockIdx.x;          // 0..31
    int bh = blockIdx.y;          // 0..31  (b*H + h)
    int b = bh / HH, h = bh % HH;
    int t = threadIdx.x;

    const float* Qg = g_qh + ((size_t)bh*SS + qt*64)*HDD;
    const float* Kg = g_kh + (size_t)bh*SS*HDD;
    const float* Vg = g_vh + (size_t)bh*SS*HDD;

#pragma unroll
    for (int i = 0; i < 4; i++)
        ((float4*)Qs)[t + i*256] = ((const float4*)Qg)[t + i*256];

    int qi = t >> 2, g = t & 3;
    float m_r = -INFINITY, l_r = 0.f;
    float acc[16];
#pragma unroll
    for (int i = 0; i < 16; i++) acc[i] = 0.f;

    for (int kt = 0; kt < SS/64; kt++) {
        __syncthreads();   // previous PV done; also covers initial Q load
        const float4* Kg4 = (const float4*)(Kg + (size_t)kt*64*HDD);
        const float4* Vg4 = (const float4*)(Vg + (size_t)kt*64*HDD);
#pragma unroll
        for (int i = 0; i < 4; i++) {
            ((float4*)Ks)[t + i*256] = Kg4[t + i*256];
            ((float4*)Vs)[t + i*256] = Vg4[t + i*256];
        }
        __syncthreads();

        // scores for (qi, kj in [g*16, g*16+16))
        float sc[16];
        const float4* qrow = (const float4*)(Qs + qi*64);
#pragma unroll
        for (int j = 0; j < 16; j++) {
            int kj = g*16 + j;
            const float4* krow = (const float4*)(Ks + kj*64);
            float sum = 0.f;
#pragma unroll
            for (int d4 = 0; d4 < 16; d4++) {
                float4 a = qrow[d4], c = krow[d4];
                sum += a.x*c.x + a.y*c.y + a.z*c.z + a.w*c.w;
            }
            sc[j] = sum * 0.125f;   // HD^-0.5
        }
        float tm = sc[0];
#pragma unroll
        for (int j = 1; j < 16; j++) tm = fmaxf(tm, sc[j]);
        tm = fmaxf(tm, __shfl_xor_sync(0xffffffffu, tm, 1));
        tm = fmaxf(tm, __shfl_xor_sync(0xffffffffu, tm, 2));
        float mn = fmaxf(m_r, tm);
        float scale = expf(m_r - mn);   // exp(-inf)=0 on first tile
        float ps = 0.f;
#pragma unroll
        for (int j = 0; j < 16; j++) {
            float p = expf(sc[j] - mn);
            Ps[qi*65 + g*16 + j] = p;
            ps += p;
        }
        ps += __shfl_xor_sync(0xffffffffu, ps, 1);
        ps += __shfl_xor_sync(0xffffffffu, ps, 2);
        l_r = l_r*scale + ps;
        m_r = mn;
#pragma unroll
        for (int i = 0; i < 16; i++) acc[i] *= scale;
        __syncwarp();   // P row written by my 4-lane group (same warp)

#pragma unroll
        for (int kj = 0; kj < 64; kj++) {
            float p = Ps[qi*65 + kj];
            const float4* vrow = (const float4*)(Vs + kj*64 + g*16);
            float4 v0 = vrow[0], v1 = vrow[1], v2 = vrow[2], v3 = vrow[3];
            acc[0]  += p*v0.x; acc[1]  += p*v0.y; acc[2]  += p*v0.z; acc[3]  += p*v0.w;
            acc[4]  += p*v1.x; acc[5]  += p*v1.y; acc[6]  += p*v1.z; acc[7]  += p*v1.w;
            acc[8]  += p*v2.x; acc[9]  += p*v2.y; acc[10] += p*v2.z; acc[11] += p*v2.w;
            acc[12] += p*v3.x; acc[13] += p*v3.y; acc[14] += p*v3.z; acc[15] += p*v3.w;
        }
    }
    float inv = 1.f / l_r;
    int sglob = qt*64 + qi;
    float* outp = g_ctx + ((size_t)(b*SS + sglob))*DD + h*HDD + g*16;
#pragma unroll
    for (int i = 0; i < 4; i++)
        ((float4*)outp)[i] = make_float4(acc[i*4]*inv, acc[i*4+1]*inv, acc[i*4+2]*inv, acc[i*4+3]*inv);
}

// ---------------- residual + layernorm(pre + bias) ----------------
__global__ __launch_bounds__(256) void ln_residual_kernel(
        const float* __restrict__ resid, const float* __restrict__ pre,
        const float* __restrict__ bias, const float* __restrict__ gam,
        const float* __restrict__ bet, float* __restrict__ out) {
    __shared__ float sh[16];
    int row = blockIdx.x, t = threadIdx.x;
    float4 p = ((const float4*)(pre + (size_t)row*DD))[t];
    float4 bb = ((const float4*)bias)[t];
    p.x += bb.x; p.y += bb.y; p.z += bb.z; p.w += bb.w;
    float s1 = p.x + p.y + p.z + p.w;
    float s2 = p.x*p.x + p.y*p.y + p.z*p.z + p.w*p.w;
    float2 tot = blockReduce2(s1, s2, sh);
    float mu = tot.x * (1.f/DD);
    float var = tot.y * (1.f/DD) - mu*mu;
    float r = rsqrtf(var + EPSV);
    float4 gg = ((const float4*)gam)[t];
    float4 ee = ((const float4*)bet)[t];
    float4 rr = ((const float4*)(resid + (size_t)row*DD))[t];
    float4 o;
    o.x = rr.x + (p.x - mu)*r*gg.x + ee.x;
    o.y = rr.y + (p.y - mu)*r*gg.y + ee.y;
    o.z = rr.z + (p.z - mu)*r*gg.z + ee.z;
    o.w = rr.w + (p.w - mu)*r*gg.w + ee.w;
    ((float4*)(out + (size_t)row*DD))[t] = o;
}

// ---------------- exact GeLU: x * Phi(x), with bias, in-place ----------------
__global__ __launch_bounds__(256) void gelu_bias_kernel(float* __restrict__ y,
                                                        const float* __restrict__ b1) {
    size_t i = ((size_t)blockIdx.x*256 + threadIdx.x) * 4;
    float4 v = *(float4*)(y + i);
    int col = (int)(i & (MLPD - 1));
    float4 bb = *(const float4*)(b1 + col);
    v.x += bb.x; v.y += bb.y; v.z += bb.z; v.w += bb.w;
    v.x *= normcdff(v.x);
    v.y *= normcdff(v.y);
    v.z *= normcdff(v.z);
    v.w *= normcdff(v.w);
    *(float4*)(y + i) = v;
}

// ---------------- host ----------------
extern "C" void kernel_launch(void* const* d_in, const int* in_sizes, int n_in,
                              void* d_out, int out_size) {
    const float* x   = (const float*)d_in[0];
    const float* lo  = (const float*)d_in[1];
    const float* qW  = (const float*)d_in[2];
    const float* qb  = (const float*)d_in[3];
    const float* qg  = (const float*)d_in[4];
    const float* qbe = (const float*)d_in[5];
    const float* kW  = (const float*)d_in[6];
    const float* kb  = (const float*)d_in[7];
    const float* kg  = (const float*)d_in[8];
    const float* kbe = (const float*)d_in[9];
    const float* vW  = (const float*)d_in[10];
    const float* vb  = (const float*)d_in[11];
    const float* vg  = (const float*)d_in[12];
    const float* vbe = (const float*)d_in[13];
    const float* oW  = (const float*)d_in[14];
    const float* ob  = (const float*)d_in[15];
    const float* ang = (const float*)d_in[16];
    const float* anb = (const float*)d_in[17];
    const float* W1  = (const float*)d_in[18];
    const float* b1  = (const float*)d_in[19];
    const float* W2  = (const float*)d_in[20];
    const float* b2  = (const float*)d_in[21];
    const float* fng = (const float*)d_in[22];
    const float* fnb = (const float*)d_in[23];
    float* out = (float*)d_out;

    void* p;
    cudaGetSymbolAddress(&p, g_Y);    float* Y    = (float*)p;
    cudaGetSymbolAddress(&p, g_ctx);  float* ctx  = (float*)p;
    cudaGetSymbolAddress(&p, g_proj); float* proj = (float*)p;
    cudaGetSymbolAddress(&p, g_out1); float* out1 = (float*)p;
    cudaGetSymbolAddress(&p, g_ffn1); float* ffn1 = (float*)p;
    cudaGetSymbolAddress(&p, g_ffn2); float* ffn2 = (float*)p;

    cudaFuncSetAttribute(attn_kernel, cudaFuncAttributeMaxDynamicSharedMemorySize, ATTN_SMEM);

    // 1. sum of LN cores over L
    normsum_kernel<<<BSR, 256>>>(lo);

    // 2. qkv relu-branch GEMMs: [16384,1024]@[1024,1024]
    dim3 gqkv(DD/128, BLSR/128);
    sgemm128<<<gqkv, 256>>>(lo, qW, Y,                      BLSR, DD, DD);
    sgemm128<<<gqkv, 256>>>(lo, kW, Y + (size_t)BLSR*DD,    BLSR, DD, DD);
    sgemm128<<<gqkv, 256>>>(lo, vW, Y + (size_t)2*BLSR*DD,  BLSR, DD, DD);

    // 3. relu-sum + norm epilogue -> q/k/v [B,H,S,HD]
    grn_reduce_kernel<<<BSR, 256>>>(qb, qg, qbe, kb, kg, kbe, vb, vg, vbe);

    // 4. attention -> ctx [B,S,D]
    attn_kernel<<<dim3(SS/64, BB*HH), 256, ATTN_SMEM>>>();

    // 5. out projection + residual/LN
    sgemm128<<<dim3(DD/128, BSR/128), 256>>>(ctx, oW, proj, BSR, DD, DD);
    ln_residual_kernel<<<BSR, 256>>>(x, proj, ob, ang, anb, out1);

    // 6. FFN
    sgemm128<<<dim3(MLPD/128, BSR/128), 256>>>(out1, W1, ffn1, BSR, MLPD, DD);
    gelu_bias_kernel<<<(BSR*(MLPD/4))/256, 256>>>(ffn1, b1);
    sgemm128<<<dim3(DD/128, BSR/128), 256>>>(ffn1, W2, ffn2, BSR, DD, MLPD);
    ln_residual_kernel<<<BSR, 256>>>(out1, ffn2, b2, fng, fnb, out);
}

// round 3
// speedup vs baseline: 1.4133x; 1.4133x over previous
#include <cuda_runtime.h>
#include <cuda_bf16.h>
#include <math.h>
#include <stdint.h>

typedef __nv_bfloat16 bf16;

#define BB 2
#define LL 4
#define SS 2048
#define DD 1024
#define HH 16
#define HDD 64
#define MLPD 4096
#define EPSV 1e-5f
#define BSR (BB*SS)      /* 4096 rows (b,s) */
#define BLSR (BB*LL*SS)  /* 16384 rows (b,l,s) */

// ================= scratch (static device globals; no allocation) =================
static __device__ float g_normsum[(size_t)BSR*DD];
static __device__ float g_Y[(size_t)3*BLSR*DD];             // qkv GEMM out (fp32)
static __device__ float g_qh[(size_t)BSR*DD];               // [B,H,S,HD]
static __device__ float g_kh[(size_t)BSR*DD];
static __device__ float g_vh[(size_t)BSR*DD];
static __device__ float g_ctx[(size_t)BSR*DD];
static __device__ float g_proj[(size_t)BSR*DD];
static __device__ float g_out1[(size_t)BSR*DD];
static __device__ float g_ffn1[(size_t)BSR*MLPD];
static __device__ float g_ffn2[(size_t)BSR*DD];

// bf16 split planes (hi/lo)
static __device__ bf16 g_loh[(size_t)BLSR*DD];
static __device__ bf16 g_lol[(size_t)BLSR*DD];
static __device__ bf16 g_wqh[(size_t)DD*DD],  g_wql[(size_t)DD*DD];
static __device__ bf16 g_wkh[(size_t)DD*DD],  g_wkl[(size_t)DD*DD];
static __device__ bf16 g_wvh[(size_t)DD*DD],  g_wvl[(size_t)DD*DD];
static __device__ bf16 g_woh[(size_t)DD*DD],  g_wol[(size_t)DD*DD];
static __device__ bf16 g_w1h[(size_t)MLPD*DD], g_w1l[(size_t)MLPD*DD];  // [N=4096, K=1024]
static __device__ bf16 g_w2h[(size_t)DD*MLPD], g_w2l[(size_t)DD*MLPD];  // [N=1024, K=4096]
static __device__ bf16 g_ctxh[(size_t)BSR*DD],  g_ctxl[(size_t)BSR*DD];
static __device__ bf16 g_o1h[(size_t)BSR*DD],   g_o1l[(size_t)BSR*DD];
static __device__ bf16 g_f1h[(size_t)BSR*MLPD], g_f1l[(size_t)BSR*MLPD];

// ================= PTX helpers (sm_80-era features only; valid on sm_103 base) =================
__device__ __forceinline__ uint32_t smem_u32(const void* p) {
    uint32_t a;
    asm("{ .reg .u64 t; cvta.to.shared.u64 t, %1; cvt.u32.u64 %0, t; }" : "=r"(a) : "l"(p));
    return a;
}
__device__ __forceinline__ void cpasync16(uint32_t dst, const void* src) {
    asm volatile("cp.async.cg.shared.global [%0], [%1], 16;" :: "r"(dst), "l"(src));
}
#define CP_COMMIT() asm volatile("cp.async.commit_group;" ::: "memory")
#define CP_WAIT0()  asm volatile("cp.async.wait_group 0;" ::: "memory")
#define CP_WAIT1()  asm volatile("cp.async.wait_group 1;" ::: "memory")

__device__ __forceinline__ void ldsm4(uint32_t* r, uint32_t addr) {
    asm volatile("ldmatrix.sync.aligned.m8n8.x4.shared.b16 {%0,%1,%2,%3}, [%4];"
        : "=r"(r[0]), "=r"(r[1]), "=r"(r[2]), "=r"(r[3]) : "r"(addr));
}
__device__ __forceinline__ void mma16816(float* d, const uint32_t* a, const uint32_t* b) {
    asm volatile("mma.sync.aligned.m16n8k16.row.col.f32.bf16.bf16.f32 "
        "{%0,%1,%2,%3}, {%4,%5,%6,%7}, {%8,%9}, {%0,%1,%2,%3};"
        : "+f"(d[0]), "+f"(d[1]), "+f"(d[2]), "+f"(d[3])
        : "r"(a[0]), "r"(a[1]), "r"(a[2]), "r"(a[3]), "r"(b[0]), "r"(b[1]));
}

// ================= mma.sync bf16x3 GEMM =================
// C[M,N] = A[M,K] @ W[K,N]; A as hi/lo bf16 planes row-major [M,K];
// W pre-transposed+split to [N,K] hi/lo planes (col-major B for row.col mma).
#define TMt 128
#define TNt 128
#define TKt 32
// smem: 4 planes (Ah,Al,Bh,Bl) x 128 rows x 32 bf16 (64B) = 8KB each, 32KB/stage, x2 stages
#define PL_AH 0
#define PL_AL 8192
#define PL_BH 16384
#define PL_BL 24576
#define STAGE_B 32768
#define GEMM_SMEM 65536

struct GemmArgs {
    const bf16* Ah; const bf16* Al;
    const bf16* Bh[3]; const bf16* Bl[3];
    float* C[3];
    int M, N, K;
};

__device__ __forceinline__ void load_stage(uint32_t st,
        const bf16* __restrict__ Ah, const bf16* __restrict__ Al,
        const bf16* __restrict__ Bh, const bf16* __restrict__ Bl,
        int K, int kt, int tid) {
    const bf16* gsrc[4] = { Ah, Al, Bh, Bl };
#pragma unroll
    for (int p = 0; p < 4; p++) {
        const bf16* g = gsrc[p] + kt * TKt;
#pragma unroll
        for (int i = tid; i < 512; i += 256) {
            int r = i >> 2, c = i & 3;
            uint32_t d = st + p * 8192 + r * 64 + (((c ^ ((r >> 1) & 3))) << 4);
            cpasync16(d, g + (size_t)r * K + c * 8);
        }
    }
    CP_COMMIT();
}

__global__ __launch_bounds__(256, 1) void gemm_mma(const GemmArgs args) {
    extern __shared__ char smem[];
    uint32_t sb = smem_u32(smem);
    int tid = threadIdx.x, lane = tid & 31, wid = tid >> 5;
    int wm = wid >> 2, wn = wid & 3;          // 2 x 4 warp grid; warp tile 64m x 32n
    int z = blockIdx.z;
    const int K = args.K, N = args.N;
    const bf16* Ah = args.Ah + (size_t)(blockIdx.y * TMt) * K;
    const bf16* Al = args.Al + (size_t)(blockIdx.y * TMt) * K;
    const bf16* Bh = args.Bh[z] + (size_t)(blockIdx.x * TNt) * K;
    const bf16* Bl = args.Bl[z] + (size_t)(blockIdx.x * TNt) * K;

    float acc[4][4][4];
#pragma unroll
    for (int i = 0; i < 4; i++)
#pragma unroll
        for (int j = 0; j < 4; j++)
#pragma unroll
            for (int c = 0; c < 4; c++) acc[i][j][c] = 0.f;

    // precompute per-thread ldmatrix row offsets (byte) + swizzle keys
    int lrow = lane & 15, lchunk = lane >> 4;    // x4: lanes 0-15 -> k-lo matrices, 16-31 -> k-hi
    uint32_t aRowOff[4], aSwz[4], bRowOff[2], bSwz[2];
#pragma unroll
    for (int mt = 0; mt < 4; mt++) {
        int r = wm * 64 + mt * 16 + lrow;
        aRowOff[mt] = r * 64; aSwz[mt] = (r >> 1) & 3;
    }
#pragma unroll
    for (int p = 0; p < 2; p++) {
        int r = wn * 32 + p * 16 + lrow;
        bRowOff[p] = r * 64; bSwz[p] = (r >> 1) & 3;
    }

    const int nch = K / TKt;
    load_stage(sb, Ah, Al, Bh, Bl, K, 0, tid);

    for (int kt = 0; kt < nch; kt++) {
        int buf = kt & 1;
        if (kt + 1 < nch) {
            load_stage(sb + (buf ^ 1) * STAGE_B, Ah, Al, Bh, Bl, K, kt + 1, tid);
            CP_WAIT1();
        } else {
            CP_WAIT0();
        }
        __syncthreads();

        uint32_t st = sb + buf * STAGE_B;
#pragma unroll
        for (int s = 0; s < 2; s++) {
            uint32_t ch = (uint32_t)(s * 2 + lchunk);
            uint32_t aF[4][4], bHf[4][2], bLf[4][2];
#pragma unroll
            for (int mt = 0; mt < 4; mt++)
                ldsm4(aF[mt], st + PL_AH + aRowOff[mt] + ((ch ^ aSwz[mt]) << 4));
#pragma unroll
            for (int p = 0; p < 2; p++) {
                uint32_t t[4];
                ldsm4(t, st + PL_BH + bRowOff[p] + ((ch ^ bSwz[p]) << 4));
                bHf[2*p][0] = t[0]; bHf[2*p][1] = t[2];
                bHf[2*p+1][0] = t[1]; bHf[2*p+1][1] = t[3];
                ldsm4(t, st + PL_BL + bRowOff[p] + ((ch ^ bSwz[p]) << 4));
                bLf[2*p][0] = t[0]; bLf[2*p][1] = t[2];
                bLf[2*p+1][0] = t[1]; bLf[2*p+1][1] = t[3];
            }
#pragma unroll
            for (int mt = 0; mt < 4; mt++)
#pragma unroll
                for (int nt = 0; nt < 4; nt++) mma16816(acc[mt][nt], aF[mt], bHf[nt]);
#pragma unroll
            for (int mt = 0; mt < 4; mt++)
#pragma unroll
                for (int nt = 0; nt < 4; nt++) mma16816(acc[mt][nt], aF[mt], bLf[nt]);
#pragma unroll
            for (int mt = 0; mt < 4; mt++)
                ldsm4(aF[mt], st + PL_AL + aRowOff[mt] + ((ch ^ aSwz[mt]) << 4));
#pragma unroll
            for (int mt = 0; mt < 4; mt++)
#pragma unroll
                for (int nt = 0; nt < 4; nt++) mma16816(acc[mt][nt], aF[mt], bHf[nt]);
        }
        __syncthreads();
    }

    // epilogue: fp32 accumulators -> C
    int g = lane >> 2, tc = lane & 3;
    float* Cz = args.C[z];
#pragma unroll
    for (int mt = 0; mt < 4; mt++) {
        int row = blockIdx.y * TMt + wm * 64 + mt * 16 + g;
#pragma unroll
        for (int nt = 0; nt < 4; nt++) {
            int col = blockIdx.x * TNt + wn * 32 + nt * 8 + tc * 2;
            *(float2*)&Cz[(size_t)row * N + col]       = make_float2(acc[mt][nt][0], acc[mt][nt][1]);
            *(float2*)&Cz[(size_t)(row + 8) * N + col] = make_float2(acc[mt][nt][2], acc[mt][nt][3]);
        }
    }
}

// ================= split / prep kernels =================
__device__ __forceinline__ void split1(float v, bf16& h, bf16& l) {
    h = __float2bfloat16_rn(v);
    l = __float2bfloat16_rn(v - __bfloat162float(h));
}

__global__ __launch_bounds__(256) void split_kernel(const float* __restrict__ x,
                                                    bf16* __restrict__ oh, bf16* __restrict__ ol) {
    size_t i = (size_t)blockIdx.x * 256 + threadIdx.x;
    float4 v = ((const float4*)x)[i];
    bf16 hx, lx, hy, ly, hz, lz, hw, lw;
    split1(v.x, hx, lx); split1(v.y, hy, ly); split1(v.z, hz, lz); split1(v.w, hw, lw);
    ((__nv_bfloat162*)oh)[2 * i]     = __nv_bfloat162(hx, hy);
    ((__nv_bfloat162*)oh)[2 * i + 1] = __nv_bfloat162(hz, hw);
    ((__nv_bfloat162*)ol)[2 * i]     = __nv_bfloat162(lx, ly);
    ((__nv_bfloat162*)ol)[2 * i + 1] = __nv_bfloat162(lz, lw);
}

__global__ __launch_bounds__(256) void gelu_split_kernel(const float* __restrict__ y, const float* __restrict__ b1,
                                                         bf16* __restrict__ oh, bf16* __restrict__ ol) {
    size_t i = (size_t)blockIdx.x * 256 + threadIdx.x;
    float4 v = ((const float4*)y)[i];
    int col = (int)((i * 4) & (MLPD - 1));
    float4 bb = *(const float4*)(b1 + col);
    v.x += bb.x; v.y += bb.y; v.z += bb.z; v.w += bb.w;
    v.x *= normcdff(v.x); v.y *= normcdff(v.y); v.z *= normcdff(v.z); v.w *= normcdff(v.w);
    bf16 hx, lx, hy, ly, hz, lz, hw, lw;
    split1(v.x, hx, lx); split1(v.y, hy, ly); split1(v.z, hz, lz); split1(v.w, hw, lw);
    ((__nv_bfloat162*)oh)[2 * i]     = __nv_bfloat162(hx, hy);
    ((__nv_bfloat162*)oh)[2 * i + 1] = __nv_bfloat162(hz, hw);
    ((__nv_bfloat162*)ol)[2 * i]     = __nv_bfloat162(lx, ly);
    ((__nv_bfloat162*)ol)[2 * i + 1] = __nv_bfloat162(lz, lw);
}

// W [K,N] fp32 -> out [N,K] bf16 hi/lo (transpose + split)
__global__ __launch_bounds__(256) void wsplit_kernel(const float* __restrict__ W,
                                                     bf16* __restrict__ oh, bf16* __restrict__ ol,
                                                     int K, int N) {
    __shared__ float tile[32][33];
    int n0 = blockIdx.x * 32, k0 = blockIdx.y * 32;
    int tx = threadIdx.x & 31, ty = threadIdx.x >> 5;
#pragma unroll
    for (int i = 0; i < 4; i++)
        tile[ty + 8 * i][tx] = W[(size_t)(k0 + ty + 8 * i) * N + n0 + tx];
    __syncthreads();
#pragma unroll
    for (int i = 0; i < 4; i++) {
        float v = tile[tx][ty + 8 * i];
        bf16 h, l; split1(v, h, l);
        size_t o = (size_t)(n0 + ty + 8 * i) * K + k0 + tx;
        oh[o] = h; ol[o] = l;
    }
}

// ================= elementwise / reduction kernels =================
__device__ __forceinline__ float2 blockReduce2(float s1, float s2, float* sh) {
    const unsigned FULL = 0xffffffffu;
#pragma unroll
    for (int o = 16; o; o >>= 1) {
        s1 += __shfl_xor_sync(FULL, s1, o);
        s2 += __shfl_xor_sync(FULL, s2, o);
    }
    int lane = threadIdx.x & 31, w = threadIdx.x >> 5;
    if (lane == 0) { sh[w] = s1; sh[8 + w] = s2; }
    __syncthreads();
    float t1 = 0.f, t2 = 0.f;
#pragma unroll
    for (int i = 0; i < 8; i++) { t1 += sh[i]; t2 += sh[8 + i]; }
    __syncthreads();
    return make_float2(t1, t2);
}

__global__ __launch_bounds__(256) void normsum_kernel(const float* __restrict__ lo) {
    __shared__ float sh[16];
    int row = blockIdx.x;
    int b = row / SS, s = row % SS;
    int t = threadIdx.x;
    float4 acc = make_float4(0.f, 0.f, 0.f, 0.f);
    for (int l = 0; l < LL; l++) {
        const float4* p = (const float4*)(lo + ((size_t)((b*LL + l)*SS + s))*DD);
        float4 v = p[t];
        float s1 = v.x + v.y + v.z + v.w;
        float s2 = v.x*v.x + v.y*v.y + v.z*v.z + v.w*v.w;
        float2 tot = blockReduce2(s1, s2, sh);
        float mu = tot.x * (1.f/DD);
        float var = tot.y * (1.f/DD) - mu*mu;
        float r = rsqrtf(var + EPSV);
        acc.x += (v.x - mu)*r; acc.y += (v.y - mu)*r;
        acc.z += (v.z - mu)*r; acc.w += (v.w - mu)*r;
    }
    ((float4*)(g_normsum + (size_t)row*DD))[t] = acc;
}

__global__ __launch_bounds__(256) void grn_reduce_kernel(
        const float* __restrict__ bq, const float* __restrict__ gq, const float* __restrict__ beq,
        const float* __restrict__ bk, const float* __restrict__ gk, const float* __restrict__ bek,
        const float* __restrict__ bv, const float* __restrict__ gv, const float* __restrict__ bev) {
    int row = blockIdx.x;
    int b = row / SS, s = row % SS;
    int t = threadIdx.x;
    int d0 = t * 4;
    float4 ns = ((const float4*)(g_normsum + (size_t)row*DD))[t];
    int h = d0 >> 6, hd = d0 & 63;
    size_t outIdx = (((size_t)(b*HH + h)*SS + s)*HDD + hd) >> 2;

    const float* Ybase[3] = { g_Y, g_Y + (size_t)BLSR*DD, g_Y + (size_t)2*BLSR*DD };
    float* outs[3] = { g_qh, g_kh, g_vh };
    const float* bias_[3] = { bq, bk, bv };
    const float* gain_[3] = { gq, gk, gv };
    const float* beta_[3] = { beq, bek, bev };

#pragma unroll
    for (int c = 0; c < 3; c++) {
        float4 bb = ((const float4*)bias_[c])[t];
        float4 gg = ((const float4*)gain_[c])[t];
        float4 ee = ((const float4*)beta_[c])[t];
        float4 a = make_float4(0.f, 0.f, 0.f, 0.f);
        for (int l = 0; l < LL; l++) {
            const float4* Yp = (const float4*)(Ybase[c] + ((size_t)((b*LL + l)*SS + s))*DD);
            float4 y = Yp[t];
            a.x += fmaxf(y.x + bb.x, 0.f); a.y += fmaxf(y.y + bb.y, 0.f);
            a.z += fmaxf(y.z + bb.z, 0.f); a.w += fmaxf(y.w + bb.w, 0.f);
        }
        float4 o;
        o.x = a.x + gg.x*ns.x + LL*ee.x;
        o.y = a.y + gg.y*ns.y + LL*ee.y;
        o.z = a.z + gg.z*ns.z + LL*ee.z;
        o.w = a.w + gg.w*ns.w + LL*ee.w;
        ((float4*)outs[c])[outIdx] = o;
    }
}

#define ATTN_SMEM ((3*4096 + 64*65) * (int)sizeof(float))
__global__ __launch_bounds__(256) void attn_kernel() {
    extern __shared__ float sm[];
    float* Qs = sm;
    float* Ks = sm + 4096;
    float* Vs = sm + 8192;
    float* Ps = sm + 12288;

    int qt = blockIdx.x;
    int bh = blockIdx.y;
    int b = bh / HH, h = bh % HH;
    int t = threadIdx.x;

    const float* Qg = g_qh + ((size_t)bh*SS + qt*64)*HDD;
    const float* Kg = g_kh + (size_t)bh*SS*HDD;
    const float* Vg = g_vh + (size_t)bh*SS*HDD;

#pragma unroll
    for (int i = 0; i < 4; i++)
        ((float4*)Qs)[t + i*256] = ((const float4*)Qg)[t + i*256];

    int qi = t >> 2, g = t & 3;
    float m_r = -INFINITY, l_r = 0.f;
    float acc[16];
#pragma unroll
    for (int i = 0; i < 16; i++) acc[i] = 0.f;

    for (int kt = 0; kt < SS/64; kt++) {
        __syncthreads();
        const float4* Kg4 = (const float4*)(Kg + (size_t)kt*64*HDD);
        const float4* Vg4 = (const float4*)(Vg + (size_t)kt*64*HDD);
#pragma unroll
        for (int i = 0; i < 4; i++) {
            ((float4*)Ks)[t + i*256] = Kg4[t + i*256];
            ((float4*)Vs)[t + i*256] = Vg4[t + i*256];
        }
        __syncthreads();

        float sc[16];
        const float4* qrow = (const float4*)(Qs + qi*64);
#pragma unroll
        for (int j = 0; j < 16; j++) {
            int kj = g*16 + j;
            const float4* krow = (const float4*)(Ks + kj*64);
            float sum = 0.f;
#pragma unroll
            for (int d4 = 0; d4 < 16; d4++) {
                float4 a = qrow[d4], c = krow[d4];
                sum += a.x*c.x + a.y*c.y + a.z*c.z + a.w*c.w;
            }
            sc[j] = sum * 0.125f;
        }
        float tm = sc[0];
#pragma unroll
        for (int j = 1; j < 16; j++) tm = fmaxf(tm, sc[j]);
        tm = fmaxf(tm, __shfl_xor_sync(0xffffffffu, tm, 1));
        tm = fmaxf(tm, __shfl_xor_sync(0xffffffffu, tm, 2));
        float mn = fmaxf(m_r, tm);
        float scale = expf(m_r - mn);
        float ps = 0.f;
#pragma unroll
        for (int j = 0; j < 16; j++) {
            float p = expf(sc[j] - mn);
            Ps[qi*65 + g*16 + j] = p;
            ps += p;
        }
        ps += __shfl_xor_sync(0xffffffffu, ps, 1);
        ps += __shfl_xor_sync(0xffffffffu, ps, 2);
        l_r = l_r*scale + ps;
        m_r = mn;
#pragma unroll
        for (int i = 0; i < 16; i++) acc[i] *= scale;
        __syncwarp();

#pragma unroll
        for (int kj = 0; kj < 64; kj++) {
            float p = Ps[qi*65 + kj];
            const float4* vrow = (const float4*)(Vs + kj*64 + g*16);
            float4 v0 = vrow[0], v1 = vrow[1], v2 = vrow[2], v3 = vrow[3];
            acc[0]  += p*v0.x; acc[1]  += p*v0.y; acc[2]  += p*v0.z; acc[3]  += p*v0.w;
            acc[4]  += p*v1.x; acc[5]  += p*v1.y; acc[6]  += p*v1.z; acc[7]  += p*v1.w;
            acc[8]  += p*v2.x; acc[9]  += p*v2.y; acc[10] += p*v2.z; acc[11] += p*v2.w;
            acc[12] += p*v3.x; acc[13] += p*v3.y; acc[14] += p*v3.z; acc[15] += p*v3.w;
        }
    }
    float inv = 1.f / l_r;
    int sglob = qt*64 + qi;
    float* outp = g_ctx + ((size_t)(b*SS + sglob))*DD + h*HDD + g*16;
#pragma unroll
    for (int i = 0; i < 4; i++)
        ((float4*)outp)[i] = make_float4(acc[i*4]*inv, acc[i*4+1]*inv, acc[i*4+2]*inv, acc[i*4+3]*inv);
}

__global__ __launch_bounds__(256) void ln_residual_kernel(
        const float* __restrict__ resid, const float* __restrict__ pre,
        const float* __restrict__ bias, const float* __restrict__ gam,
        const float* __restrict__ bet, float* __restrict__ out) {
    __shared__ float sh[16];
    int row = blockIdx.x, t = threadIdx.x;
    float4 p = ((const float4*)(pre + (size_t)row*DD))[t];
    float4 bb = ((const float4*)bias)[t];
    p.x += bb.x; p.y += bb.y; p.z += bb.z; p.w += bb.w;
    float s1 = p.x + p.y + p.z + p.w;
    float s2 = p.x*p.x + p.y*p.y + p.z*p.z + p.w*p.w;
    float2 tot = blockReduce2(s1, s2, sh);
    float mu = tot.x * (1.f/DD);
    float var = tot.y * (1.f/DD) - mu*mu;
    float r = rsqrtf(var + EPSV);
    float4 gg = ((const float4*)gam)[t];
    float4 ee = ((const float4*)bet)[t];
    float4 rr = ((const float4*)(resid + (size_t)row*DD))[t];
    float4 o;
    o.x = rr.x + (p.x - mu)*r*gg.x + ee.x;
    o.y = rr.y + (p.y - mu)*r*gg.y + ee.y;
    o.z = rr.z + (p.z - mu)*r*gg.z + ee.z;
    o.w = rr.w + (p.w - mu)*r*gg.w + ee.w;
    ((float4*)(out + (size_t)row*DD))[t] = o;
}

// ================= host =================
static void* symaddr(const void* sym) { void* p; cudaGetSymbolAddress(&p, sym); return p; }

extern "C" void kernel_launch(void* const* d_in, const int* in_sizes, int n_in,
                              void* d_out, int out_size) {
    const float* x   = (const float*)d_in[0];
    const float* lo  = (const float*)d_in[1];
    const float* qW  = (const float*)d_in[2];
    const float* qb  = (const float*)d_in[3];
    const float* qg  = (const float*)d_in[4];
    const float* qbe = (const float*)d_in[5];
    const float* kW  = (const float*)d_in[6];
    const float* kb  = (const float*)d_in[7];
    const float* kg  = (const float*)d_in[8];
    const float* kbe = (const float*)d_in[9];
    const float* vW  = (const float*)d_in[10];
    const float* vb  = (const float*)d_in[11];
    const float* vg  = (const float*)d_in[12];
    const float* vbe = (const float*)d_in[13];
    const float* oW  = (const float*)d_in[14];
    const float* ob  = (const float*)d_in[15];
    const float* ang = (const float*)d_in[16];
    const float* anb = (const float*)d_in[17];
    const float* W1  = (const float*)d_in[18];
    const float* b1  = (const float*)d_in[19];
    const float* W2  = (const float*)d_in[20];
    const float* b2  = (const float*)d_in[21];
    const float* fng = (const float*)d_in[22];
    const float* fnb = (const float*)d_in[23];
    float* out = (float*)d_out;

    float* Y    = (float*)symaddr(g_Y);
    float* ctx  = (float*)symaddr(g_ctx);
    float* proj = (float*)symaddr(g_proj);
    float* out1 = (float*)symaddr(g_out1);
    float* ffn1 = (float*)symaddr(g_ffn1);
    float* ffn2 = (float*)symaddr(g_ffn2);
    bf16 *loh = (bf16*)symaddr(g_loh), *lol = (bf16*)symaddr(g_lol);
    bf16 *wqh = (bf16*)symaddr(g_wqh), *wql = (bf16*)symaddr(g_wql);
    bf16 *wkh = (bf16*)symaddr(g_wkh), *wkl = (bf16*)symaddr(g_wkl);
    bf16 *wvh = (bf16*)symaddr(g_wvh), *wvl = (bf16*)symaddr(g_wvl);
    bf16 *woh = (bf16*)symaddr(g_woh), *wol = (bf16*)symaddr(g_wol);
    bf16 *w1h = (bf16*)symaddr(g_w1h), *w1l = (bf16*)symaddr(g_w1l);
    bf16 *w2h = (bf16*)symaddr(g_w2h), *w2l = (bf16*)symaddr(g_w2l);
    bf16 *ctxh = (bf16*)symaddr(g_ctxh), *ctxl = (bf16*)symaddr(g_ctxl);
    bf16 *o1h = (bf16*)symaddr(g_o1h), *o1l = (bf16*)symaddr(g_o1l);
    bf16 *f1h = (bf16*)symaddr(g_f1h), *f1l = (bf16*)symaddr(g_f1l);

    cudaFuncSetAttribute(attn_kernel, cudaFuncAttributeMaxDynamicSharedMemorySize, ATTN_SMEM);
    cudaFuncSetAttribute(gemm_mma, cudaFuncAttributeMaxDynamicSharedMemorySize, GEMM_SMEM);

    // ---- weight prep (transpose + split) ----
    wsplit_kernel<<<dim3(DD/32, DD/32), 256>>>(qW, wqh, wql, DD, DD);
    wsplit_kernel<<<dim3(DD/32, DD/32), 256>>>(kW, wkh, wkl, DD, DD);
    wsplit_kernel<<<dim3(DD/32, DD/32), 256>>>(vW, wvh, wvl, DD, DD);
    wsplit_kernel<<<dim3(DD/32, DD/32), 256>>>(oW, woh, wol, DD, DD);
    wsplit_kernel<<<dim3(MLPD/32, DD/32), 256>>>(W1, w1h, w1l, DD, MLPD);
    wsplit_kernel<<<dim3(DD/32, MLPD/32), 256>>>(W2, w2h, w2l, MLPD, DD);

    // ---- activation split + normsum ----
    split_kernel<<<((size_t)BLSR*DD/4)/256, 256>>>(lo, loh, lol);
    normsum_kernel<<<BSR, 256>>>(lo);

    // ---- QKV GEMMs (one fused launch, z = q/k/v) ----
    {
        GemmArgs a;
        a.Ah = loh; a.Al = lol;
        a.Bh[0] = wqh; a.Bl[0] = wql; a.C[0] = Y;
        a.Bh[1] = wkh; a.Bl[1] = wkl; a.C[1] = Y + (size_t)BLSR*DD;
        a.Bh[2] = wvh; a.Bl[2] = wvl; a.C[2] = Y + (size_t)2*BLSR*DD;
        a.M = BLSR; a.N = DD; a.K = DD;
        gemm_mma<<<dim3(DD/TNt, BLSR/TMt, 3), 256, GEMM_SMEM>>>(a);
    }

    grn_reduce_kernel<<<BSR, 256>>>(qb, qg, qbe, kb, kg, kbe, vb, vg, vbe);
    attn_kernel<<<dim3(SS/64, BB*HH), 256, ATTN_SMEM>>>();

    // ---- attn out projection ----
    split_kernel<<<((size_t)BSR*DD/4)/256, 256>>>(ctx, ctxh, ctxl);
    {
        GemmArgs a = {};
        a.Ah = ctxh; a.Al = ctxl;
        a.Bh[0] = woh; a.Bl[0] = wol; a.C[0] = proj;
        a.M = BSR; a.N = DD; a.K = DD;
        gemm_mma<<<dim3(DD/TNt, BSR/TMt, 1), 256, GEMM_SMEM>>>(a);
    }
    ln_residual_kernel<<<BSR, 256>>>(x, proj, ob, ang, anb, out1);

    // ---- FFN ----
    split_kernel<<<((size_t)BSR*DD/4)/256, 256>>>(out1, o1h, o1l);
    {
        GemmArgs a = {};
        a.Ah = o1h; a.Al = o1l;
        a.Bh[0] = w1h; a.Bl[0] = w1l; a.C[0] = ffn1;
        a.M = BSR; a.N = MLPD; a.K = DD;
        gemm_mma<<<dim3(MLPD/TNt, BSR/TMt, 1), 256, GEMM_SMEM>>>(a);
    }
    gelu_split_kernel<<<((size_t)BSR*MLPD/4)/256, 256>>>(ffn1, b1, f1h, f1l);
    {
        GemmArgs a = {};
        a.Ah = f1h; a.Al = f1l;
        a.Bh[0] = w2h; a.Bl[0] = w2l; a.C[0] = ffn2;
        a.M = BSR; a.N = DD; a.K = MLPD;
        gemm_mma<<<dim3(DD/TNt, BSR/TMt, 1), 256, GEMM_SMEM>>>(a);
    }
    ln_residual_kernel<<<BSR, 256>>>(out1, ffn2, b2, fng, fnb, out);
}

// round 4
// speedup vs baseline: 4.7302x; 3.3468x over previous
#include <cuda_runtime.h>
#include <cuda_bf16.h>
#include <math.h>
#include <stdint.h>

typedef __nv_bfloat16 bf16;

#define BB 2
#define LL 4
#define SS 2048
#define DD 1024
#define HH 16
#define HDD 64
#define MLPD 4096
#define EPSV 1e-5f
#define BSR (BB*SS)
#define BLSR (BB*LL*SS)

// ================= scratch =================
static __device__ float g_normsum[(size_t)BSR*DD];
static __device__ float g_proj[(size_t)BSR*DD];
static __device__ float g_out1[(size_t)BSR*DD];
static __device__ float g_ffn2[(size_t)BSR*DD];

static __device__ bf16 g_loh[(size_t)BLSR*DD], g_lol[(size_t)BLSR*DD];
static __device__ bf16 g_wqh[(size_t)DD*DD],  g_wql[(size_t)DD*DD];
static __device__ bf16 g_wkh[(size_t)DD*DD],  g_wkl[(size_t)DD*DD];
static __device__ bf16 g_wvh[(size_t)DD*DD],  g_wvl[(size_t)DD*DD];
static __device__ bf16 g_woh[(size_t)DD*DD],  g_wol[(size_t)DD*DD];
static __device__ bf16 g_w1h[(size_t)MLPD*DD], g_w1l[(size_t)MLPD*DD];
static __device__ bf16 g_w2h[(size_t)DD*MLPD], g_w2l[(size_t)DD*MLPD];
// q/k/v bf16 hi/lo planes in [B,H,S,HD]
static __device__ bf16 g_qph[(size_t)BSR*DD], g_qpl[(size_t)BSR*DD];
static __device__ bf16 g_kph[(size_t)BSR*DD], g_kpl[(size_t)BSR*DD];
static __device__ bf16 g_vph[(size_t)BSR*DD], g_vpl[(size_t)BSR*DD];
static __device__ bf16 g_cxh[(size_t)BSR*DD], g_cxl[(size_t)BSR*DD];
static __device__ bf16 g_o1h[(size_t)BSR*DD], g_o1l[(size_t)BSR*DD];
static __device__ bf16 g_f1h[(size_t)BSR*MLPD], g_f1l[(size_t)BSR*MLPD];

// ================= PTX helpers =================
__device__ __forceinline__ uint32_t smem_u32(const void* p) {
    uint32_t a;
    asm("{ .reg .u64 t; cvta.to.shared.u64 t, %1; cvt.u32.u64 %0, t; }" : "=r"(a) : "l"(p));
    return a;
}
__device__ __forceinline__ void cpasync16(uint32_t dst, const void* src) {
    asm volatile("cp.async.cg.shared.global [%0], [%1], 16;" :: "r"(dst), "l"(src));
}
#define CP_COMMIT() asm volatile("cp.async.commit_group;" ::: "memory")
#define CP_WAIT0()  asm volatile("cp.async.wait_group 0;" ::: "memory")
#define CP_WAIT1()  asm volatile("cp.async.wait_group 1;" ::: "memory")

__device__ __forceinline__ void ldsm4(uint32_t* r, uint32_t addr) {
    asm volatile("ldmatrix.sync.aligned.m8n8.x4.shared.b16 {%0,%1,%2,%3}, [%4];"
        : "=r"(r[0]), "=r"(r[1]), "=r"(r[2]), "=r"(r[3]) : "r"(addr));
}
__device__ __forceinline__ void ldsm4t(uint32_t* r, uint32_t addr) {
    asm volatile("ldmatrix.sync.aligned.m8n8.x4.trans.shared.b16 {%0,%1,%2,%3}, [%4];"
        : "=r"(r[0]), "=r"(r[1]), "=r"(r[2]), "=r"(r[3]) : "r"(addr));
}
__device__ __forceinline__ void mma16816(float* d, const uint32_t* a, const uint32_t* b) {
    asm volatile("mma.sync.aligned.m16n8k16.row.col.f32.bf16.bf16.f32 "
        "{%0,%1,%2,%3}, {%4,%5,%6,%7}, {%8,%9}, {%0,%1,%2,%3};"
        : "+f"(d[0]), "+f"(d[1]), "+f"(d[2]), "+f"(d[3])
        : "r"(a[0]), "r"(a[1]), "r"(a[2]), "r"(a[3]), "r"(b[0]), "r"(b[1]));
}
__device__ __forceinline__ void split1(float v, bf16& h, bf16& l) {
    h = __float2bfloat16_rn(v);
    l = __float2bfloat16_rn(v - __bfloat162float(h));
}
__device__ __forceinline__ void split2u(float a, float b, uint32_t& hi, uint32_t& lo) {
    bf16 ha, la, hb, lb;
    split1(a, ha, la); split1(b, hb, lb);
    __nv_bfloat162 H(ha, hb), L(la, lb);
    hi = *(uint32_t*)&H; lo = *(uint32_t*)&L;
}

// ================= generic mma GEMM (128x128 tile, K chunk 32) =================
#define PL_AH 0
#define PL_AL 8192
#define PL_BH 16384
#define PL_BL 24576
#define STAGE_B 32768
#define GEMM_SMEM 65536

__device__ __forceinline__ void load_stage(uint32_t st,
        const bf16* __restrict__ Ah, const bf16* __restrict__ Al,
        const bf16* __restrict__ Bh, const bf16* __restrict__ Bl,
        int K, int kt, int tid) {
    const bf16* gsrc[4] = { Ah, Al, Bh, Bl };
#pragma unroll
    for (int p = 0; p < 4; p++) {
        const bf16* g = gsrc[p] + kt * 32;
#pragma unroll
        for (int i = tid; i < 512; i += 256) {
            int r = i >> 2, c = i & 3;
            uint32_t d = st + p * 8192 + r * 64 + (((c ^ ((r >> 1) & 3))) << 4);
            cpasync16(d, g + (size_t)r * K + c * 8);
        }
    }
    CP_COMMIT();
}

// core K loop: accumulates into acc[4][4][4]
__device__ __forceinline__ void gemm_core(uint32_t sb, float acc[4][4][4],
        const bf16* Ah, const bf16* Al, const bf16* Bh, const bf16* Bl,
        int K, int tid, const uint32_t* aRowOff, const uint32_t* aSwz,
        const uint32_t* bRowOff, const uint32_t* bSwz, int lchunk) {
    const int nch = K / 32;
    load_stage(sb, Ah, Al, Bh, Bl, K, 0, tid);
    for (int kt = 0; kt < nch; kt++) {
        int buf = kt & 1;
        if (kt + 1 < nch) {
            load_stage(sb + (buf ^ 1) * STAGE_B, Ah, Al, Bh, Bl, K, kt + 1, tid);
            CP_WAIT1();
        } else {
            CP_WAIT0();
        }
        __syncthreads();
        uint32_t st = sb + buf * STAGE_B;
#pragma unroll
        for (int s = 0; s < 2; s++) {
            uint32_t ch = (uint32_t)(s * 2 + lchunk);
            uint32_t aF[4][4], bHf[4][2], bLf[4][2];
#pragma unroll
            for (int mt = 0; mt < 4; mt++)
                ldsm4(aF[mt], st + PL_AH + aRowOff[mt] + ((ch ^ aSwz[mt]) << 4));
#pragma unroll
            for (int p = 0; p < 2; p++) {
                uint32_t t[4];
                ldsm4(t, st + PL_BH + bRowOff[p] + ((ch ^ bSwz[p]) << 4));
                bHf[2*p][0] = t[0]; bHf[2*p][1] = t[2];
                bHf[2*p+1][0] = t[1]; bHf[2*p+1][1] = t[3];
                ldsm4(t, st + PL_BL + bRowOff[p] + ((ch ^ bSwz[p]) << 4));
                bLf[2*p][0] = t[0]; bLf[2*p][1] = t[2];
                bLf[2*p+1][0] = t[1]; bLf[2*p+1][1] = t[3];
            }
#pragma unroll
            for (int mt = 0; mt < 4; mt++)
#pragma unroll
                for (int nt = 0; nt < 4; nt++) mma16816(acc[mt][nt], aF[mt], bHf[nt]);
#pragma unroll
            for (int mt = 0; mt < 4; mt++)
#pragma unroll
                for (int nt = 0; nt < 4; nt++) mma16816(acc[mt][nt], aF[mt], bLf[nt]);
#pragma unroll
            for (int mt = 0; mt < 4; mt++)
                ldsm4(aF[mt], st + PL_AL + aRowOff[mt] + ((ch ^ aSwz[mt]) << 4));
#pragma unroll
            for (int mt = 0; mt < 4; mt++)
#pragma unroll
                for (int nt = 0; nt < 4; nt++) mma16816(acc[mt][nt], aF[mt], bHf[nt]);
        }
        __syncthreads();
    }
}

struct GArgs {
    const bf16 *Ah, *Al, *Bh, *Bl;
    float* C;
    const float* bias;
    bf16 *Ch, *Cl;
    int N, K;
};

// EPI 0: fp32 C.  EPI 1: gelu(acc+bias) -> bf16 hi/lo planes.
template<int EPI>
__global__ __launch_bounds__(256, 1) void gemm_mma(const GArgs args) {
    extern __shared__ char smem[];
    uint32_t sb = smem_u32(smem);
    int tid = threadIdx.x, lane = tid & 31, wid = tid >> 5;
    int wm = wid >> 2, wn = wid & 3;
    const int K = args.K, N = args.N;
    const bf16* Ah = args.Ah + (size_t)(blockIdx.y * 128) * K;
    const bf16* Al = args.Al + (size_t)(blockIdx.y * 128) * K;
    const bf16* Bh = args.Bh + (size_t)(blockIdx.x * 128) * K;
    const bf16* Bl = args.Bl + (size_t)(blockIdx.x * 128) * K;

    float acc[4][4][4];
#pragma unroll
    for (int i = 0; i < 4; i++)
#pragma unroll
        for (int j = 0; j < 4; j++)
#pragma unroll
            for (int c = 0; c < 4; c++) acc[i][j][c] = 0.f;

    int lrow = lane & 15, lchunk = lane >> 4;
    uint32_t aRowOff[4], aSwz[4], bRowOff[2], bSwz[2];
#pragma unroll
    for (int mt = 0; mt < 4; mt++) {
        int r = wm * 64 + mt * 16 + lrow;
        aRowOff[mt] = r * 64; aSwz[mt] = (r >> 1) & 3;
    }
#pragma unroll
    for (int p = 0; p < 2; p++) {
        int r = wn * 32 + p * 16 + lrow;
        bRowOff[p] = r * 64; bSwz[p] = (r >> 1) & 3;
    }

    gemm_core(sb, acc, Ah, Al, Bh, Bl, K, tid, aRowOff, aSwz, bRowOff, bSwz, lchunk);

    int g = lane >> 2, tc = lane & 3;
#pragma unroll
    for (int mt = 0; mt < 4; mt++) {
        int row = blockIdx.y * 128 + wm * 64 + mt * 16 + g;
#pragma unroll
        for (int nt = 0; nt < 4; nt++) {
            int col = blockIdx.x * 128 + wn * 32 + nt * 8 + tc * 2;
            if (EPI == 0) {
                *(float2*)&args.C[(size_t)row * N + col]       = make_float2(acc[mt][nt][0], acc[mt][nt][1]);
                *(float2*)&args.C[(size_t)(row + 8) * N + col] = make_float2(acc[mt][nt][2], acc[mt][nt][3]);
            } else {
                float b0 = args.bias[col], b1 = args.bias[col + 1];
                float v0 = acc[mt][nt][0] + b0, v1 = acc[mt][nt][1] + b1;
                float v2 = acc[mt][nt][2] + b0, v3 = acc[mt][nt][3] + b1;
                v0 *= normcdff(v0); v1 *= normcdff(v1); v2 *= normcdff(v2); v3 *= normcdff(v3);
                uint32_t h01, l01, h23, l23;
                split2u(v0, v1, h01, l01);
                split2u(v2, v3, h23, l23);
                *(uint32_t*)&args.Ch[(size_t)row * N + col]       = h01;
                *(uint32_t*)&args.Cl[(size_t)row * N + col]       = l01;
                *(uint32_t*)&args.Ch[(size_t)(row + 8) * N + col] = h23;
                *(uint32_t*)&args.Cl[(size_t)(row + 8) * N + col] = l23;
            }
        }
    }
}

// ================= QKV GEMM with fused GRN epilogue =================
struct QkvArgs {
    const bf16 *Ah, *Al;                 // lo split planes [BLSR, DD]
    const bf16 *Bh[3], *Bl[3];           // weights [DD, DD] (N-major)
    const float *bias[3], *gain[3], *beta[3];
    bf16 *Oh[3], *Ol[3];                 // outputs [B,H,S,HD] hi/lo
};

__global__ __launch_bounds__(256, 1) void gemm_qkv(const QkvArgs args) {
    extern __shared__ char smem[];
    uint32_t sb = smem_u32(smem);
    int tid = threadIdx.x, lane = tid & 31, wid = tid >> 5;
    int wm = wid >> 2, wn = wid & 3;
    int z = blockIdx.z;
    int by = blockIdx.y;
    int b = (by * 128) / SS;
    int s0 = by * 128 - b * SS;
    const int K = DD;
    const bf16* Bh = args.Bh[z] + (size_t)(blockIdx.x * 128) * K;
    const bf16* Bl = args.Bl[z] + (size_t)(blockIdx.x * 128) * K;

    int lrow = lane & 15, lchunk = lane >> 4;
    uint32_t aRowOff[4], aSwz[4], bRowOff[2], bSwz[2];
#pragma unroll
    for (int mt = 0; mt < 4; mt++) {
        int r = wm * 64 + mt * 16 + lrow;
        aRowOff[mt] = r * 64; aSwz[mt] = (r >> 1) & 3;
    }
#pragma unroll
    for (int p = 0; p < 2; p++) {
        int r = wn * 32 + p * 16 + lrow;
        bRowOff[p] = r * 64; bSwz[p] = (r >> 1) & 3;
    }
    int g = lane >> 2, tc = lane & 3;

    // per-thread bias values (2 per n-tile)
    float bs0[4], bs1[4];
#pragma unroll
    for (int nt = 0; nt < 4; nt++) {
        int col = blockIdx.x * 128 + wn * 32 + nt * 8 + tc * 2;
        bs0[nt] = args.bias[z][col];
        bs1[nt] = args.bias[z][col + 1];
    }

    float sum[4][4][4];
#pragma unroll
    for (int i = 0; i < 4; i++)
#pragma unroll
        for (int j = 0; j < 4; j++)
#pragma unroll
            for (int c = 0; c < 4; c++) sum[i][j][c] = 0.f;

    for (int l = 0; l < LL; l++) {
        const bf16* Ah = args.Ah + ((size_t)((b * LL + l) * SS + s0)) * DD;
        const bf16* Al = args.Al + ((size_t)((b * LL + l) * SS + s0)) * DD;
        float acc[4][4][4];
#pragma unroll
        for (int i = 0; i < 4; i++)
#pragma unroll
            for (int j = 0; j < 4; j++)
#pragma unroll
                for (int c = 0; c < 4; c++) acc[i][j][c] = 0.f;

        gemm_core(sb, acc, Ah, Al, Bh, Bl, K, tid, aRowOff, aSwz, bRowOff, bSwz, lchunk);

#pragma unroll
        for (int mt = 0; mt < 4; mt++)
#pragma unroll
            for (int nt = 0; nt < 4; nt++) {
                sum[mt][nt][0] += fmaxf(acc[mt][nt][0] + bs0[nt], 0.f);
                sum[mt][nt][1] += fmaxf(acc[mt][nt][1] + bs1[nt], 0.f);
                sum[mt][nt][2] += fmaxf(acc[mt][nt][2] + bs0[nt], 0.f);
                sum[mt][nt][3] += fmaxf(acc[mt][nt][3] + bs1[nt], 0.f);
            }
    }

    // final: + g*normsum + L*be, write head-layout bf16 hi/lo
#pragma unroll
    for (int nt = 0; nt < 4; nt++) {
        int col = blockIdx.x * 128 + wn * 32 + nt * 8 + tc * 2;
        float gg0 = args.gain[z][col], gg1 = args.gain[z][col + 1];
        float be0 = args.beta[z][col], be1 = args.beta[z][col + 1];
        int h = col >> 6, hd = col & 63;
#pragma unroll
        for (int mt = 0; mt < 4; mt++) {
            int rl = wm * 64 + mt * 16 + g;
            int nsrow = by * 128 + rl;
            int s = s0 + rl;
            float2 ns0 = *(const float2*)&g_normsum[(size_t)nsrow * DD + col];
            float2 ns1 = *(const float2*)&g_normsum[(size_t)(nsrow + 8) * DD + col];
            float v0 = sum[mt][nt][0] + gg0 * ns0.x + LL * be0;
            float v1 = sum[mt][nt][1] + gg1 * ns0.y + LL * be1;
            float v2 = sum[mt][nt][2] + gg0 * ns1.x + LL * be0;
            float v3 = sum[mt][nt][3] + gg1 * ns1.y + LL * be1;
            uint32_t h01, l01, h23, l23;
            split2u(v0, v1, h01, l01);
            split2u(v2, v3, h23, l23);
            size_t o0 = ((size_t)(b * HH + h) * SS + s) * HDD + hd;
            size_t o1 = ((size_t)(b * HH + h) * SS + s + 8) * HDD + hd;
            *(uint32_t*)&args.Oh[z][o0] = h01;
            *(uint32_t*)&args.Ol[z][o0] = l01;
            *(uint32_t*)&args.Oh[z][o1] = h23;
            *(uint32_t*)&args.Ol[z][o1] = l23;
        }
    }
}

// ================= tensor-core flash attention =================
// block: 128 threads (4 warps), Q tile 64 rows; K tiles of 64 keys.
// smem stage: Kh 0, Kl 8K, Vh 16K, Vl 24K; 2 stages = 64KB.
#define AT_STAGE 32768
#define AT_SMEM  65536

__device__ __forceinline__ void attn_load_kv(uint32_t st, int bh, int kt, int tid) {
    const bf16* src[4] = {
        g_kph + ((size_t)bh * SS + kt * 64) * HDD,
        g_kpl + ((size_t)bh * SS + kt * 64) * HDD,
        g_vph + ((size_t)bh * SS + kt * 64) * HDD,
        g_vpl + ((size_t)bh * SS + kt * 64) * HDD };
#pragma unroll
    for (int p = 0; p < 4; p++) {
#pragma unroll
        for (int i = tid; i < 512; i += 128) {
            int r = i >> 3, c = i & 7;
            uint32_t d = st + p * 8192 + r * 128 + (((c ^ (r & 7))) << 4);
            cpasync16(d, src[p] + (size_t)r * HDD + c * 8);
        }
    }
    CP_COMMIT();
}

__global__ __launch_bounds__(128, 2) void attn_mma() {
    extern __shared__ char smem[];
    uint32_t sb = smem_u32(smem);
    int tid = threadIdx.x, lane = tid & 31, wid = tid >> 5;
    int qt = blockIdx.x, bh = blockIdx.y;
    int b = bh / HH, h = bh % HH;
    int g = lane >> 2, tc = lane & 3;
    int lrow = lane & 15, lchunk = lane >> 4;

    // ---- stage Q into smem (stage0), ldmatrix to regs ----
    {
        const bf16* qsrc[2] = {
            g_qph + ((size_t)bh * SS + qt * 64) * HDD,
            g_qpl + ((size_t)bh * SS + qt * 64) * HDD };
#pragma unroll
        for (int p = 0; p < 2; p++)
#pragma unroll
            for (int i = tid; i < 512; i += 128) {
                int r = i >> 3, c = i & 7;
                uint32_t d = sb + p * 8192 + r * 128 + (((c ^ (r & 7))) << 4);
                cpasync16(d, qsrc[p] + (size_t)r * HDD + c * 8);
            }
        CP_COMMIT(); CP_WAIT0();
        __syncthreads();
    }
    uint32_t qhF[4][4], qlF[4][4];
#pragma unroll
    for (int ks = 0; ks < 4; ks++) {
        int r = wid * 16 + lrow;
        uint32_t cc = (uint32_t)(ks * 2 + lchunk);
        uint32_t off = r * 128 + ((cc ^ (r & 7)) << 4);
        ldsm4(qhF[ks], sb + off);
        ldsm4(qlF[ks], sb + 8192 + off);
    }
    __syncthreads();

    float o[8][4];
#pragma unroll
    for (int i = 0; i < 8; i++)
#pragma unroll
        for (int c = 0; c < 4; c++) o[i][c] = 0.f;
    float m0 = -INFINITY, m1 = -INFINITY, l0 = 0.f, l1 = 0.f;
    const float ls = 0.125f * 1.44269504088896f;   // scale * log2(e)

    attn_load_kv(sb, bh, 0, tid);

    for (int kt = 0; kt < SS / 64; kt++) {
        int buf = kt & 1;
        if (kt + 1 < SS / 64) {
            attn_load_kv(sb + (buf ^ 1) * AT_STAGE, bh, kt + 1, tid);
            CP_WAIT1();
        } else {
            CP_WAIT0();
        }
        __syncthreads();
        uint32_t st = sb + buf * AT_STAGE;

        // ---- S = Q K^T (16 rows x 64 keys per warp) ----
        float S[8][4];
#pragma unroll
        for (int i = 0; i < 8; i++)
#pragma unroll
            for (int c = 0; c < 4; c++) S[i][c] = 0.f;
#pragma unroll
        for (int np = 0; np < 4; np++) {
            int r = np * 16 + lrow;
#pragma unroll
            for (int ks = 0; ks < 4; ks++) {
                uint32_t cc = (uint32_t)(ks * 2 + lchunk);
                uint32_t off = r * 128 + ((cc ^ (r & 7)) << 4);
                uint32_t tH[4], tL[4];
                ldsm4(tH, st + off);          // Kh
                ldsm4(tL, st + 8192 + off);   // Kl
                uint32_t b0h[2] = { tH[0], tH[2] }, b1h[2] = { tH[1], tH[3] };
                uint32_t b0l[2] = { tL[0], tL[2] }, b1l[2] = { tL[1], tL[3] };
                mma16816(S[2*np],   qhF[ks], b0h);
                mma16816(S[2*np+1], qhF[ks], b1h);
                mma16816(S[2*np],   qhF[ks], b0l);
                mma16816(S[2*np+1], qhF[ks], b1l);
                mma16816(S[2*np],   qlF[ks], b0h);
                mma16816(S[2*np+1], qlF[ks], b1h);
            }
        }

        // ---- online softmax (log2 domain) ----
        float tm0 = -INFINITY, tm1 = -INFINITY;
#pragma unroll
        for (int i = 0; i < 8; i++) {
            S[i][0] *= ls; S[i][1] *= ls; S[i][2] *= ls; S[i][3] *= ls;
            tm0 = fmaxf(tm0, fmaxf(S[i][0], S[i][1]));
            tm1 = fmaxf(tm1, fmaxf(S[i][2], S[i][3]));
        }
        tm0 = fmaxf(tm0, __shfl_xor_sync(0xffffffffu, tm0, 1));
        tm0 = fmaxf(tm0, __shfl_xor_sync(0xffffffffu, tm0, 2));
        tm1 = fmaxf(tm1, __shfl_xor_sync(0xffffffffu, tm1, 1));
        tm1 = fmaxf(tm1, __shfl_xor_sync(0xffffffffu, tm1, 2));
        float nm0 = fmaxf(m0, tm0), nm1 = fmaxf(m1, tm1);
        float c0 = exp2f(m0 - nm0), c1 = exp2f(m1 - nm1);
        float ps0 = 0.f, ps1 = 0.f;
#pragma unroll
        for (int i = 0; i < 8; i++) {
            S[i][0] = exp2f(S[i][0] - nm0); S[i][1] = exp2f(S[i][1] - nm0);
            S[i][2] = exp2f(S[i][2] - nm1); S[i][3] = exp2f(S[i][3] - nm1);
            ps0 += S[i][0] + S[i][1];
            ps1 += S[i][2] + S[i][3];
        }
        ps0 += __shfl_xor_sync(0xffffffffu, ps0, 1);
        ps0 += __shfl_xor_sync(0xffffffffu, ps0, 2);
        ps1 += __shfl_xor_sync(0xffffffffu, ps1, 1);
        ps1 += __shfl_xor_sync(0xffffffffu, ps1, 2);
        l0 = l0 * c0 + ps0; l1 = l1 * c1 + ps1;
        m0 = nm0; m1 = nm1;
#pragma unroll
        for (int i = 0; i < 8; i++) {
            o[i][0] *= c0; o[i][1] *= c0; o[i][2] *= c1; o[i][3] *= c1;
        }

        // ---- P fragments (hi/lo) ----
        uint32_t pH[4][4], pL[4][4];
#pragma unroll
        for (int j = 0; j < 4; j++) {
            split2u(S[2*j][0],   S[2*j][1],   pH[j][0], pL[j][0]);
            split2u(S[2*j][2],   S[2*j][3],   pH[j][1], pL[j][1]);
            split2u(S[2*j+1][0], S[2*j+1][1], pH[j][2], pL[j][2]);
            split2u(S[2*j+1][2], S[2*j+1][3], pH[j][3], pL[j][3]);
        }

        // ---- O += P V ----
#pragma unroll
        for (int j = 0; j < 4; j++) {     // key 16-groups
            int r = j * 16 + lrow;
#pragma unroll
            for (int dp = 0; dp < 4; dp++) {   // d 16-groups
                uint32_t cc = (uint32_t)(dp * 2 + lchunk);
                uint32_t off = r * 128 + ((cc ^ (r & 7)) << 4);
                uint32_t tH[4], tL[4];
                ldsm4t(tH, st + 16384 + off);   // Vh
                ldsm4t(tL, st + 24576 + off);   // Vl
                uint32_t b0h[2] = { tH[0], tH[1] }, b1h[2] = { tH[2], tH[3] };
                uint32_t b0l[2] = { tL[0], tL[1] }, b1l[2] = { tL[2], tL[3] };
                mma16816(o[2*dp],   pH[j], b0h);
                mma16816(o[2*dp+1], pH[j], b1h);
                mma16816(o[2*dp],   pH[j], b0l);
                mma16816(o[2*dp+1], pH[j], b1l);
                mma16816(o[2*dp],   pL[j], b0h);
                mma16816(o[2*dp+1], pL[j], b1h);
            }
        }
        __syncthreads();
    }

    // ---- epilogue: normalize, write ctx bf16 hi/lo ----
    float il0 = 1.f / l0, il1 = 1.f / l1;
    int srow = qt * 64 + wid * 16 + g;
#pragma unroll
    for (int nt = 0; nt < 8; nt++) {
        int col = h * HDD + nt * 8 + tc * 2;
        float v0 = o[nt][0] * il0, v1 = o[nt][1] * il0;
        float v2 = o[nt][2] * il1, v3 = o[nt][3] * il1;
        uint32_t h01, lo01, h23, lo23;
        split2u(v0, v1, h01, lo01);
        split2u(v2, v3, h23, lo23);
        size_t r0 = (size_t)(b * SS + srow) * DD + col;
        size_t r1 = (size_t)(b * SS + srow + 8) * DD + col;
        *(uint32_t*)&g_cxh[r0] = h01;
        *(uint32_t*)&g_cxl[r0] = lo01;
        *(uint32_t*)&g_cxh[r1] = h23;
        *(uint32_t*)&g_cxl[r1] = lo23;
    }
}

// ================= split / prep / LN kernels =================
__global__ __launch_bounds__(256) void split_kernel(const float* __restrict__ x,
                                                    bf16* __restrict__ oh, bf16* __restrict__ ol) {
    size_t i = (size_t)blockIdx.x * 256 + threadIdx.x;
    float4 v = ((const float4*)x)[i];
    uint32_t h01, l01, h23, l23;
    split2u(v.x, v.y, h01, l01);
    split2u(v.z, v.w, h23, l23);
    ((uint32_t*)oh)[2 * i] = h01; ((uint32_t*)oh)[2 * i + 1] = h23;
    ((uint32_t*)ol)[2 * i] = l01; ((uint32_t*)ol)[2 * i + 1] = l23;
}

__global__ __launch_bounds__(256) void wsplit_kernel(const float* __restrict__ W,
                                                     bf16* __restrict__ oh, bf16* __restrict__ ol,
                                                     int K, int N) {
    __shared__ float tile[32][33];
    int n0 = blockIdx.x * 32, k0 = blockIdx.y * 32;
    int tx = threadIdx.x & 31, ty = threadIdx.x >> 5;
#pragma unroll
    for (int i = 0; i < 4; i++)
        tile[ty + 8 * i][tx] = W[(size_t)(k0 + ty + 8 * i) * N + n0 + tx];
    __syncthreads();
#pragma unroll
    for (int i = 0; i < 4; i++) {
        float v = tile[tx][ty + 8 * i];
        bf16 hh, ll; split1(v, hh, ll);
        size_t o = (size_t)(n0 + ty + 8 * i) * K + k0 + tx;
        oh[o] = hh; ol[o] = ll;
    }
}

__device__ __forceinline__ float2 blockReduce2(float s1, float s2, float* sh) {
    const unsigned FULL = 0xffffffffu;
#pragma unroll
    for (int o = 16; o; o >>= 1) {
        s1 += __shfl_xor_sync(FULL, s1, o);
        s2 += __shfl_xor_sync(FULL, s2, o);
    }
    int lane = threadIdx.x & 31, w = threadIdx.x >> 5;
    if (lane == 0) { sh[w] = s1; sh[8 + w] = s2; }
    __syncthreads();
    float t1 = 0.f, t2 = 0.f;
#pragma unroll
    for (int i = 0; i < 8; i++) { t1 += sh[i]; t2 += sh[8 + i]; }
    __syncthreads();
    return make_float2(t1, t2);
}

__global__ __launch_bounds__(256) void normsum_kernel(const float* __restrict__ lo) {
    __shared__ float sh[16];
    int row = blockIdx.x;
    int b = row / SS, s = row % SS;
    int t = threadIdx.x;
    float4 acc = make_float4(0.f, 0.f, 0.f, 0.f);
    for (int l = 0; l < LL; l++) {
        const float4* p = (const float4*)(lo + ((size_t)((b*LL + l)*SS + s))*DD);
        float4 v = p[t];
        float s1 = v.x + v.y + v.z + v.w;
        float s2 = v.x*v.x + v.y*v.y + v.z*v.z + v.w*v.w;
        float2 tot = blockReduce2(s1, s2, sh);
        float mu = tot.x * (1.f/DD);
        float var = tot.y * (1.f/DD) - mu*mu;
        float r = rsqrtf(var + EPSV);
        acc.x += (v.x - mu)*r; acc.y += (v.y - mu)*r;
        acc.z += (v.z - mu)*r; acc.w += (v.w - mu)*r;
    }
    ((float4*)(g_normsum + (size_t)row*DD))[t] = acc;
}

// residual + LN; optionally also emit bf16 hi/lo split of result
template<int SPLIT>
__global__ __launch_bounds__(256) void ln_residual_kernel(
        const float* __restrict__ resid, const float* __restrict__ pre,
        const float* __restrict__ bias, const float* __restrict__ gam,
        const float* __restrict__ bet, float* __restrict__ out,
        bf16* __restrict__ oh, bf16* __restrict__ ol) {
    __shared__ float sh[16];
    int row = blockIdx.x, t = threadIdx.x;
    float4 p = ((const float4*)(pre + (size_t)row*DD))[t];
    float4 bb = ((const float4*)bias)[t];
    p.x += bb.x; p.y += bb.y; p.z += bb.z; p.w += bb.w;
    float s1 = p.x + p.y + p.z + p.w;
    float s2 = p.x*p.x + p.y*p.y + p.z*p.z + p.w*p.w;
    float2 tot = blockReduce2(s1, s2, sh);
    float mu = tot.x * (1.f/DD);
    float var = tot.y * (1.f/DD) - mu*mu;
    float r = rsqrtf(var + EPSV);
    float4 gg = ((const float4*)gam)[t];
    float4 ee = ((const float4*)bet)[t];
    float4 rr = ((const float4*)(resid + (size_t)row*DD))[t];
    float4 o;
    o.x = rr.x + (p.x - mu)*r*gg.x + ee.x;
    o.y = rr.y + (p.y - mu)*r*gg.y + ee.y;
    o.z = rr.z + (p.z - mu)*r*gg.z + ee.z;
    o.w = rr.w + (p.w - mu)*r*gg.w + ee.w;
    ((float4*)(out + (size_t)row*DD))[t] = o;
    if (SPLIT) {
        uint32_t h01, l01, h23, l23;
        split2u(o.x, o.y, h01, l01);
        split2u(o.z, o.w, h23, l23);
        size_t i = (size_t)row * (DD/4) + t;
        ((uint32_t*)oh)[2 * i] = h01; ((uint32_t*)oh)[2 * i + 1] = h23;
        ((uint32_t*)ol)[2 * i] = l01; ((uint32_t*)ol)[2 * i + 1] = l23;
    }
}

// ================= host =================
static void* symaddr(const void* sym) { void* p; cudaGetSymbolAddress(&p, sym); return p; }

extern "C" void kernel_launch(void* const* d_in, const int* in_sizes, int n_in,
                              void* d_out, int out_size) {
    const float* x   = (const float*)d_in[0];
    const float* lo  = (const float*)d_in[1];
    const float* qW  = (const float*)d_in[2];
    const float* qb  = (const float*)d_in[3];
    const float* qg  = (const float*)d_in[4];
    const float* qbe = (const float*)d_in[5];
    const float* kW  = (const float*)d_in[6];
    const float* kb  = (const float*)d_in[7];
    const float* kg  = (const float*)d_in[8];
    const float* kbe = (const float*)d_in[9];
    const float* vW  = (const float*)d_in[10];
    const float* vb  = (const float*)d_in[11];
    const float* vg  = (const float*)d_in[12];
    const float* vbe = (const float*)d_in[13];
    const float* oW  = (const float*)d_in[14];
    const float* ob  = (const float*)d_in[15];
    const float* ang = (const float*)d_in[16];
    const float* anb = (const float*)d_in[17];
    const float* W1  = (const float*)d_in[18];
    const float* b1  = (const float*)d_in[19];
    const float* W2  = (const float*)d_in[20];
    const float* b2  = (const float*)d_in[21];
    const float* fng = (const float*)d_in[22];
    const float* fnb = (const float*)d_in[23];
    float* out = (float*)d_out;

    float* proj = (float*)symaddr(g_proj);
    float* out1 = (float*)symaddr(g_out1);
    float* ffn2 = (float*)symaddr(g_ffn2);
    bf16 *loh = (bf16*)symaddr(g_loh), *lol = (bf16*)symaddr(g_lol);
    bf16 *wqh = (bf16*)symaddr(g_wqh), *wql = (bf16*)symaddr(g_wql);
    bf16 *wkh = (bf16*)symaddr(g_wkh), *wkl = (bf16*)symaddr(g_wkl);
    bf16 *wvh = (bf16*)symaddr(g_wvh), *wvl = (bf16*)symaddr(g_wvl);
    bf16 *woh = (bf16*)symaddr(g_woh), *wol = (bf16*)symaddr(g_wol);
    bf16 *w1h = (bf16*)symaddr(g_w1h), *w1l = (bf16*)symaddr(g_w1l);
    bf16 *w2h = (bf16*)symaddr(g_w2h), *w2l = (bf16*)symaddr(g_w2l);
    bf16 *cxh = (bf16*)symaddr(g_cxh), *cxl = (bf16*)symaddr(g_cxl);
    bf16 *o1h = (bf16*)symaddr(g_o1h), *o1l = (bf16*)symaddr(g_o1l);
    bf16 *f1h = (bf16*)symaddr(g_f1h), *f1l = (bf16*)symaddr(g_f1l);

    cudaFuncSetAttribute(gemm_mma<0>, cudaFuncAttributeMaxDynamicSharedMemorySize, GEMM_SMEM);
    cudaFuncSetAttribute(gemm_mma<1>, cudaFuncAttributeMaxDynamicSharedMemorySize, GEMM_SMEM);
    cudaFuncSetAttribute(gemm_qkv,    cudaFuncAttributeMaxDynamicSharedMemorySize, GEMM_SMEM);
    cudaFuncSetAttribute(attn_mma,    cudaFuncAttributeMaxDynamicSharedMemorySize, AT_SMEM);

    // weight prep
    wsplit_kernel<<<dim3(DD/32, DD/32), 256>>>(qW, wqh, wql, DD, DD);
    wsplit_kernel<<<dim3(DD/32, DD/32), 256>>>(kW, wkh, wkl, DD, DD);
    wsplit_kernel<<<dim3(DD/32, DD/32), 256>>>(vW, wvh, wvl, DD, DD);
    wsplit_kernel<<<dim3(DD/32, DD/32), 256>>>(oW, woh, wol, DD, DD);
    wsplit_kernel<<<dim3(MLPD/32, DD/32), 256>>>(W1, w1h, w1l, DD, MLPD);
    wsplit_kernel<<<dim3(DD/32, MLPD/32), 256>>>(W2, w2h, w2l, MLPD, DD);

    split_kernel<<<((size_t)BLSR*DD/4)/256, 256>>>(lo, loh, lol);
    normsum_kernel<<<BSR, 256>>>(lo);

    // QKV + fused GRN epilogue -> q/k/v bf16 hi/lo head layout
    {
        QkvArgs a;
        a.Ah = loh; a.Al = lol;
        a.Bh[0] = wqh; a.Bl[0] = wql; a.bias[0] = qb; a.gain[0] = qg; a.beta[0] = qbe;
        a.Bh[1] = wkh; a.Bl[1] = wkl; a.bias[1] = kb; a.gain[1] = kg; a.beta[1] = kbe;
        a.Bh[2] = wvh; a.Bl[2] = wvl; a.bias[2] = vb; a.gain[2] = vg; a.beta[2] = vbe;
        a.Oh[0] = (bf16*)symaddr(g_qph); a.Ol[0] = (bf16*)symaddr(g_qpl);
        a.Oh[1] = (bf16*)symaddr(g_kph); a.Ol[1] = (bf16*)symaddr(g_kpl);
        a.Oh[2] = (bf16*)symaddr(g_vph); a.Ol[2] = (bf16*)symaddr(g_vpl);
        gemm_qkv<<<dim3(DD/128, BSR/128, 3), 256, GEMM_SMEM>>>(a);
    }

    attn_mma<<<dim3(SS/64, BB*HH), 128, AT_SMEM>>>();

    // attn out projection (plain fp32 out)
    {
        GArgs a = {};
        a.Ah = cxh; a.Al = cxl; a.Bh = woh; a.Bl = wol;
        a.C = proj; a.N = DD; a.K = DD;
        gemm_mma<0><<<dim3(DD/128, BSR/128), 256, GEMM_SMEM>>>(a);
    }
    ln_residual_kernel<1><<<BSR, 256>>>(x, proj, ob, ang, anb, out1, o1h, o1l);

    // FFN1 with fused bias+gelu+split epilogue
    {
        GArgs a = {};
        a.Ah = o1h; a.Al = o1l; a.Bh = w1h; a.Bl = w1l;
        a.bias = b1; a.Ch = f1h; a.Cl = f1l; a.N = MLPD; a.K = DD;
        gemm_mma<1><<<dim3(MLPD/128, BSR/128), 256, GEMM_SMEM>>>(a);
    }
    // FFN2 plain
    {
        GArgs a = {};
        a.Ah = f1h; a.Al = f1l; a.Bh = w2h; a.Bl = w2l;
        a.C = ffn2; a.N = DD; a.K = MLPD;
        gemm_mma<0><<<dim3(DD/128, BSR/128), 256, GEMM_SMEM>>>(a);
    }
    ln_residual_kernel<0><<<BSR, 256>>>(out1, ffn2, b2, fng, fnb, out, nullptr, nullptr);
}

// round 8
// speedup vs baseline: 5.5434x; 1.1719x over previous
#include <cuda_runtime.h>
#include <cuda_bf16.h>
#include <math.h>
#include <stdint.h>

typedef __nv_bfloat16 bf16;

#define BB 2
#define LL 4
#define SS 2048
#define DD 1024
#define HH 16
#define HDD 64
#define MLPD 4096
#define EPSV 1e-5f
#define BSR (BB*SS)
#define BLSR (BB*LL*SS)

// ================= scratch =================
static __device__ float g_normsum[(size_t)BSR*DD];
static __device__ float g_proj[(size_t)BSR*DD];
static __device__ float g_out1[(size_t)BSR*DD];
static __device__ float g_ffn2[(size_t)BSR*DD];
static __device__ float g_qkvp[(size_t)12*BSR*DD];   // 192MB: [ch*4+l][BSR*DD] relu partials

static __device__ bf16 g_loh[(size_t)BLSR*DD], g_lol[(size_t)BLSR*DD];
static __device__ bf16 g_wqh[(size_t)DD*DD],  g_wql[(size_t)DD*DD];
static __device__ bf16 g_wkh[(size_t)DD*DD],  g_wkl[(size_t)DD*DD];
static __device__ bf16 g_wvh[(size_t)DD*DD],  g_wvl[(size_t)DD*DD];
static __device__ bf16 g_woh[(size_t)DD*DD],  g_wol[(size_t)DD*DD];
static __device__ bf16 g_w1h[(size_t)MLPD*DD], g_w1l[(size_t)MLPD*DD];
static __device__ bf16 g_w2h[(size_t)DD*MLPD], g_w2l[(size_t)DD*MLPD];
static __device__ bf16 g_qph[(size_t)BSR*DD], g_qpl[(size_t)BSR*DD];
static __device__ bf16 g_kph[(size_t)BSR*DD], g_kpl[(size_t)BSR*DD];
static __device__ bf16 g_vph[(size_t)BSR*DD], g_vpl[(size_t)BSR*DD];
static __device__ bf16 g_cxh[(size_t)BSR*DD], g_cxl[(size_t)BSR*DD];
static __device__ bf16 g_o1h[(size_t)BSR*DD], g_o1l[(size_t)BSR*DD];
static __device__ bf16 g_f1h[(size_t)BSR*MLPD], g_f1l[(size_t)BSR*MLPD];

// ================= PTX helpers =================
__device__ __forceinline__ uint32_t smem_u32(const void* p) {
    uint32_t a;
    asm("{ .reg .u64 t; cvta.to.shared.u64 t, %1; cvt.u32.u64 %0, t; }" : "=r"(a) : "l"(p));
    return a;
}
__device__ __forceinline__ void cpasync16(uint32_t dst, const void* src) {
    asm volatile("cp.async.cg.shared.global [%0], [%1], 16;" :: "r"(dst), "l"(src));
}
#define CP_COMMIT() asm volatile("cp.async.commit_group;" ::: "memory")
#define CP_WAIT0()  asm volatile("cp.async.wait_group 0;" ::: "memory")
#define CP_WAIT1()  asm volatile("cp.async.wait_group 1;" ::: "memory")

__device__ __forceinline__ void ldsm4(uint32_t* r, uint32_t addr) {
    asm volatile("ldmatrix.sync.aligned.m8n8.x4.shared.b16 {%0,%1,%2,%3}, [%4];"
        : "=r"(r[0]), "=r"(r[1]), "=r"(r[2]), "=r"(r[3]) : "r"(addr));
}
__device__ __forceinline__ void ldsm4t(uint32_t* r, uint32_t addr) {
    asm volatile("ldmatrix.sync.aligned.m8n8.x4.trans.shared.b16 {%0,%1,%2,%3}, [%4];"
        : "=r"(r[0]), "=r"(r[1]), "=r"(r[2]), "=r"(r[3]) : "r"(addr));
}
__device__ __forceinline__ void mma16816(float* d, const uint32_t* a, const uint32_t* b) {
    asm volatile("mma.sync.aligned.m16n8k16.row.col.f32.bf16.bf16.f32 "
        "{%0,%1,%2,%3}, {%4,%5,%6,%7}, {%8,%9}, {%0,%1,%2,%3};"
        : "+f"(d[0]), "+f"(d[1]), "+f"(d[2]), "+f"(d[3])
        : "r"(a[0]), "r"(a[1]), "r"(a[2]), "r"(a[3]), "r"(b[0]), "r"(b[1]));
}
__device__ __forceinline__ void split1(float v, bf16& h, bf16& l) {
    h = __float2bfloat16_rn(v);
    l = __float2bfloat16_rn(v - __bfloat162float(h));
}
__device__ __forceinline__ void split2u(float a, float b, uint32_t& hi, uint32_t& lo) {
    bf16 ha, la, hb, lb;
    split1(a, ha, la); split1(b, hb, lb);
    __nv_bfloat162 H(ha, hb), L(la, lb);
    hi = *(uint32_t*)&H; lo = *(uint32_t*)&L;
}

// ================= generic mma GEMM (128x128 tile, K chunk 32) =================
#define PL_AH 0
#define PL_AL 8192
#define PL_BH 16384
#define PL_BL 24576
#define STAGE_B 32768
#define GEMM_SMEM 65536

__device__ __forceinline__ void load_stage(uint32_t st,
        const bf16* __restrict__ Ah, const bf16* __restrict__ Al,
        const bf16* __restrict__ Bh, const bf16* __restrict__ Bl,
        int K, int kt, int tid) {
    const bf16* gsrc[4] = { Ah, Al, Bh, Bl };
#pragma unroll
    for (int p = 0; p < 4; p++) {
        const bf16* g = gsrc[p] + kt * 32;
#pragma unroll
        for (int i = tid; i < 512; i += 256) {
            int r = i >> 2, c = i & 3;
            uint32_t d = st + p * 8192 + r * 64 + (((c ^ ((r >> 1) & 3))) << 4);
            cpasync16(d, g + (size_t)r * K + c * 8);
        }
    }
    CP_COMMIT();
}

__device__ __forceinline__ void gemm_core(uint32_t sb, float acc[4][4][4],
        const bf16* Ah, const bf16* Al, const bf16* Bh, const bf16* Bl,
        int K, int tid, const uint32_t* aRowOff, const uint32_t* aSwz,
        const uint32_t* bRowOff, const uint32_t* bSwz, int lchunk) {
    const int nch = K / 32;
    load_stage(sb, Ah, Al, Bh, Bl, K, 0, tid);
    for (int kt = 0; kt < nch; kt++) {
        int buf = kt & 1;
        if (kt + 1 < nch) {
            load_stage(sb + (buf ^ 1) * STAGE_B, Ah, Al, Bh, Bl, K, kt + 1, tid);
            CP_WAIT1();
        } else {
            CP_WAIT0();
        }
        __syncthreads();
        uint32_t st = sb + buf * STAGE_B;
#pragma unroll
        for (int s = 0; s < 2; s++) {
            uint32_t ch = (uint32_t)(s * 2 + lchunk);
            uint32_t aF[4][4], bHf[4][2], bLf[4][2];
#pragma unroll
            for (int mt = 0; mt < 4; mt++)
                ldsm4(aF[mt], st + PL_AH + aRowOff[mt] + ((ch ^ aSwz[mt]) << 4));
#pragma unroll
            for (int p = 0; p < 2; p++) {
                uint32_t t[4];
                ldsm4(t, st + PL_BH + bRowOff[p] + ((ch ^ bSwz[p]) << 4));
                bHf[2*p][0] = t[0]; bHf[2*p][1] = t[2];
                bHf[2*p+1][0] = t[1]; bHf[2*p+1][1] = t[3];
                ldsm4(t, st + PL_BL + bRowOff[p] + ((ch ^ bSwz[p]) << 4));
                bLf[2*p][0] = t[0]; bLf[2*p][1] = t[2];
                bLf[2*p+1][0] = t[1]; bLf[2*p+1][1] = t[3];
            }
#pragma unroll
            for (int mt = 0; mt < 4; mt++)
#pragma unroll
                for (int nt = 0; nt < 4; nt++) mma16816(acc[mt][nt], aF[mt], bHf[nt]);
#pragma unroll
            for (int mt = 0; mt < 4; mt++)
#pragma unroll
                for (int nt = 0; nt < 4; nt++) mma16816(acc[mt][nt], aF[mt], bLf[nt]);
#pragma unroll
            for (int mt = 0; mt < 4; mt++)
                ldsm4(aF[mt], st + PL_AL + aRowOff[mt] + ((ch ^ aSwz[mt]) << 4));
#pragma unroll
            for (int mt = 0; mt < 4; mt++)
#pragma unroll
                for (int nt = 0; nt < 4; nt++) mma16816(acc[mt][nt], aF[mt], bHf[nt]);
        }
        __syncthreads();
    }
}

struct GArgs {
    const bf16 *Ah, *Al, *Bh, *Bl;
    float* C;
    const float* bias;
    bf16 *Ch, *Cl;
    int N, K;
};

// EPI 0: fp32 C.  EPI 1: gelu(acc+bias) -> bf16 hi/lo planes.
template<int EPI>
__global__ __launch_bounds__(256, 2) void gemm_mma(const GArgs args) {
    extern __shared__ char smem[];
    uint32_t sb = smem_u32(smem);
    int tid = threadIdx.x, lane = tid & 31, wid = tid >> 5;
    int wm = wid >> 2, wn = wid & 3;
    const int K = args.K, N = args.N;
    const bf16* Ah = args.Ah + (size_t)(blockIdx.y * 128) * K;
    const bf16* Al = args.Al + (size_t)(blockIdx.y * 128) * K;
    const bf16* Bh = args.Bh + (size_t)(blockIdx.x * 128) * K;
    const bf16* Bl = args.Bl + (size_t)(blockIdx.x * 128) * K;

    float acc[4][4][4];
#pragma unroll
    for (int i = 0; i < 4; i++)
#pragma unroll
        for (int j = 0; j < 4; j++)
#pragma unroll
            for (int c = 0; c < 4; c++) acc[i][j][c] = 0.f;

    int lrow = lane & 15, lchunk = lane >> 4;
    uint32_t aRowOff[4], aSwz[4], bRowOff[2], bSwz[2];
#pragma unroll
    for (int mt = 0; mt < 4; mt++) {
        int r = wm * 64 + mt * 16 + lrow;
        aRowOff[mt] = r * 64; aSwz[mt] = (r >> 1) & 3;
    }
#pragma unroll
    for (int p = 0; p < 2; p++) {
        int r = wn * 32 + p * 16 + lrow;
        bRowOff[p] = r * 64; bSwz[p] = (r >> 1) & 3;
    }

    gemm_core(sb, acc, Ah, Al, Bh, Bl, K, tid, aRowOff, aSwz, bRowOff, bSwz, lchunk);

    int g = lane >> 2, tc = lane & 3;
#pragma unroll
    for (int mt = 0; mt < 4; mt++) {
        int row = blockIdx.y * 128 + wm * 64 + mt * 16 + g;
#pragma unroll
        for (int nt = 0; nt < 4; nt++) {
            int col = blockIdx.x * 128 + wn * 32 + nt * 8 + tc * 2;
            if (EPI == 0) {
                *(float2*)&args.C[(size_t)row * N + col]       = make_float2(acc[mt][nt][0], acc[mt][nt][1]);
                *(float2*)&args.C[(size_t)(row + 8) * N + col] = make_float2(acc[mt][nt][2], acc[mt][nt][3]);
            } else {
                float b0 = args.bias[col], b1 = args.bias[col + 1];
                float v0 = acc[mt][nt][0] + b0, v1 = acc[mt][nt][1] + b1;
                float v2 = acc[mt][nt][2] + b0, v3 = acc[mt][nt][3] + b1;
                v0 *= normcdff(v0); v1 *= normcdff(v1); v2 *= normcdff(v2); v3 *= normcdff(v3);
                uint32_t h01, l01, h23, l23;
                split2u(v0, v1, h01, l01);
                split2u(v2, v3, h23, l23);
                *(uint32_t*)&args.Ch[(size_t)row * N + col]       = h01;
                *(uint32_t*)&args.Cl[(size_t)row * N + col]       = l01;
                *(uint32_t*)&args.Ch[(size_t)(row + 8) * N + col] = h23;
                *(uint32_t*)&args.Cl[(size_t)(row + 8) * N + col] = l23;
            }
        }
    }
}

// ================= QKV partial GEMM: z = ch*4 + l, relu(acc+bias) -> fp32 partial =================
struct QkvpArgs {
    const bf16 *Ah, *Al;                 // lo split planes [BLSR, DD]
    const bf16 *Bh[3], *Bl[3];
    const float *bias[3];
    float* P;                            // [12][BSR*DD]
};

__global__ __launch_bounds__(256, 2) void gemm_qkvp(const QkvpArgs args) {
    extern __shared__ char smem[];
    uint32_t sb = smem_u32(smem);
    int tid = threadIdx.x, lane = tid & 31, wid = tid >> 5;
    int wm = wid >> 2, wn = wid & 3;
    int z = blockIdx.z, zc = z >> 2, l = z & 3;
    int by = blockIdx.y;
    int b = (by * 128) / SS;
    int s0 = by * 128 - b * SS;
    const bf16* Ah = args.Ah + ((size_t)((b * LL + l) * SS + s0)) * DD;
    const bf16* Al = args.Al + ((size_t)((b * LL + l) * SS + s0)) * DD;
    const bf16* Bh = args.Bh[zc] + (size_t)(blockIdx.x * 128) * DD;
    const bf16* Bl = args.Bl[zc] + (size_t)(blockIdx.x * 128) * DD;

    float acc[4][4][4];
#pragma unroll
    for (int i = 0; i < 4; i++)
#pragma unroll
        for (int j = 0; j < 4; j++)
#pragma unroll
            for (int c = 0; c < 4; c++) acc[i][j][c] = 0.f;

    int lrow = lane & 15, lchunk = lane >> 4;
    uint32_t aRowOff[4], aSwz[4], bRowOff[2], bSwz[2];
#pragma unroll
    for (int mt = 0; mt < 4; mt++) {
        int r = wm * 64 + mt * 16 + lrow;
        aRowOff[mt] = r * 64; aSwz[mt] = (r >> 1) & 3;
    }
#pragma unroll
    for (int p = 0; p < 2; p++) {
        int r = wn * 32 + p * 16 + lrow;
        bRowOff[p] = r * 64; bSwz[p] = (r >> 1) & 3;
    }

    gemm_core(sb, acc, Ah, Al, Bh, Bl, DD, tid, aRowOff, aSwz, bRowOff, bSwz, lchunk);

    float* P = args.P + (size_t)z * BSR * DD;
    int g = lane >> 2, tc = lane & 3;
#pragma unroll
    for (int mt = 0; mt < 4; mt++) {
        int row = by * 128 + wm * 64 + mt * 16 + g;
#pragma unroll
        for (int nt = 0; nt < 4; nt++) {
            int col = blockIdx.x * 128 + wn * 32 + nt * 8 + tc * 2;
            float b0 = args.bias[zc][col], b1 = args.bias[zc][col + 1];
            *(float2*)&P[(size_t)row * DD + col] =
                make_float2(fmaxf(acc[mt][nt][0] + b0, 0.f), fmaxf(acc[mt][nt][1] + b1, 0.f));
            *(float2*)&P[(size_t)(row + 8) * DD + col] =
                make_float2(fmaxf(acc[mt][nt][2] + b0, 0.f), fmaxf(acc[mt][nt][3] + b1, 0.f));
        }
    }
}

// ================= combine partials + g*normsum + L*be -> head-layout bf16 hi/lo =================
__global__ __launch_bounds__(256) void qkv_combine(
        const float* __restrict__ gq, const float* __restrict__ beq,
        const float* __restrict__ gk, const float* __restrict__ bek,
        const float* __restrict__ gv, const float* __restrict__ bev,
        bf16* __restrict__ qh, bf16* __restrict__ ql,
        bf16* __restrict__ kh, bf16* __restrict__ kl,
        bf16* __restrict__ vh, bf16* __restrict__ vl) {
    int row = blockIdx.x;                 // b*S+s
    int b = row / SS, s = row % SS;
    int t = threadIdx.x;
    int d0 = t * 4;
    int h = d0 >> 6, hd = d0 & 63;
    size_t oIdx = ((size_t)(b * HH + h) * SS + s) * HDD + hd;
    float4 ns = ((const float4*)(g_normsum + (size_t)row * DD))[t];

    const float* gain_[3] = { gq, gk, gv };
    const float* beta_[3] = { beq, bek, bev };
    bf16* oh_[3] = { qh, kh, vh };
    bf16* ol_[3] = { ql, kl, vl };

#pragma unroll
    for (int c = 0; c < 3; c++) {
        float4 a = make_float4(0.f, 0.f, 0.f, 0.f);
#pragma unroll
        for (int l = 0; l < LL; l++) {
            const float4* P = (const float4*)(g_qkvp + ((size_t)(c * 4 + l) * BSR + row) * DD);
            float4 p = P[t];
            a.x += p.x; a.y += p.y; a.z += p.z; a.w += p.w;
        }
        float4 gg = ((const float4*)gain_[c])[t];
        float4 ee = ((const float4*)beta_[c])[t];
        float v0 = a.x + gg.x * ns.x + LL * ee.x;
        float v1 = a.y + gg.y * ns.y + LL * ee.y;
        float v2 = a.z + gg.z * ns.z + LL * ee.z;
        float v3 = a.w + gg.w * ns.w + LL * ee.w;
        uint32_t h01, l01, h23, l23;
        split2u(v0, v1, h01, l01);
        split2u(v2, v3, h23, l23);
        *(uint32_t*)&oh_[c][oIdx]     = h01;
        *(uint32_t*)&ol_[c][oIdx]     = l01;
        *(uint32_t*)&oh_[c][oIdx + 2] = h23;
        *(uint32_t*)&ol_[c][oIdx + 2] = l23;
    }
}

// ================= tensor-core flash attention =================
#define AT_STAGE 32768
#define AT_SMEM  65536

__device__ __forceinline__ void attn_load_kv(uint32_t st, int bh, int kt, int tid) {
    const bf16* src[4] = {
        g_kph + ((size_t)bh * SS + kt * 64) * HDD,
        g_kpl + ((size_t)bh * SS + kt * 64) * HDD,
        g_vph + ((size_t)bh * SS + kt * 64) * HDD,
        g_vpl + ((size_t)bh * SS + kt * 64) * HDD };
#pragma unroll
    for (int p = 0; p < 4; p++) {
#pragma unroll
        for (int i = tid; i < 512; i += 128) {
            int r = i >> 3, c = i & 7;
            uint32_t d = st + p * 8192 + r * 128 + (((c ^ (r & 7))) << 4);
            cpasync16(d, src[p] + (size_t)r * HDD + c * 8);
        }
    }
    CP_COMMIT();
}

__global__ __launch_bounds__(128, 3) void attn_mma() {
    extern __shared__ char smem[];
    uint32_t sb = smem_u32(smem);
    int tid = threadIdx.x, lane = tid & 31, wid = tid >> 5;
    int qt = blockIdx.x, bh = blockIdx.y;
    int b = bh / HH, h = bh % HH;
    int g = lane >> 2, tc = lane & 3;
    int lrow = lane & 15, lchunk = lane >> 4;

    {
        const bf16* qsrc[2] = {
            g_qph + ((size_t)bh * SS + qt * 64) * HDD,
            g_qpl + ((size_t)bh * SS + qt * 64) * HDD };
#pragma unroll
        for (int p = 0; p < 2; p++)
#pragma unroll
            for (int i = tid; i < 512; i += 128) {
                int r = i >> 3, c = i & 7;
                uint32_t d = sb + p * 8192 + r * 128 + (((c ^ (r & 7))) << 4);
                cpasync16(d, qsrc[p] + (size_t)r * HDD + c * 8);
            }
        CP_COMMIT(); CP_WAIT0();
        __syncthreads();
    }
    uint32_t qhF[4][4], qlF[4][4];
#pragma unroll
    for (int ks = 0; ks < 4; ks++) {
        int r = wid * 16 + lrow;
        uint32_t cc = (uint32_t)(ks * 2 + lchunk);
        uint32_t off = r * 128 + ((cc ^ (r & 7)) << 4);
        ldsm4(qhF[ks], sb + off);
        ldsm4(qlF[ks], sb + 8192 + off);
    }
    __syncthreads();

    float o[8][4];
#pragma unroll
    for (int i = 0; i < 8; i++)
#pragma unroll
        for (int c = 0; c < 4; c++) o[i][c] = 0.f;
    float m0 = -INFINITY, m1 = -INFINITY, l0 = 0.f, l1 = 0.f;
    const float ls = 0.125f * 1.44269504088896f;

    attn_load_kv(sb, bh, 0, tid);

    for (int kt = 0; kt < SS / 64; kt++) {
        int buf = kt & 1;
        if (kt + 1 < SS / 64) {
            attn_load_kv(sb + (buf ^ 1) * AT_STAGE, bh, kt + 1, tid);
            CP_WAIT1();
        } else {
            CP_WAIT0();
        }
        __syncthreads();
        uint32_t st = sb + buf * AT_STAGE;

        float S[8][4];
#pragma unroll
        for (int i = 0; i < 8; i++)
#pragma unroll
            for (int c = 0; c < 4; c++) S[i][c] = 0.f;
#pragma unroll
        for (int np = 0; np < 4; np++) {
            int r = np * 16 + lrow;
#pragma unroll
            for (int ks = 0; ks < 4; ks++) {
                uint32_t cc = (uint32_t)(ks * 2 + lchunk);
                uint32_t off = r * 128 + ((cc ^ (r & 7)) << 4);
                uint32_t tH[4], tL[4];
                ldsm4(tH, st + off);
                ldsm4(tL, st + 8192 + off);
                uint32_t b0h[2] = { tH[0], tH[2] }, b1h[2] = { tH[1], tH[3] };
                uint32_t b0l[2] = { tL[0], tL[2] }, b1l[2] = { tL[1], tL[3] };
                mma16816(S[2*np],   qhF[ks], b0h);
                mma16816(S[2*np+1], qhF[ks], b1h);
                mma16816(S[2*np],   qhF[ks], b0l);
                mma16816(S[2*np+1], qhF[ks], b1l);
                mma16816(S[2*np],   qlF[ks], b0h);
                mma16816(S[2*np+1], qlF[ks], b1h);
            }
        }

        float tm0 = -INFINITY, tm1 = -INFINITY;
#pragma unroll
        for (int i = 0; i < 8; i++) {
            S[i][0] *= ls; S[i][1] *= ls; S[i][2] *= ls; S[i][3] *= ls;
            tm0 = fmaxf(tm0, fmaxf(S[i][0], S[i][1]));
            tm1 = fmaxf(tm1, fmaxf(S[i][2], S[i][3]));
        }
        tm0 = fmaxf(tm0, __shfl_xor_sync(0xffffffffu, tm0, 1));
        tm0 = fmaxf(tm0, __shfl_xor_sync(0xffffffffu, tm0, 2));
        tm1 = fmaxf(tm1, __shfl_xor_sync(0xffffffffu, tm1, 1));
        tm1 = fmaxf(tm1, __shfl_xor_sync(0xffffffffu, tm1, 2));
        float nm0 = fmaxf(m0, tm0), nm1 = fmaxf(m1, tm1);
        float c0 = exp2f(m0 - nm0), c1 = exp2f(m1 - nm1);
        float ps0 = 0.f, ps1 = 0.f;
#pragma unroll
        for (int i = 0; i < 8; i++) {
            S[i][0] = exp2f(S[i][0] - nm0); S[i][1] = exp2f(S[i][1] - nm0);
            S[i][2] = exp2f(S[i][2] - nm1); S[i][3] = exp2f(S[i][3] - nm1);
            ps0 += S[i][0] + S[i][1];
            ps1 += S[i][2] + S[i][3];
        }
        ps0 += __shfl_xor_sync(0xffffffffu, ps0, 1);
        ps0 += __shfl_xor_sync(0xffffffffu, ps0, 2);
        ps1 += __shfl_xor_sync(0xffffffffu, ps1, 1);
        ps1 += __shfl_xor_sync(0xffffffffu, ps1, 2);
        l0 = l0 * c0 + ps0; l1 = l1 * c1 + ps1;
        m0 = nm0; m1 = nm1;
#pragma unroll
        for (int i = 0; i < 8; i++) {
            o[i][0] *= c0; o[i][1] *= c0; o[i][2] *= c1; o[i][3] *= c1;
        }

        uint32_t pH[4][4], pL[4][4];
#pragma unroll
        for (int j = 0; j < 4; j++) {
            split2u(S[2*j][0],   S[2*j][1],   pH[j][0], pL[j][0]);
            split2u(S[2*j][2],   S[2*j][3],   pH[j][1], pL[j][1]);
            split2u(S[2*j+1][0], S[2*j+1][1], pH[j][2], pL[j][2]);
            split2u(S[2*j+1][2], S[2*j+1][3], pH[j][3], pL[j][3]);
        }

#pragma unroll
        for (int j = 0; j < 4; j++) {
            int r = j * 16 + lrow;
#pragma unroll
            for (int dp = 0; dp < 4; dp++) {
                uint32_t cc = (uint32_t)(dp * 2 + lchunk);
                uint32_t off = r * 128 + ((cc ^ (r & 7)) << 4);
                uint32_t tH[4], tL[4];
                ldsm4t(tH, st + 16384 + off);
                ldsm4t(tL, st + 24576 + off);
                uint32_t b0h[2] = { tH[0], tH[1] }, b1h[2] = { tH[2], tH[3] };
                uint32_t b0l[2] = { tL[0], tL[1] }, b1l[2] = { tL[2], tL[3] };
                mma16816(o[2*dp],   pH[j], b0h);
                mma16816(o[2*dp+1], pH[j], b1h);
                mma16816(o[2*dp],   pH[j], b0l);
                mma16816(o[2*dp+1], pH[j], b1l);
                mma16816(o[2*dp],   pL[j], b0h);
                mma16816(o[2*dp+1], pL[j], b1h);
            }
        }
        __syncthreads();
    }

    float il0 = 1.f / l0, il1 = 1.f / l1;
    int srow = qt * 64 + wid * 16 + g;
#pragma unroll
    for (int nt = 0; nt < 8; nt++) {
        int col = h * HDD + nt * 8 + tc * 2;
        float v0 = o[nt][0] * il0, v1 = o[nt][1] * il0;
        float v2 = o[nt][2] * il1, v3 = o[nt][3] * il1;
        uint32_t h01, lo01, h23, lo23;
        split2u(v0, v1, h01, lo01);
        split2u(v2, v3, h23, lo23);
        size_t r0 = (size_t)(b * SS + srow) * DD + col;
        size_t r1 = (size_t)(b * SS + srow + 8) * DD + col;
        *(uint32_t*)&g_cxh[r0] = h01;
        *(uint32_t*)&g_cxl[r0] = lo01;
        *(uint32_t*)&g_cxh[r1] = h23;
        *(uint32_t*)&g_cxl[r1] = lo23;
    }
}

// ================= split / prep / LN kernels =================
__global__ __launch_bounds__(256) void split_kernel(const float* __restrict__ x,
                                                    bf16* __restrict__ oh, bf16* __restrict__ ol) {
    size_t i = (size_t)blockIdx.x * 256 + threadIdx.x;
    float4 v = ((const float4*)x)[i];
    uint32_t h01, l01, h23, l23;
    split2u(v.x, v.y, h01, l01);
    split2u(v.z, v.w, h23, l23);
    ((uint32_t*)oh)[2 * i] = h01; ((uint32_t*)oh)[2 * i + 1] = h23;
    ((uint32_t*)ol)[2 * i] = l01; ((uint32_t*)ol)[2 * i + 1] = l23;
}

__global__ __launch_bounds__(256) void wsplit_kernel(const float* __restrict__ W,
                                                     bf16* __restrict__ oh, bf16* __restrict__ ol,
                                                     int K, int N) {
    __shared__ float tile[32][33];
    int n0 = blockIdx.x * 32, k0 = blockIdx.y * 32;
    int tx = threadIdx.x & 31, ty = threadIdx.x >> 5;
#pragma unroll
    for (int i = 0; i < 4; i++)
        tile[ty + 8 * i][tx] = W[(size_t)(k0 + ty + 8 * i) * N + n0 + tx];
    __syncthreads();
#pragma unroll
    for (int i = 0; i < 4; i++) {
        float v = tile[tx][ty + 8 * i];
        bf16 hh, ll; split1(v, hh, ll);
        size_t o = (size_t)(n0 + ty + 8 * i) * K + k0 + tx;
        oh[o] = hh; ol[o] = ll;
    }
}

__device__ __forceinline__ float2 blockReduce2(float s1, float s2, float* sh) {
    const unsigned FULL = 0xffffffffu;
#pragma unroll
    for (int o = 16; o; o >>= 1) {
        s1 += __shfl_xor_sync(FULL, s1, o);
        s2 += __shfl_xor_sync(FULL, s2, o);
    }
    int lane = threadIdx.x & 31, w = threadIdx.x >> 5;
    if (lane == 0) { sh[w] = s1; sh[8 + w] = s2; }
    __syncthreads();
    float t1 = 0.f, t2 = 0.f;
#pragma unroll
    for (int i = 0; i < 8; i++) { t1 += sh[i]; t2 += sh[8 + i]; }
    __syncthreads();
    return make_float2(t1, t2);
}

__global__ __launch_bounds__(256) void normsum_kernel(const float* __restrict__ lo) {
    __shared__ float sh[16];
    int row = blockIdx.x;
    int b = row / SS, s = row % SS;
    int t = threadIdx.x;
    float4 acc = make_float4(0.f, 0.f, 0.f, 0.f);
    for (int l = 0; l < LL; l++) {
        const float4* p = (const float4*)(lo + ((size_t)((b*LL + l)*SS + s))*DD);
        float4 v = p[t];
        float s1 = v.x + v.y + v.z + v.w;
        float s2 = v.x*v.x + v.y*v.y + v.z*v.z + v.w*v.w;
        float2 tot = blockReduce2(s1, s2, sh);
        float mu = tot.x * (1.f/DD);
        float var = tot.y * (1.f/DD) - mu*mu;
        float r = rsqrtf(var + EPSV);
        acc.x += (v.x - mu)*r; acc.y += (v.y - mu)*r;
        acc.z += (v.z - mu)*r; acc.w += (v.w - mu)*r;
    }
    ((float4*)(g_normsum + (size_t)row*DD))[t] = acc;
}

template<int SPLIT>
__global__ __launch_bounds__(256) void ln_residual_kernel(
        const float* __restrict__ resid, const float* __restrict__ pre,
        const float* __restrict__ bias, const float* __restrict__ gam,
        const float* __restrict__ bet, float* __restrict__ out,
        bf16* __restrict__ oh, bf16* __restrict__ ol) {
    __shared__ float sh[16];
    int row = blockIdx.x, t = threadIdx.x;
    float4 p = ((const float4*)(pre + (size_t)row*DD))[t];
    float4 bb = ((const float4*)bias)[t];
    p.x += bb.x; p.y += bb.y; p.z += bb.z; p.w += bb.w;
    float s1 = p.x + p.y + p.z + p.w;
    float s2 = p.x*p.x + p.y*p.y + p.z*p.z + p.w*p.w;
    float2 tot = blockReduce2(s1, s2, sh);
    float mu = tot.x * (1.f/DD);
    float var = tot.y * (1.f/DD) - mu*mu;
    float r = rsqrtf(var + EPSV);
    float4 gg = ((const float4*)gam)[t];
    float4 ee = ((const float4*)bet)[t];
    float4 rr = ((const float4*)(resid + (size_t)row*DD))[t];
    float4 o;
    o.x = rr.x + (p.x - mu)*r*gg.x + ee.x;
    o.y = rr.y + (p.y - mu)*r*gg.y + ee.y;
    o.z = rr.z + (p.z - mu)*r*gg.z + ee.z;
    o.w = rr.w + (p.w - mu)*r*gg.w + ee.w;
    ((float4*)(out + (size_t)row*DD))[t] = o;
    if (SPLIT) {
        uint32_t h01, l01, h23, l23;
        split2u(o.x, o.y, h01, l01);
        split2u(o.z, o.w, h23, l23);
        size_t i = (size_t)row * (DD/4) + t;
        ((uint32_t*)oh)[2 * i] = h01; ((uint32_t*)oh)[2 * i + 1] = h23;
        ((uint32_t*)ol)[2 * i] = l01; ((uint32_t*)ol)[2 * i + 1] = l23;
    }
}

// ================= host =================
static void* symaddr(const void* sym) { void* p; cudaGetSymbolAddress(&p, sym); return p; }

extern "C" void kernel_launch(void* const* d_in, const int* in_sizes, int n_in,
                              void* d_out, int out_size) {
    const float* x   = (const float*)d_in[0];
    const float* lo  = (const float*)d_in[1];
    const float* qW  = (const float*)d_in[2];
    const float* qb  = (const float*)d_in[3];
    const float* qg  = (const float*)d_in[4];
    const float* qbe = (const float*)d_in[5];
    const float* kW  = (const float*)d_in[6];
    const float* kb  = (const float*)d_in[7];
    const float* kg  = (const float*)d_in[8];
    const float* kbe = (const float*)d_in[9];
    const float* vW  = (const float*)d_in[10];
    const float* vb  = (const float*)d_in[11];
    const float* vg  = (const float*)d_in[12];
    const float* vbe = (const float*)d_in[13];
    const float* oW  = (const float*)d_in[14];
    const float* ob  = (const float*)d_in[15];
    const float* ang = (const float*)d_in[16];
    const float* anb = (const float*)d_in[17];
    const float* W1  = (const float*)d_in[18];
    const float* b1  = (const float*)d_in[19];
    const float* W2  = (const float*)d_in[20];
    const float* b2  = (const float*)d_in[21];
    const float* fng = (const float*)d_in[22];
    const float* fnb = (const float*)d_in[23];
    float* out = (float*)d_out;

    float* proj = (float*)symaddr(g_proj);
    float* out1 = (float*)symaddr(g_out1);
    float* ffn2 = (float*)symaddr(g_ffn2);
    float* qkvp = (float*)symaddr(g_qkvp);
    bf16 *loh = (bf16*)symaddr(g_loh), *lol = (bf16*)symaddr(g_lol);
    bf16 *wqh = (bf16*)symaddr(g_wqh), *wql = (bf16*)symaddr(g_wql);
    bf16 *wkh = (bf16*)symaddr(g_wkh), *wkl = (bf16*)symaddr(g_wkl);
    bf16 *wvh = (bf16*)symaddr(g_wvh), *wvl = (bf16*)symaddr(g_wvl);
    bf16 *woh = (bf16*)symaddr(g_woh), *wol = (bf16*)symaddr(g_wol);
    bf16 *w1h = (bf16*)symaddr(g_w1h), *w1l = (bf16*)symaddr(g_w1l);
    bf16 *w2h = (bf16*)symaddr(g_w2h), *w2l = (bf16*)symaddr(g_w2l);
    bf16 *cxh = (bf16*)symaddr(g_cxh), *cxl = (bf16*)symaddr(g_cxl);
    bf16 *o1h = (bf16*)symaddr(g_o1h), *o1l = (bf16*)symaddr(g_o1l);
    bf16 *f1h = (bf16*)symaddr(g_f1h), *f1l = (bf16*)symaddr(g_f1l);

    cudaFuncSetAttribute(gemm_mma<0>, cudaFuncAttributeMaxDynamicSharedMemorySize, GEMM_SMEM);
    cudaFuncSetAttribute(gemm_mma<1>, cudaFuncAttributeMaxDynamicSharedMemorySize, GEMM_SMEM);
    cudaFuncSetAttribute(gemm_qkvp,   cudaFuncAttributeMaxDynamicSharedMemorySize, GEMM_SMEM);
    cudaFuncSetAttribute(attn_mma,    cudaFuncAttributeMaxDynamicSharedMemorySize, AT_SMEM);

    // weight prep
    wsplit_kernel<<<dim3(DD/32, DD/32), 256>>>(qW, wqh, wql, DD, DD);
    wsplit_kernel<<<dim3(DD/32, DD/32), 256>>>(kW, wkh, wkl, DD, DD);
    wsplit_kernel<<<dim3(DD/32, DD/32), 256>>>(vW, wvh, wvl, DD, DD);
    wsplit_kernel<<<dim3(DD/32, DD/32), 256>>>(oW, woh, wol, DD, DD);
    wsplit_kernel<<<dim3(MLPD/32, DD/32), 256>>>(W1, w1h, w1l, DD, MLPD);
    wsplit_kernel<<<dim3(DD/32, MLPD/32), 256>>>(W2, w2h, w2l, MLPD, DD);

    split_kernel<<<((size_t)BLSR*DD/4)/256, 256>>>(lo, loh, lol);
    normsum_kernel<<<BSR, 256>>>(lo);

    // QKV partial GEMMs (z = ch*4 + l), then combine
    {
        QkvpArgs a;
        a.Ah = loh; a.Al = lol;
        a.Bh[0] = wqh; a.Bl[0] = wql; a.bias[0] = qb;
        a.Bh[1] = wkh; a.Bl[1] = wkl; a.bias[1] = kb;
        a.Bh[2] = wvh; a.Bl[2] = wvl; a.bias[2] = vb;
        a.P = qkvp;
        gemm_qkvp<<<dim3(DD/128, BSR/128, 12), 256, GEMM_SMEM>>>(a);
    }
    qkv_combine<<<BSR, 256>>>(qg, qbe, kg, kbe, vg, vbe,
        (bf16*)symaddr(g_qph), (bf16*)symaddr(g_qpl),
        (bf16*)symaddr(g_kph), (bf16*)symaddr(g_kpl),
        (bf16*)symaddr(g_vph), (bf16*)symaddr(g_vpl));

    attn_mma<<<dim3(SS/64, BB*HH), 128, AT_SMEM>>>();

    // attn out projection
    {
        GArgs a = {};
        a.Ah = cxh; a.Al = cxl; a.Bh = woh; a.Bl = wol;
        a.C = proj; a.N = DD; a.K = DD;
        gemm_mma<0><<<dim3(DD/128, BSR/128), 256, GEMM_SMEM>>>(a);
    }
    ln_residual_kernel<1><<<BSR, 256>>>(x, proj, ob, ang, anb, out1, o1h, o1l);

    // FFN1 with fused bias+gelu+split epilogue
    {
        GArgs a = {};
        a.Ah = o1h; a.Al = o1l; a.Bh = w1h; a.Bl = w1l;
        a.bias = b1; a.Ch = f1h; a.Cl = f1l; a.N = MLPD; a.K = DD;
        gemm_mma<1><<<dim3(MLPD/128, BSR/128), 256, GEMM_SMEM>>>(a);
    }
    // FFN2
    {
        GArgs a = {};
        a.Ah = f1h; a.Al = f1l; a.Bh = w2h; a.Bl = w2l;
        a.C = ffn2; a.N = DD; a.K = MLPD;
        gemm_mma<0><<<dim3(DD/128, BSR/128), 256, GEMM_SMEM>>>(a);
    }
    ln_residual_kernel<0><<<BSR, 256>>>(out1, ffn2, b2, fng, fnb, out, nullptr, nullptr);
}

// round 13
// speedup vs baseline: 5.5958x; 1.0095x over previous
#include <cuda_runtime.h>
#include <cuda_bf16.h>
#include <cuda_fp16.h>
#include <math.h>
#include <stdint.h>

typedef __nv_bfloat16 bf16;

#define BB 2
#define LL 4
#define SS 2048
#define DD 1024
#define HH 16
#define HDD 64
#define MLPD 4096
#define EPSV 1e-5f
#define BSR (BB*SS)
#define BLSR (BB*LL*SS)

// ================= scratch =================
static __device__ float g_normsum[(size_t)BSR*DD];
static __device__ float g_proj[(size_t)BSR*DD];
static __device__ float g_out1[(size_t)BSR*DD];
static __device__ float g_ffn2[(size_t)BSR*DD];
static __device__ __half g_qkvp[(size_t)12*BSR*DD];   // 96MB: [ch*4+l][BSR*DD] relu partials (fp16)

static __device__ bf16 g_loh[(size_t)BLSR*DD], g_lol[(size_t)BLSR*DD];
static __device__ bf16 g_wqh[(size_t)DD*DD],  g_wql[(size_t)DD*DD];
static __device__ bf16 g_wkh[(size_t)DD*DD],  g_wkl[(size_t)DD*DD];
static __device__ bf16 g_wvh[(size_t)DD*DD],  g_wvl[(size_t)DD*DD];
static __device__ bf16 g_woh[(size_t)DD*DD],  g_wol[(size_t)DD*DD];
static __device__ bf16 g_w1h[(size_t)MLPD*DD], g_w1l[(size_t)MLPD*DD];
static __device__ bf16 g_w2h[(size_t)DD*MLPD], g_w2l[(size_t)DD*MLPD];
static __device__ bf16 g_qph[(size_t)BSR*DD], g_qpl[(size_t)BSR*DD];
static __device__ bf16 g_kph[(size_t)BSR*DD], g_kpl[(size_t)BSR*DD];
static __device__ bf16 g_vph[(size_t)BSR*DD], g_vpl[(size_t)BSR*DD];
static __device__ bf16 g_cxh[(size_t)BSR*DD], g_cxl[(size_t)BSR*DD];
static __device__ bf16 g_o1h[(size_t)BSR*DD], g_o1l[(size_t)BSR*DD];
static __device__ bf16 g_f1h[(size_t)BSR*MLPD], g_f1l[(size_t)BSR*MLPD];

// ================= PTX helpers =================
__device__ __forceinline__ uint32_t smem_u32(const void* p) {
    uint32_t a;
    asm("{ .reg .u64 t; cvta.to.shared.u64 t, %1; cvt.u32.u64 %0, t; }" : "=r"(a) : "l"(p));
    return a;
}
__device__ __forceinline__ void cpasync16(uint32_t dst, const void* src) {
    asm volatile("cp.async.cg.shared.global [%0], [%1], 16;" :: "r"(dst), "l"(src));
}
#define CP_COMMIT() asm volatile("cp.async.commit_group;" ::: "memory")
#define CP_WAIT0()  asm volatile("cp.async.wait_group 0;" ::: "memory")
#define CP_WAIT1()  asm volatile("cp.async.wait_group 1;" ::: "memory")
#define CP_WAIT2()  asm volatile("cp.async.wait_group 2;" ::: "memory")

__device__ __forceinline__ void ldsm4(uint32_t* r, uint32_t addr) {
    asm volatile("ldmatrix.sync.aligned.m8n8.x4.shared.b16 {%0,%1,%2,%3}, [%4];"
        : "=r"(r[0]), "=r"(r[1]), "=r"(r[2]), "=r"(r[3]) : "r"(addr));
}
__device__ __forceinline__ void ldsm4t(uint32_t* r, uint32_t addr) {
    asm volatile("ldmatrix.sync.aligned.m8n8.x4.trans.shared.b16 {%0,%1,%2,%3}, [%4];"
        : "=r"(r[0]), "=r"(r[1]), "=r"(r[2]), "=r"(r[3]) : "r"(addr));
}
__device__ __forceinline__ void mma16816(float* d, const uint32_t* a, const uint32_t* b) {
    asm volatile("mma.sync.aligned.m16n8k16.row.col.f32.bf16.bf16.f32 "
        "{%0,%1,%2,%3}, {%4,%5,%6,%7}, {%8,%9}, {%0,%1,%2,%3};"
        : "+f"(d[0]), "+f"(d[1]), "+f"(d[2]), "+f"(d[3])
        : "r"(a[0]), "r"(a[1]), "r"(a[2]), "r"(a[3]), "r"(b[0]), "r"(b[1]));
}
__device__ __forceinline__ void split1(float v, bf16& h, bf16& l) {
    h = __float2bfloat16_rn(v);
    l = __float2bfloat16_rn(v - __bfloat162float(h));
}
__device__ __forceinline__ void split2u(float a, float b, uint32_t& hi, uint32_t& lo) {
    bf16 ha, la, hb, lb;
    split1(a, ha, la); split1(b, hb, lb);
    __nv_bfloat162 H(ha, hb), L(la, lb);
    hi = *(uint32_t*)&H; lo = *(uint32_t*)&L;
}

// ================= generic mma GEMM (128x128 tile, K chunk 32, 3-stage) =================
#define PL_AH 0
#define PL_AL 8192
#define PL_BH 16384
#define PL_BL 24576
#define STAGE_B 32768
#define GEMM_SMEM (3*32768)

__device__ __forceinline__ void load_stage(uint32_t st,
        const bf16* __restrict__ Ah, const bf16* __restrict__ Al,
        const bf16* __restrict__ Bh, const bf16* __restrict__ Bl,
        int K, int kt, int tid) {
    const bf16* gsrc[4] = { Ah, Al, Bh, Bl };
#pragma unroll
    for (int p = 0; p < 4; p++) {
        const bf16* g = gsrc[p] + kt * 32;
#pragma unroll
        for (int i = tid; i < 512; i += 256) {
            int r = i >> 2, c = i & 3;
            uint32_t d = st + p * 8192 + r * 64 + (((c ^ ((r >> 1) & 3))) << 4);
            cpasync16(d, g + (size_t)r * K + c * 8);
        }
    }
    CP_COMMIT();
}

__device__ __forceinline__ void gemm_core(uint32_t sb, float acc[4][4][4],
        const bf16* Ah, const bf16* Al, const bf16* Bh, const bf16* Bl,
        int K, int tid, const uint32_t* aRowOff, const uint32_t* aSwz,
        const uint32_t* bRowOff, const uint32_t* bSwz, int lchunk) {
    const int nch = K / 32;
    load_stage(sb, Ah, Al, Bh, Bl, K, 0, tid);
    if (nch > 1) load_stage(sb + STAGE_B, Ah, Al, Bh, Bl, K, 1, tid);
    for (int kt = 0; kt < nch; kt++) {
        int buf = kt % 3;
        if (kt + 2 < nch) {
            load_stage(sb + ((kt + 2) % 3) * STAGE_B, Ah, Al, Bh, Bl, K, kt + 2, tid);
            CP_WAIT2();
        } else if (kt + 1 < nch) {
            CP_WAIT1();
        } else {
            CP_WAIT0();
        }
        __syncthreads();
        uint32_t st = sb + buf * STAGE_B;
#pragma unroll
        for (int s = 0; s < 2; s++) {
            uint32_t ch = (uint32_t)(s * 2 + lchunk);
            uint32_t aF[4][4], bHf[4][2], bLf[4][2];
#pragma unroll
            for (int mt = 0; mt < 4; mt++)
                ldsm4(aF[mt], st + PL_AH + aRowOff[mt] + ((ch ^ aSwz[mt]) << 4));
#pragma unroll
            for (int p = 0; p < 2; p++) {
                uint32_t t[4];
                ldsm4(t, st + PL_BH + bRowOff[p] + ((ch ^ bSwz[p]) << 4));
                bHf[2*p][0] = t[0]; bHf[2*p][1] = t[2];
                bHf[2*p+1][0] = t[1]; bHf[2*p+1][1] = t[3];
                ldsm4(t, st + PL_BL + bRowOff[p] + ((ch ^ bSwz[p]) << 4));
                bLf[2*p][0] = t[0]; bLf[2*p][1] = t[2];
                bLf[2*p+1][0] = t[1]; bLf[2*p+1][1] = t[3];
            }
#pragma unroll
            for (int mt = 0; mt < 4; mt++)
#pragma unroll
                for (int nt = 0; nt < 4; nt++) mma16816(acc[mt][nt], aF[mt], bHf[nt]);
#pragma unroll
            for (int mt = 0; mt < 4; mt++)
#pragma unroll
                for (int nt = 0; nt < 4; nt++) mma16816(acc[mt][nt], aF[mt], bLf[nt]);
#pragma unroll
            for (int mt = 0; mt < 4; mt++)
                ldsm4(aF[mt], st + PL_AL + aRowOff[mt] + ((ch ^ aSwz[mt]) << 4));
#pragma unroll
            for (int mt = 0; mt < 4; mt++)
#pragma unroll
                for (int nt = 0; nt < 4; nt++) mma16816(acc[mt][nt], aF[mt], bHf[nt]);
        }
        __syncthreads();
    }
}

struct GArgs {
    const bf16 *Ah, *Al, *Bh, *Bl;
    float* C;
    const float* bias;
    bf16 *Ch, *Cl;
    int N, K;
};

// EPI 0: fp32 C.  EPI 1: gelu(acc+bias) -> bf16 hi/lo planes.
template<int EPI>
__global__ __launch_bounds__(256, 2) void gemm_mma(const GArgs args) {
    extern __shared__ char smem[];
    uint32_t sb = smem_u32(smem);
    int tid = threadIdx.x, lane = tid & 31, wid = tid >> 5;
    int wm = wid >> 2, wn = wid & 3;
    const int K = args.K, N = args.N;
    const bf16* Ah = args.Ah + (size_t)(blockIdx.y * 128) * K;
    const bf16* Al = args.Al + (size_t)(blockIdx.y * 128) * K;
    const bf16* Bh = args.Bh + (size_t)(blockIdx.x * 128) * K;
    const bf16* Bl = args.Bl + (size_t)(blockIdx.x * 128) * K;

    float acc[4][4][4];
#pragma unroll
    for (int i = 0; i < 4; i++)
#pragma unroll
        for (int j = 0; j < 4; j++)
#pragma unroll
            for (int c = 0; c < 4; c++) acc[i][j][c] = 0.f;

    int lrow = lane & 15, lchunk = lane >> 4;
    uint32_t aRowOff[4], aSwz[4], bRowOff[2], bSwz[2];
#pragma unroll
    for (int mt = 0; mt < 4; mt++) {
        int r = wm * 64 + mt * 16 + lrow;
        aRowOff[mt] = r * 64; aSwz[mt] = (r >> 1) & 3;
    }
#pragma unroll
    for (int p = 0; p < 2; p++) {
        int r = wn * 32 + p * 16 + lrow;
        bRowOff[p] = r * 64; bSwz[p] = (r >> 1) & 3;
    }

    gemm_core(sb, acc, Ah, Al, Bh, Bl, K, tid, aRowOff, aSwz, bRowOff, bSwz, lchunk);

    int g = lane >> 2, tc = lane & 3;
#pragma unroll
    for (int mt = 0; mt < 4; mt++) {
        int row = blockIdx.y * 128 + wm * 64 + mt * 16 + g;
#pragma unroll
        for (int nt = 0; nt < 4; nt++) {
            int col = blockIdx.x * 128 + wn * 32 + nt * 8 + tc * 2;
            if (EPI == 0) {
                *(float2*)&args.C[(size_t)row * N + col]       = make_float2(acc[mt][nt][0], acc[mt][nt][1]);
                *(float2*)&args.C[(size_t)(row + 8) * N + col] = make_float2(acc[mt][nt][2], acc[mt][nt][3]);
            } else {
                float b0 = args.bias[col], b1 = args.bias[col + 1];
                float v0 = acc[mt][nt][0] + b0, v1 = acc[mt][nt][1] + b1;
                float v2 = acc[mt][nt][2] + b0, v3 = acc[mt][nt][3] + b1;
                v0 *= normcdff(v0); v1 *= normcdff(v1); v2 *= normcdff(v2); v3 *= normcdff(v3);
                uint32_t h01, l01, h23, l23;
                split2u(v0, v1, h01, l01);
                split2u(v2, v3, h23, l23);
                *(uint32_t*)&args.Ch[(size_t)row * N + col]       = h01;
                *(uint32_t*)&args.Cl[(size_t)row * N + col]       = l01;
                *(uint32_t*)&args.Ch[(size_t)(row + 8) * N + col] = h23;
                *(uint32_t*)&args.Cl[(size_t)(row + 8) * N + col] = l23;
            }
        }
    }
}

// ================= QKV partial GEMM: z = ch*4 + l, relu(acc+bias) -> fp16 partial =================
struct QkvpArgs {
    const bf16 *Ah, *Al;                 // lo split planes [BLSR, DD]
    const bf16 *Bh[3], *Bl[3];
    const float *bias[3];
    __half* P;                           // [12][BSR*DD]
};

__global__ __launch_bounds__(256, 2) void gemm_qkvp(const QkvpArgs args) {
    extern __shared__ char smem[];
    uint32_t sb = smem_u32(smem);
    int tid = threadIdx.x, lane = tid & 31, wid = tid >> 5;
    int wm = wid >> 2, wn = wid & 3;
    int z = blockIdx.z, zc = z >> 2, l = z & 3;
    int by = blockIdx.y;
    int b = (by * 128) / SS;
    int s0 = by * 128 - b * SS;
    const bf16* Ah = args.Ah + ((size_t)((b * LL + l) * SS + s0)) * DD;
    const bf16* Al = args.Al + ((size_t)((b * LL + l) * SS + s0)) * DD;
    const bf16* Bh = args.Bh[zc] + (size_t)(blockIdx.x * 128) * DD;
    const bf16* Bl = args.Bl[zc] + (size_t)(blockIdx.x * 128) * DD;

    float acc[4][4][4];
#pragma unroll
    for (int i = 0; i < 4; i++)
#pragma unroll
        for (int j = 0; j < 4; j++)
#pragma unroll
            for (int c = 0; c < 4; c++) acc[i][j][c] = 0.f;

    int lrow = lane & 15, lchunk = lane >> 4;
    uint32_t aRowOff[4], aSwz[4], bRowOff[2], bSwz[2];
#pragma unroll
    for (int mt = 0; mt < 4; mt++) {
        int r = wm * 64 + mt * 16 + lrow;
        aRowOff[mt] = r * 64; aSwz[mt] = (r >> 1) & 3;
    }
#pragma unroll
    for (int p = 0; p < 2; p++) {
        int r = wn * 32 + p * 16 + lrow;
        bRowOff[p] = r * 64; bSwz[p] = (r >> 1) & 3;
    }

    gemm_core(sb, acc, Ah, Al, Bh, Bl, DD, tid, aRowOff, aSwz, bRowOff, bSwz, lchunk);

    __half* P = args.P + (size_t)z * BSR * DD;
    int g = lane >> 2, tc = lane & 3;
#pragma unroll
    for (int mt = 0; mt < 4; mt++) {
        int row = by * 128 + wm * 64 + mt * 16 + g;
#pragma unroll
        for (int nt = 0; nt < 4; nt++) {
            int col = blockIdx.x * 128 + wn * 32 + nt * 8 + tc * 2;
            float b0 = args.bias[zc][col], b1 = args.bias[zc][col + 1];
            *(__half2*)&P[(size_t)row * DD + col] =
                __floats2half2_rn(fmaxf(acc[mt][nt][0] + b0, 0.f), fmaxf(acc[mt][nt][1] + b1, 0.f));
            *(__half2*)&P[(size_t)(row + 8) * DD + col] =
                __floats2half2_rn(fmaxf(acc[mt][nt][2] + b0, 0.f), fmaxf(acc[mt][nt][3] + b1, 0.f));
        }
    }
}

// ================= combine partials + g*normsum + L*be -> head-layout bf16 hi/lo =================
__global__ __launch_bounds__(256) void qkv_combine(
        const float* __restrict__ gq, const float* __restrict__ beq,
        const float* __restrict__ gk, const float* __restrict__ bek,
        const float* __restrict__ gv, const float* __restrict__ bev,
        bf16* __restrict__ qh, bf16* __restrict__ ql,
        bf16* __restrict__ kh, bf16* __restrict__ kl,
        bf16* __restrict__ vh, bf16* __restrict__ vl) {
    int row = blockIdx.x;                 // b*S+s
    int b = row / SS, s = row % SS;
    int t = threadIdx.x;
    int d0 = t * 4;
    int h = d0 >> 6, hd = d0 & 63;
    size_t oIdx = ((size_t)(b * HH + h) * SS + s) * HDD + hd;
    float4 ns = ((const float4*)(g_normsum + (size_t)row * DD))[t];

    const float* gain_[3] = { gq, gk, gv };
    const float* beta_[3] = { beq, bek, bev };
    bf16* oh_[3] = { qh, kh, vh };
    bf16* ol_[3] = { ql, kl, vl };

#pragma unroll
    for (int c = 0; c < 3; c++) {
        float4 a = make_float4(0.f, 0.f, 0.f, 0.f);
#pragma unroll
        for (int l = 0; l < LL; l++) {
            const __half* P = g_qkvp + ((size_t)(c * 4 + l) * BSR + row) * DD;
            uint2 pr = ((const uint2*)P)[t];
            float2 f01 = __half22float2(*(__half2*)&pr.x);
            float2 f23 = __half22float2(*(__half2*)&pr.y);
            a.x += f01.x; a.y += f01.y; a.z += f23.x; a.w += f23.y;
        }
        float4 gg = ((const float4*)gain_[c])[t];
        float4 ee = ((const float4*)beta_[c])[t];
        float v0 = a.x + gg.x * ns.x + LL * ee.x;
        float v1 = a.y + gg.y * ns.y + LL * ee.y;
        float v2 = a.z + gg.z * ns.z + LL * ee.z;
        float v3 = a.w + gg.w * ns.w + LL * ee.w;
        uint32_t h01, l01, h23, l23;
        split2u(v0, v1, h01, l01);
        split2u(v2, v3, h23, l23);
        *(uint32_t*)&oh_[c][oIdx]     = h01;
        *(uint32_t*)&ol_[c][oIdx]     = l01;
        *(uint32_t*)&oh_[c][oIdx + 2] = h23;
        *(uint32_t*)&ol_[c][oIdx + 2] = l23;
    }
}

// ================= tensor-core flash attention =================
#define AT_STAGE 32768
#define AT_SMEM  65536

__device__ __forceinline__ void attn_load_kv(uint32_t st, int bh, int kt, int tid) {
    const bf16* src[4] = {
        g_kph + ((size_t)bh * SS + kt * 64) * HDD,
        g_kpl + ((size_t)bh * SS + kt * 64) * HDD,
        g_vph + ((size_t)bh * SS + kt * 64) * HDD,
        g_vpl + ((size_t)bh * SS + kt * 64) * HDD };
#pragma unroll
    for (int p = 0; p < 4; p++) {
#pragma unroll
        for (int i = tid; i < 512; i += 128) {
            int r = i >> 3, c = i & 7;
            uint32_t d = st + p * 8192 + r * 128 + (((c ^ (r & 7))) << 4);
            cpasync16(d, src[p] + (size_t)r * HDD + c * 8);
        }
    }
    CP_COMMIT();
}

__global__ __launch_bounds__(128, 3) void attn_mma() {
    extern __shared__ char smem[];
    uint32_t sb = smem_u32(smem);
    int tid = threadIdx.x, lane = tid & 31, wid = tid >> 5;
    int qt = blockIdx.x, bh = blockIdx.y;
    int b = bh / HH, h = bh % HH;
    int g = lane >> 2, tc = lane & 3;
    int lrow = lane & 15, lchunk = lane >> 4;

    {
        const bf16* qsrc[2] = {
            g_qph + ((size_t)bh * SS + qt * 64) * HDD,
            g_qpl + ((size_t)bh * SS + qt * 64) * HDD };
#pragma unroll
        for (int p = 0; p < 2; p++)
#pragma unroll
            for (int i = tid; i < 512; i += 128) {
                int r = i >> 3, c = i & 7;
                uint32_t d = sb + p * 8192 + r * 128 + (((c ^ (r & 7))) << 4);
                cpasync16(d, qsrc[p] + (size_t)r * HDD + c * 8);
            }
        CP_COMMIT(); CP_WAIT0();
        __syncthreads();
    }
    uint32_t qhF[4][4], qlF[4][4];
#pragma unroll
    for (int ks = 0; ks < 4; ks++) {
        int r = wid * 16 + lrow;
        uint32_t cc = (uint32_t)(ks * 2 + lchunk);
        uint32_t off = r * 128 + ((cc ^ (r & 7)) << 4);
        ldsm4(qhF[ks], sb + off);
        ldsm4(qlF[ks], sb + 8192 + off);
    }
    __syncthreads();

    float o[8][4];
#pragma unroll
    for (int i = 0; i < 8; i++)
#pragma unroll
        for (int c = 0; c < 4; c++) o[i][c] = 0.f;
    float m0 = -INFINITY, m1 = -INFINITY, l0 = 0.f, l1 = 0.f;
    const float ls = 0.125f * 1.44269504088896f;

    attn_load_kv(sb, bh, 0, tid);

    for (int kt = 0; kt < SS / 64; kt++) {
        int buf = kt & 1;
        if (kt + 1 < SS / 64) {
            attn_load_kv(sb + (buf ^ 1) * AT_STAGE, bh, kt + 1, tid);
            CP_WAIT1();
        } else {
            CP_WAIT0();
        }
        __syncthreads();
        uint32_t st = sb + buf * AT_STAGE;

        float S[8][4];
#pragma unroll
        for (int i = 0; i < 8; i++)
#pragma unroll
            for (int c = 0; c < 4; c++) S[i][c] = 0.f;
#pragma unroll
        for (int np = 0; np < 4; np++) {
            int r = np * 16 + lrow;
#pragma unroll
            for (int ks = 0; ks < 4; ks++) {
                uint32_t cc = (uint32_t)(ks * 2 + lchunk);
                uint32_t off = r * 128 + ((cc ^ (r & 7)) << 4);
                uint32_t tH[4], tL[4];
                ldsm4(tH, st + off);
                ldsm4(tL, st + 8192 + off);
                uint32_t b0h[2] = { tH[0], tH[2] }, b1h[2] = { tH[1], tH[3] };
                uint32_t b0l[2] = { tL[0], tL[2] }, b1l[2] = { tL[1], tL[3] };
                mma16816(S[2*np],   qhF[ks], b0h);
                mma16816(S[2*np+1], qhF[ks], b1h);
                mma16816(S[2*np],   qhF[ks], b0l);
                mma16816(S[2*np+1], qhF[ks], b1l);
                mma16816(S[2*np],   qlF[ks], b0h);
                mma16816(S[2*np+1], qlF[ks], b1h);
            }
        }

        float tm0 = -INFINITY, tm1 = -INFINITY;
#pragma unroll
        for (int i = 0; i < 8; i++) {
            S[i][0] *= ls; S[i][1] *= ls; S[i][2] *= ls; S[i][3] *= ls;
            tm0 = fmaxf(tm0, fmaxf(S[i][0], S[i][1]));
            tm1 = fmaxf(tm1, fmaxf(S[i][2], S[i][3]));
        }
        tm0 = fmaxf(tm0, __shfl_xor_sync(0xffffffffu, tm0, 1));
        tm0 = fmaxf(tm0, __shfl_xor_sync(0xffffffffu, tm0, 2));
        tm1 = fmaxf(tm1, __shfl_xor_sync(0xffffffffu, tm1, 1));
        tm1 = fmaxf(tm1, __shfl_xor_sync(0xffffffffu, tm1, 2));
        float nm0 = fmaxf(m0, tm0), nm1 = fmaxf(m1, tm1);
        float c0 = exp2f(m0 - nm0), c1 = exp2f(m1 - nm1);
        float ps0 = 0.f, ps1 = 0.f;
#pragma unroll
        for (int i = 0; i < 8; i++) {
            S[i][0] = exp2f(S[i][0] - nm0); S[i][1] = exp2f(S[i][1] - nm0);
            S[i][2] = exp2f(S[i][2] - nm1); S[i][3] = exp2f(S[i][3] - nm1);
            ps0 += S[i][0] + S[i][1];
            ps1 += S[i][2] + S[i][3];
        }
        ps0 += __shfl_xor_sync(0xffffffffu, ps0, 1);
        ps0 += __shfl_xor_sync(0xffffffffu, ps0, 2);
        ps1 += __shfl_xor_sync(0xffffffffu, ps1, 1);
        ps1 += __shfl_xor_sync(0xffffffffu, ps1, 2);
        l0 = l0 * c0 + ps0; l1 = l1 * c1 + ps1;
        m0 = nm0; m1 = nm1;
#pragma unroll
        for (int i = 0; i < 8; i++) {
            o[i][0] *= c0; o[i][1] *= c0; o[i][2] *= c1; o[i][3] *= c1;
        }

        uint32_t pH[4][4], pL[4][4];
#pragma unroll
        for (int j = 0; j < 4; j++) {
            split2u(S[2*j][0],   S[2*j][1],   pH[j][0], pL[j][0]);
            split2u(S[2*j][2],   S[2*j][3],   pH[j][1], pL[j][1]);
            split2u(S[2*j+1][0], S[2*j+1][1], pH[j][2], pL[j][2]);
            split2u(S[2*j+1][2], S[2*j+1][3], pH[j][3], pL[j][3]);
        }

#pragma unroll
        for (int j = 0; j < 4; j++) {
            int r = j * 16 + lrow;
#pragma unroll
            for (int dp = 0; dp < 4; dp++) {
                uint32_t cc = (uint32_t)(dp * 2 + lchunk);
                uint32_t off = r * 128 + ((cc ^ (r & 7)) << 4);
                uint32_t tH[4], tL[4];
                ldsm4t(tH, st + 16384 + off);
                ldsm4t(tL, st + 24576 + off);
                uint32_t b0h[2] = { tH[0], tH[1] }, b1h[2] = { tH[2], tH[3] };
                uint32_t b0l[2] = { tL[0], tL[1] }, b1l[2] = { tL[2], tL[3] };
                mma16816(o[2*dp],   pH[j], b0h);
                mma16816(o[2*dp+1], pH[j], b1h);
                mma16816(o[2*dp],   pH[j], b0l);
                mma16816(o[2*dp+1], pH[j], b1l);
                mma16816(o[2*dp],   pL[j], b0h);
                mma16816(o[2*dp+1], pL[j], b1h);
            }
        }
        __syncthreads();
    }

    float il0 = 1.f / l0, il1 = 1.f / l1;
    int srow = qt * 64 + wid * 16 + g;
#pragma unroll
    for (int nt = 0; nt < 8; nt++) {
        int col = h * HDD + nt * 8 + tc * 2;
        float v0 = o[nt][0] * il0, v1 = o[nt][1] * il0;
        float v2 = o[nt][2] * il1, v3 = o[nt][3] * il1;
        uint32_t h01, lo01, h23, lo23;
        split2u(v0, v1, h01, lo01);
        split2u(v2, v3, h23, lo23);
        size_t r0 = (size_t)(b * SS + srow) * DD + col;
        size_t r1 = (size_t)(b * SS + srow + 8) * DD + col;
        *(uint32_t*)&g_cxh[r0] = h01;
        *(uint32_t*)&g_cxl[r0] = lo01;
        *(uint32_t*)&g_cxh[r1] = h23;
        *(uint32_t*)&g_cxl[r1] = lo23;
    }
}

// ================= fused split + normsum =================
__device__ __forceinline__ float2 blockReduce2(float s1, float s2, float* sh) {
    const unsigned FULL = 0xffffffffu;
#pragma unroll
    for (int o = 16; o; o >>= 1) {
        s1 += __shfl_xor_sync(FULL, s1, o);
        s2 += __shfl_xor_sync(FULL, s2, o);
    }
    int lane = threadIdx.x & 31, w = threadIdx.x >> 5;
    if (lane == 0) { sh[w] = s1; sh[8 + w] = s2; }
    __syncthreads();
    float t1 = 0.f, t2 = 0.f;
#pragma unroll
    for (int i = 0; i < 8; i++) { t1 += sh[i]; t2 += sh[8 + i]; }
    __syncthreads();
    return make_float2(t1, t2);
}

// one pass over lo: emit bf16 hi/lo planes AND sum-of-LN-cores
__global__ __launch_bounds__(256) void split_normsum_kernel(const float* __restrict__ lo,
                                                            bf16* __restrict__ oh, bf16* __restrict__ ol) {
    __shared__ float sh[16];
    int row = blockIdx.x;
    int b = row / SS, s = row % SS;
    int t = threadIdx.x;
    float4 acc = make_float4(0.f, 0.f, 0.f, 0.f);
    for (int l = 0; l < LL; l++) {
        size_t ridx = ((size_t)((b*LL + l)*SS + s))*DD;
        float4 v = ((const float4*)(lo + ridx))[t];
        uint32_t h01, l01, h23, l23;
        split2u(v.x, v.y, h01, l01);
        split2u(v.z, v.w, h23, l23);
        ((uint32_t*)(oh + ridx))[2*t]     = h01;
        ((uint32_t*)(oh + ridx))[2*t + 1] = h23;
        ((uint32_t*)(ol + ridx))[2*t]     = l01;
        ((uint32_t*)(ol + ridx))[2*t + 1] = l23;
        float s1 = v.x + v.y + v.z + v.w;
        float s2 = v.x*v.x + v.y*v.y + v.z*v.z + v.w*v.w;
        float2 tot = blockReduce2(s1, s2, sh);
        float mu = tot.x * (1.f/DD);
        float var = tot.y * (1.f/DD) - mu*mu;
        float r = rsqrtf(var + EPSV);
        acc.x += (v.x - mu)*r; acc.y += (v.y - mu)*r;
        acc.z += (v.z - mu)*r; acc.w += (v.w - mu)*r;
    }
    ((float4*)(g_normsum + (size_t)row*DD))[t] = acc;
}

// ================= weight prep =================
__global__ __launch_bounds__(256) void wsplit_kernel(const float* __restrict__ W,
                                                     bf16* __restrict__ oh, bf16* __restrict__ ol,
                                                     int K, int N) {
    __shared__ float tile[32][33];
    int n0 = blockIdx.x * 32, k0 = blockIdx.y * 32;
    int tx = threadIdx.x & 31, ty = threadIdx.x >> 5;
#pragma unroll
    for (int i = 0; i < 4; i++)
        tile[ty + 8 * i][tx] = W[(size_t)(k0 + ty + 8 * i) * N + n0 + tx];
    __syncthreads();
#pragma unroll
    for (int i = 0; i < 4; i++) {
        float v = tile[tx][ty + 8 * i];
        bf16 hh, ll; split1(v, hh, ll);
        size_t o = (size_t)(n0 + ty + 8 * i) * K + k0 + tx;
        oh[o] = hh; ol[o] = ll;
    }
}

template<int SPLIT>
__global__ __launch_bounds__(256) void ln_residual_kernel(
        const float* __restrict__ resid, const float* __restrict__ pre,
        const float* __restrict__ bias, const float* __restrict__ gam,
        const float* __restrict__ bet, float* __restrict__ out,
        bf16* __restrict__ oh, bf16* __restrict__ ol) {
    __shared__ float sh[16];
    int row = blockIdx.x, t = threadIdx.x;
    float4 p = ((const float4*)(pre + (size_t)row*DD))[t];
    float4 bb = ((const float4*)bias)[t];
    p.x += bb.x; p.y += bb.y; p.z += bb.z; p.w += bb.w;
    float s1 = p.x + p.y + p.z + p.w;
    float s2 = p.x*p.x + p.y*p.y + p.z*p.z + p.w*p.w;
    float2 tot = blockReduce2(s1, s2, sh);
    float mu = tot.x * (1.f/DD);
    float var = tot.y * (1.f/DD) - mu*mu;
    float r = rsqrtf(var + EPSV);
    float4 gg = ((const float4*)gam)[t];
    float4 ee = ((const float4*)bet)[t];
    float4 rr = ((const float4*)(resid + (size_t)row*DD))[t];
    float4 o;
    o.x = rr.x + (p.x - mu)*r*gg.x + ee.x;
    o.y = rr.y + (p.y - mu)*r*gg.y + ee.y;
    o.z = rr.z + (p.z - mu)*r*gg.z + ee.z;
    o.w = rr.w + (p.w - mu)*r*gg.w + ee.w;
    ((float4*)(out + (size_t)row*DD))[t] = o;
    if (SPLIT) {
        uint32_t h01, l01, h23, l23;
        split2u(o.x, o.y, h01, l01);
        split2u(o.z, o.w, h23, l23);
        size_t i = (size_t)row * (DD/4) + t;
        ((uint32_t*)oh)[2 * i] = h01; ((uint32_t*)oh)[2 * i + 1] = h23;
        ((uint32_t*)ol)[2 * i] = l01; ((uint32_t*)ol)[2 * i + 1] = l23;
    }
}

// ================= host =================
static void* symaddr(const void* sym) { void* p; cudaGetSymbolAddress(&p, sym); return p; }

extern "C" void kernel_launch(void* const* d_in, const int* in_sizes, int n_in,
                              void* d_out, int out_size) {
    const float* x   = (const float*)d_in[0];
    const float* lo  = (const float*)d_in[1];
    const float* qW  = (const float*)d_in[2];
    const float* qb  = (const float*)d_in[3];
    const float* qg  = (const float*)d_in[4];
    const float* qbe = (const float*)d_in[5];
    const float* kW  = (const float*)d_in[6];
    const float* kb  = (const float*)d_in[7];
    const float* kg  = (const float*)d_in[8];
    const float* kbe = (const float*)d_in[9];
    const float* vW  = (const float*)d_in[10];
    const float* vb  = (const float*)d_in[11];
    const float* vg  = (const float*)d_in[12];
    const float* vbe = (const float*)d_in[13];
    const float* oW  = (const float*)d_in[14];
    const float* ob  = (const float*)d_in[15];
    const float* ang = (const float*)d_in[16];
    const float* anb = (const float*)d_in[17];
    const float* W1  = (const float*)d_in[18];
    const float* b1  = (const float*)d_in[19];
    const float* W2  = (const float*)d_in[20];
    const float* b2  = (const float*)d_in[21];
    const float* fng = (const float*)d_in[22];
    const float* fnb = (const float*)d_in[23];
    float* out = (float*)d_out;

    float* proj = (float*)symaddr(g_proj);
    float* out1 = (float*)symaddr(g_out1);
    float* ffn2 = (float*)symaddr(g_ffn2);
    __half* qkvp = (__half*)symaddr(g_qkvp);
    bf16 *loh = (bf16*)symaddr(g_loh), *lol = (bf16*)symaddr(g_lol);
    bf16 *wqh = (bf16*)symaddr(g_wqh), *wql = (bf16*)symaddr(g_wql);
    bf16 *wkh = (bf16*)symaddr(g_wkh), *wkl = (bf16*)symaddr(g_wkl);
    bf16 *wvh = (bf16*)symaddr(g_wvh), *wvl = (bf16*)symaddr(g_wvl);
    bf16 *woh = (bf16*)symaddr(g_woh), *wol = (bf16*)symaddr(g_wol);
    bf16 *w1h = (bf16*)symaddr(g_w1h), *w1l = (bf16*)symaddr(g_w1l);
    bf16 *w2h = (bf16*)symaddr(g_w2h), *w2l = (bf16*)symaddr(g_w2l);
    bf16 *cxh = (bf16*)symaddr(g_cxh), *cxl = (bf16*)symaddr(g_cxl);
    bf16 *o1h = (bf16*)symaddr(g_o1h), *o1l = (bf16*)symaddr(g_o1l);
    bf16 *f1h = (bf16*)symaddr(g_f1h), *f1l = (bf16*)symaddr(g_f1l);

    cudaFuncSetAttribute(gemm_mma<0>, cudaFuncAttributeMaxDynamicSharedMemorySize, GEMM_SMEM);
    cudaFuncSetAttribute(gemm_mma<1>, cudaFuncAttributeMaxDynamicSharedMemorySize, GEMM_SMEM);
    cudaFuncSetAttribute(gemm_qkvp,   cudaFuncAttributeMaxDynamicSharedMemorySize, GEMM_SMEM);
    cudaFuncSetAttribute(attn_mma,    cudaFuncAttributeMaxDynamicSharedMemorySize, AT_SMEM);

    // weight prep
    wsplit_kernel<<<dim3(DD/32, DD/32), 256>>>(qW, wqh, wql, DD, DD);
    wsplit_kernel<<<dim3(DD/32, DD/32), 256>>>(kW, wkh, wkl, DD, DD);
    wsplit_kernel<<<dim3(DD/32, DD/32), 256>>>(vW, wvh, wvl, DD, DD);
    wsplit_kernel<<<dim3(DD/32, DD/32), 256>>>(oW, woh, wol, DD, DD);
    wsplit_kernel<<<dim3(MLPD/32, DD/32), 256>>>(W1, w1h, w1l, DD, MLPD);
    wsplit_kernel<<<dim3(DD/32, MLPD/32), 256>>>(W2, w2h, w2l, MLPD, DD);

    // fused activation split + norm-core sum (one pass over lo)
    split_normsum_kernel<<<BSR, 256>>>(lo, loh, lol);

    // QKV partial GEMMs (z = ch*4 + l), then combine
    {
        QkvpArgs a;
        a.Ah = loh; a.Al = lol;
        a.Bh[0] = wqh; a.Bl[0] = wql; a.bias[0] = qb;
        a.Bh[1] = wkh; a.Bl[1] = wkl; a.bias[1] = kb;
        a.Bh[2] = wvh; a.Bl[2] = wvl; a.bias[2] = vb;
        a.P = qkvp;
        gemm_qkvp<<<dim3(DD/128, BSR/128, 12), 256, GEMM_SMEM>>>(a);
    }
    qkv_combine<<<BSR, 256>>>(qg, qbe, kg, kbe, vg, vbe,
        (bf16*)symaddr(g_qph), (bf16*)symaddr(g_qpl),
        (bf16*)symaddr(g_kph), (bf16*)symaddr(g_kpl),
        (bf16*)symaddr(g_vph), (bf16*)symaddr(g_vpl));

    attn_mma<<<dim3(SS/64, BB*HH), 128, AT_SMEM>>>();

    // attn out projection
    {
        GArgs a = {};
        a.Ah = cxh; a.Al = cxl; a.Bh = woh; a.Bl = wol;
        a.C = proj; a.N = DD; a.K = DD;
        gemm_mma<0><<<dim3(DD/128, BSR/128), 256, GEMM_SMEM>>>(a);
    }
    ln_residual_kernel<1><<<BSR, 256>>>(x, proj, ob, ang, anb, out1, o1h, o1l);

    // FFN1 with fused bias+gelu+split epilogue
    {
        GArgs a = {};
        a.Ah = o1h; a.Al = o1l; a.Bh = w1h; a.Bl = w1l;
        a.bias = b1; a.Ch = f1h; a.Cl = f1l; a.N = MLPD; a.K = DD;
        gemm_mma<1><<<dim3(MLPD/128, BSR/128), 256, GEMM_SMEM>>>(a);
    }
    // FFN2
    {
        GArgs a = {};
        a.Ah = f1h; a.Al = f1l; a.Bh = w2h; a.Bl = w2l;
        a.C = ffn2; a.N = DD; a.K = MLPD;
        gemm_mma<0><<<dim3(DD/128, BSR/128), 256, GEMM_SMEM>>>(a);
    }
    ln_residual_kernel<0><<<BSR, 256>>>(out1, ffn2, b2, fng, fnb, out, nullptr, nullptr);
}

// round 14
// speedup vs baseline: 7.6103x; 1.3600x over previous
#include <cuda_runtime.h>
#include <cuda_bf16.h>
#include <cuda_fp16.h>
#include <math.h>
#include <stdint.h>

typedef __nv_bfloat16 bf16;
typedef __half fp16;

#define BB 2
#define LL 4
#define SS 2048
#define DD 1024
#define HH 16
#define HDD 64
#define MLPD 4096
#define EPSV 1e-5f
#define BSR (BB*SS)
#define BLSR (BB*LL*SS)

// ================= scratch =================
static __device__ float g_normsum[(size_t)BSR*DD];
static __device__ float g_proj[(size_t)BSR*DD];
static __device__ float g_out1[(size_t)BSR*DD];
static __device__ float g_ffn2[(size_t)BSR*DD];
static __device__ fp16  g_qkvp[(size_t)12*BSR*DD];    // relu partials (fp16)

static __device__ fp16 g_lof[(size_t)BLSR*DD];         // activations, single fp16 plane
static __device__ fp16 g_cxf[(size_t)BSR*DD];          // ctx fp16
static __device__ fp16 g_o1f[(size_t)BSR*DD];          // out1 fp16
static __device__ fp16 g_f1f[(size_t)BSR*MLPD];        // gelu(ffn1) fp16
// weights: fp16 hi/lo, [N,K]
static __device__ fp16 g_wqh[(size_t)DD*DD],  g_wql[(size_t)DD*DD];
static __device__ fp16 g_wkh[(size_t)DD*DD],  g_wkl[(size_t)DD*DD];
static __device__ fp16 g_wvh[(size_t)DD*DD],  g_wvl[(size_t)DD*DD];
static __device__ fp16 g_woh[(size_t)DD*DD],  g_wol[(size_t)DD*DD];
static __device__ fp16 g_w1h[(size_t)MLPD*DD], g_w1l[(size_t)MLPD*DD];
static __device__ fp16 g_w2h[(size_t)DD*MLPD], g_w2l[(size_t)DD*MLPD];
// attention operands stay bf16 hi/lo [B,H,S,HD]
static __device__ bf16 g_qph[(size_t)BSR*DD], g_qpl[(size_t)BSR*DD];
static __device__ bf16 g_kph[(size_t)BSR*DD], g_kpl[(size_t)BSR*DD];
static __device__ bf16 g_vph[(size_t)BSR*DD], g_vpl[(size_t)BSR*DD];

// ================= PTX helpers =================
__device__ __forceinline__ uint32_t smem_u32(const void* p) {
    uint32_t a;
    asm("{ .reg .u64 t; cvta.to.shared.u64 t, %1; cvt.u32.u64 %0, t; }" : "=r"(a) : "l"(p));
    return a;
}
__device__ __forceinline__ void cpasync16(uint32_t dst, const void* src) {
    asm volatile("cp.async.cg.shared.global [%0], [%1], 16;" :: "r"(dst), "l"(src));
}
#define CP_COMMIT() asm volatile("cp.async.commit_group;" ::: "memory")
#define CP_WAIT0()  asm volatile("cp.async.wait_group 0;" ::: "memory")
#define CP_WAIT1()  asm volatile("cp.async.wait_group 1;" ::: "memory")
#define CP_WAIT2()  asm volatile("cp.async.wait_group 2;" ::: "memory")

__device__ __forceinline__ void ldsm4(uint32_t* r, uint32_t addr) {
    asm volatile("ldmatrix.sync.aligned.m8n8.x4.shared.b16 {%0,%1,%2,%3}, [%4];"
        : "=r"(r[0]), "=r"(r[1]), "=r"(r[2]), "=r"(r[3]) : "r"(addr));
}
__device__ __forceinline__ void ldsm4t(uint32_t* r, uint32_t addr) {
    asm volatile("ldmatrix.sync.aligned.m8n8.x4.trans.shared.b16 {%0,%1,%2,%3}, [%4];"
        : "=r"(r[0]), "=r"(r[1]), "=r"(r[2]), "=r"(r[3]) : "r"(addr));
}
// bf16 mma (attention)
__device__ __forceinline__ void mma16816(float* d, const uint32_t* a, const uint32_t* b) {
    asm volatile("mma.sync.aligned.m16n8k16.row.col.f32.bf16.bf16.f32 "
        "{%0,%1,%2,%3}, {%4,%5,%6,%7}, {%8,%9}, {%0,%1,%2,%3};"
        : "+f"(d[0]), "+f"(d[1]), "+f"(d[2]), "+f"(d[3])
        : "r"(a[0]), "r"(a[1]), "r"(a[2]), "r"(a[3]), "r"(b[0]), "r"(b[1]));
}
// fp16 mma (linear GEMMs)
__device__ __forceinline__ void mma16816h(float* d, const uint32_t* a, const uint32_t* b) {
    asm volatile("mma.sync.aligned.m16n8k16.row.col.f32.f16.f16.f32 "
        "{%0,%1,%2,%3}, {%4,%5,%6,%7}, {%8,%9}, {%0,%1,%2,%3};"
        : "+f"(d[0]), "+f"(d[1]), "+f"(d[2]), "+f"(d[3])
        : "r"(a[0]), "r"(a[1]), "r"(a[2]), "r"(a[3]), "r"(b[0]), "r"(b[1]));
}
__device__ __forceinline__ void split1(float v, bf16& h, bf16& l) {
    h = __float2bfloat16_rn(v);
    l = __float2bfloat16_rn(v - __bfloat162float(h));
}
__device__ __forceinline__ void split2u(float a, float b, uint32_t& hi, uint32_t& lo) {
    bf16 ha, la, hb, lb;
    split1(a, ha, la); split1(b, hb, lb);
    __nv_bfloat162 H(ha, hb), L(la, lb);
    hi = *(uint32_t*)&H; lo = *(uint32_t*)&L;
}
__device__ __forceinline__ void hsplit1(float v, fp16& h, fp16& l) {
    h = __float2half_rn(v);
    l = __float2half_rn(v - __half2float(h));
}

// ================= fp16 GEMM (128x128 tile, K chunk 32, 3-stage, 2-pass split) =================
// C[M,N] = A[M,K] @ W[K,N]; A fp16 [M,K]; W as B=[N,K] fp16 hi/lo.
#define PL_A  0
#define PL_BH 8192
#define PL_BL 16384
#define STAGE_B 24576
#define GEMM_SMEM (3*24576)

__device__ __forceinline__ void load_stage(uint32_t st,
        const fp16* __restrict__ A,
        const fp16* __restrict__ Bh, const fp16* __restrict__ Bl,
        int K, int kt, int tid) {
    const fp16* gsrc[3] = { A, Bh, Bl };
#pragma unroll
    for (int p = 0; p < 3; p++) {
        const fp16* g = gsrc[p] + kt * 32;
#pragma unroll
        for (int i = tid; i < 512; i += 256) {
            int r = i >> 2, c = i & 3;
            uint32_t d = st + p * 8192 + r * 64 + (((c ^ ((r >> 1) & 3))) << 4);
            cpasync16(d, g + (size_t)r * K + c * 8);
        }
    }
    CP_COMMIT();
}

__device__ __forceinline__ void gemm_core(uint32_t sb, float acc[4][4][4],
        const fp16* A, const fp16* Bh, const fp16* Bl,
        int K, int tid, const uint32_t* aRowOff, const uint32_t* aSwz,
        const uint32_t* bRowOff, const uint32_t* bSwz, int lchunk) {
    const int nch = K / 32;
    load_stage(sb, A, Bh, Bl, K, 0, tid);
    if (nch > 1) load_stage(sb + STAGE_B, A, Bh, Bl, K, 1, tid);
    for (int kt = 0; kt < nch; kt++) {
        int buf = kt % 3;
        if (kt + 2 < nch) {
            load_stage(sb + ((kt + 2) % 3) * STAGE_B, A, Bh, Bl, K, kt + 2, tid);
            CP_WAIT2();
        } else if (kt + 1 < nch) {
            CP_WAIT1();
        } else {
            CP_WAIT0();
        }
        __syncthreads();
        uint32_t st = sb + buf * STAGE_B;
#pragma unroll
        for (int s = 0; s < 2; s++) {
            uint32_t ch = (uint32_t)(s * 2 + lchunk);
            uint32_t aF[4][4], bHf[4][2], bLf[4][2];
#pragma unroll
            for (int mt = 0; mt < 4; mt++)
                ldsm4(aF[mt], st + PL_A + aRowOff[mt] + ((ch ^ aSwz[mt]) << 4));
#pragma unroll
            for (int p = 0; p < 2; p++) {
                uint32_t t[4];
                ldsm4(t, st + PL_BH + bRowOff[p] + ((ch ^ bSwz[p]) << 4));
                bHf[2*p][0] = t[0]; bHf[2*p][1] = t[2];
                bHf[2*p+1][0] = t[1]; bHf[2*p+1][1] = t[3];
                ldsm4(t, st + PL_BL + bRowOff[p] + ((ch ^ bSwz[p]) << 4));
                bLf[2*p][0] = t[0]; bLf[2*p][1] = t[2];
                bLf[2*p+1][0] = t[1]; bLf[2*p+1][1] = t[3];
            }
#pragma unroll
            for (int mt = 0; mt < 4; mt++)
#pragma unroll
                for (int nt = 0; nt < 4; nt++) mma16816h(acc[mt][nt], aF[mt], bHf[nt]);
#pragma unroll
            for (int mt = 0; mt < 4; mt++)
#pragma unroll
                for (int nt = 0; nt < 4; nt++) mma16816h(acc[mt][nt], aF[mt], bLf[nt]);
        }
        __syncthreads();
    }
}

struct GArgs {
    const fp16 *A, *Bh, *Bl;
    float* C;
    const float* bias;
    fp16* Cf;
    int N, K;
};

// EPI 0: fp32 C.  EPI 1: gelu(acc+bias) -> fp16 plane.
template<int EPI>
__global__ __launch_bounds__(256, 2) void gemm_mma(const GArgs args) {
    extern __shared__ char smem[];
    uint32_t sb = smem_u32(smem);
    int tid = threadIdx.x, lane = tid & 31, wid = tid >> 5;
    int wm = wid >> 2, wn = wid & 3;
    const int K = args.K, N = args.N;
    const fp16* A  = args.A  + (size_t)(blockIdx.y * 128) * K;
    const fp16* Bh = args.Bh + (size_t)(blockIdx.x * 128) * K;
    const fp16* Bl = args.Bl + (size_t)(blockIdx.x * 128) * K;

    float acc[4][4][4];
#pragma unroll
    for (int i = 0; i < 4; i++)
#pragma unroll
        for (int j = 0; j < 4; j++)
#pragma unroll
            for (int c = 0; c < 4; c++) acc[i][j][c] = 0.f;

    int lrow = lane & 15, lchunk = lane >> 4;
    uint32_t aRowOff[4], aSwz[4], bRowOff[2], bSwz[2];
#pragma unroll
    for (int mt = 0; mt < 4; mt++) {
        int r = wm * 64 + mt * 16 + lrow;
        aRowOff[mt] = r * 64; aSwz[mt] = (r >> 1) & 3;
    }
#pragma unroll
    for (int p = 0; p < 2; p++) {
        int r = wn * 32 + p * 16 + lrow;
        bRowOff[p] = r * 64; bSwz[p] = (r >> 1) & 3;
    }

    gemm_core(sb, acc, A, Bh, Bl, K, tid, aRowOff, aSwz, bRowOff, bSwz, lchunk);

    int g = lane >> 2, tc = lane & 3;
#pragma unroll
    for (int mt = 0; mt < 4; mt++) {
        int row = blockIdx.y * 128 + wm * 64 + mt * 16 + g;
#pragma unroll
        for (int nt = 0; nt < 4; nt++) {
            int col = blockIdx.x * 128 + wn * 32 + nt * 8 + tc * 2;
            if (EPI == 0) {
                *(float2*)&args.C[(size_t)row * N + col]       = make_float2(acc[mt][nt][0], acc[mt][nt][1]);
                *(float2*)&args.C[(size_t)(row + 8) * N + col] = make_float2(acc[mt][nt][2], acc[mt][nt][3]);
            } else {
                float b0 = args.bias[col], b1 = args.bias[col + 1];
                float v0 = acc[mt][nt][0] + b0, v1 = acc[mt][nt][1] + b1;
                float v2 = acc[mt][nt][2] + b0, v3 = acc[mt][nt][3] + b1;
                v0 *= normcdff(v0); v1 *= normcdff(v1); v2 *= normcdff(v2); v3 *= normcdff(v3);
                *(__half2*)&args.Cf[(size_t)row * N + col]       = __floats2half2_rn(v0, v1);
                *(__half2*)&args.Cf[(size_t)(row + 8) * N + col] = __floats2half2_rn(v2, v3);
            }
        }
    }
}

// ================= QKV partial GEMM: z = ch*4 + l, relu(acc+bias) -> fp16 partial =================
struct QkvpArgs {
    const fp16 *A;                       // [BLSR, DD] fp16
    const fp16 *Bh[3], *Bl[3];
    const float *bias[3];
    fp16* P;                             // [12][BSR*DD]
};

__global__ __launch_bounds__(256, 2) void gemm_qkvp(const QkvpArgs args) {
    extern __shared__ char smem[];
    uint32_t sb = smem_u32(smem);
    int tid = threadIdx.x, lane = tid & 31, wid = tid >> 5;
    int wm = wid >> 2, wn = wid & 3;
    int z = blockIdx.z, zc = z >> 2, l = z & 3;
    int by = blockIdx.y;
    int b = (by * 128) / SS;
    int s0 = by * 128 - b * SS;
    const fp16* A  = args.A + ((size_t)((b * LL + l) * SS + s0)) * DD;
    const fp16* Bh = args.Bh[zc] + (size_t)(blockIdx.x * 128) * DD;
    const fp16* Bl = args.Bl[zc] + (size_t)(blockIdx.x * 128) * DD;

    float acc[4][4][4];
#pragma unroll
    for (int i = 0; i < 4; i++)
#pragma unroll
        for (int j = 0; j < 4; j++)
#pragma unroll
            for (int c = 0; c < 4; c++) acc[i][j][c] = 0.f;

    int lrow = lane & 15, lchunk = lane >> 4;
    uint32_t aRowOff[4], aSwz[4], bRowOff[2], bSwz[2];
#pragma unroll
    for (int mt = 0; mt < 4; mt++) {
        int r = wm * 64 + mt * 16 + lrow;
        aRowOff[mt] = r * 64; aSwz[mt] = (r >> 1) & 3;
    }
#pragma unroll
    for (int p = 0; p < 2; p++) {
        int r = wn * 32 + p * 16 + lrow;
        bRowOff[p] = r * 64; bSwz[p] = (r >> 1) & 3;
    }

    gemm_core(sb, acc, A, Bh, Bl, DD, tid, aRowOff, aSwz, bRowOff, bSwz, lchunk);

    fp16* P = args.P + (size_t)z * BSR * DD;
    int g = lane >> 2, tc = lane & 3;
#pragma unroll
    for (int mt = 0; mt < 4; mt++) {
        int row = by * 128 + wm * 64 + mt * 16 + g;
#pragma unroll
        for (int nt = 0; nt < 4; nt++) {
            int col = blockIdx.x * 128 + wn * 32 + nt * 8 + tc * 2;
            float b0 = args.bias[zc][col], b1 = args.bias[zc][col + 1];
            *(__half2*)&P[(size_t)row * DD + col] =
                __floats2half2_rn(fmaxf(acc[mt][nt][0] + b0, 0.f), fmaxf(acc[mt][nt][1] + b1, 0.f));
            *(__half2*)&P[(size_t)(row + 8) * DD + col] =
                __floats2half2_rn(fmaxf(acc[mt][nt][2] + b0, 0.f), fmaxf(acc[mt][nt][3] + b1, 0.f));
        }
    }
}

// ================= combine partials + g*normsum + L*be -> head-layout bf16 hi/lo =================
__global__ __launch_bounds__(256) void qkv_combine(
        const float* __restrict__ gq, const float* __restrict__ beq,
        const float* __restrict__ gk, const float* __restrict__ bek,
        const float* __restrict__ gv, const float* __restrict__ bev,
        bf16* __restrict__ qh, bf16* __restrict__ ql,
        bf16* __restrict__ kh, bf16* __restrict__ kl,
        bf16* __restrict__ vh, bf16* __restrict__ vl) {
    int row = blockIdx.x;                 // b*S+s
    int b = row / SS, s = row % SS;
    int t = threadIdx.x;
    int d0 = t * 4;
    int h = d0 >> 6, hd = d0 & 63;
    size_t oIdx = ((size_t)(b * HH + h) * SS + s) * HDD + hd;
    float4 ns = ((const float4*)(g_normsum + (size_t)row * DD))[t];

    const float* gain_[3] = { gq, gk, gv };
    const float* beta_[3] = { beq, bek, bev };
    bf16* oh_[3] = { qh, kh, vh };
    bf16* ol_[3] = { ql, kl, vl };

#pragma unroll
    for (int c = 0; c < 3; c++) {
        float4 a = make_float4(0.f, 0.f, 0.f, 0.f);
#pragma unroll
        for (int l = 0; l < LL; l++) {
            const fp16* P = g_qkvp + ((size_t)(c * 4 + l) * BSR + row) * DD;
            uint2 pr = ((const uint2*)P)[t];
            float2 f01 = __half22float2(*(__half2*)&pr.x);
            float2 f23 = __half22float2(*(__half2*)&pr.y);
            a.x += f01.x; a.y += f01.y; a.z += f23.x; a.w += f23.y;
        }
        float4 gg = ((const float4*)gain_[c])[t];
        float4 ee = ((const float4*)beta_[c])[t];
        float v0 = a.x + gg.x * ns.x + LL * ee.x;
        float v1 = a.y + gg.y * ns.y + LL * ee.y;
        float v2 = a.z + gg.z * ns.z + LL * ee.z;
        float v3 = a.w + gg.w * ns.w + LL * ee.w;
        uint32_t h01, l01, h23, l23;
        split2u(v0, v1, h01, l01);
        split2u(v2, v3, h23, l23);
        *(uint32_t*)&oh_[c][oIdx]     = h01;
        *(uint32_t*)&ol_[c][oIdx]     = l01;
        *(uint32_t*)&oh_[c][oIdx + 2] = h23;
        *(uint32_t*)&ol_[c][oIdx + 2] = l23;
    }
}

// ================= tensor-core flash attention (bf16 x3, unchanged math) =================
#define AT_STAGE 32768
#define AT_SMEM  65536

__device__ __forceinline__ void attn_load_kv(uint32_t st, int bh, int kt, int tid) {
    const bf16* src[4] = {
        g_kph + ((size_t)bh * SS + kt * 64) * HDD,
        g_kpl + ((size_t)bh * SS + kt * 64) * HDD,
        g_vph + ((size_t)bh * SS + kt * 64) * HDD,
        g_vpl + ((size_t)bh * SS + kt * 64) * HDD };
#pragma unroll
    for (int p = 0; p < 4; p++) {
#pragma unroll
        for (int i = tid; i < 512; i += 128) {
            int r = i >> 3, c = i & 7;
            uint32_t d = st + p * 8192 + r * 128 + (((c ^ (r & 7))) << 4);
            cpasync16(d, src[p] + (size_t)r * HDD + c * 8);
        }
    }
    CP_COMMIT();
}

__global__ __launch_bounds__(128, 3) void attn_mma() {
    extern __shared__ char smem[];
    uint32_t sb = smem_u32(smem);
    int tid = threadIdx.x, lane = tid & 31, wid = tid >> 5;
    int qt = blockIdx.x, bh = blockIdx.y;
    int b = bh / HH, h = bh % HH;
    int g = lane >> 2, tc = lane & 3;
    int lrow = lane & 15, lchunk = lane >> 4;

    {
        const bf16* qsrc[2] = {
            g_qph + ((size_t)bh * SS + qt * 64) * HDD,
            g_qpl + ((size_t)bh * SS + qt * 64) * HDD };
#pragma unroll
        for (int p = 0; p < 2; p++)
#pragma unroll
            for (int i = tid; i < 512; i += 128) {
                int r = i >> 3, c = i & 7;
                uint32_t d = sb + p * 8192 + r * 128 + (((c ^ (r & 7))) << 4);
                cpasync16(d, qsrc[p] + (size_t)r * HDD + c * 8);
            }
        CP_COMMIT(); CP_WAIT0();
        __syncthreads();
    }
    uint32_t qhF[4][4], qlF[4][4];
#pragma unroll
    for (int ks = 0; ks < 4; ks++) {
        int r = wid * 16 + lrow;
        uint32_t cc = (uint32_t)(ks * 2 + lchunk);
        uint32_t off = r * 128 + ((cc ^ (r & 7)) << 4);
        ldsm4(qhF[ks], sb + off);
        ldsm4(qlF[ks], sb + 8192 + off);
    }
    __syncthreads();

    float o[8][4];
#pragma unroll
    for (int i = 0; i < 8; i++)
#pragma unroll
        for (int c = 0; c < 4; c++) o[i][c] = 0.f;
    float m0 = -INFINITY, m1 = -INFINITY, l0 = 0.f, l1 = 0.f;
    const float ls = 0.125f * 1.44269504088896f;

    attn_load_kv(sb, bh, 0, tid);

    for (int kt = 0; kt < SS / 64; kt++) {
        int buf = kt & 1;
        if (kt + 1 < SS / 64) {
            attn_load_kv(sb + (buf ^ 1) * AT_STAGE, bh, kt + 1, tid);
            CP_WAIT1();
        } else {
            CP_WAIT0();
        }
        __syncthreads();
        uint32_t st = sb + buf * AT_STAGE;

        float S[8][4];
#pragma unroll
        for (int i = 0; i < 8; i++)
#pragma unroll
            for (int c = 0; c < 4; c++) S[i][c] = 0.f;
#pragma unroll
        for (int np = 0; np < 4; np++) {
            int r = np * 16 + lrow;
#pragma unroll
            for (int ks = 0; ks < 4; ks++) {
                uint32_t cc = (uint32_t)(ks * 2 + lchunk);
                uint32_t off = r * 128 + ((cc ^ (r & 7)) << 4);
                uint32_t tH[4], tL[4];
                ldsm4(tH, st + off);
                ldsm4(tL, st + 8192 + off);
                uint32_t b0h[2] = { tH[0], tH[2] }, b1h[2] = { tH[1], tH[3] };
                uint32_t b0l[2] = { tL[0], tL[2] }, b1l[2] = { tL[1], tL[3] };
                mma16816(S[2*np],   qhF[ks], b0h);
                mma16816(S[2*np+1], qhF[ks], b1h);
                mma16816(S[2*np],   qhF[ks], b0l);
                mma16816(S[2*np+1], qhF[ks], b1l);
                mma16816(S[2*np],   qlF[ks], b0h);
                mma16816(S[2*np+1], qlF[ks], b1h);
            }
        }

        float tm0 = -INFINITY, tm1 = -INFINITY;
#pragma unroll
        for (int i = 0; i < 8; i++) {
            S[i][0] *= ls; S[i][1] *= ls; S[i][2] *= ls; S[i][3] *= ls;
            tm0 = fmaxf(tm0, fmaxf(S[i][0], S[i][1]));
            tm1 = fmaxf(tm1, fmaxf(S[i][2], S[i][3]));
        }
        tm0 = fmaxf(tm0, __shfl_xor_sync(0xffffffffu, tm0, 1));
        tm0 = fmaxf(tm0, __shfl_xor_sync(0xffffffffu, tm0, 2));
        tm1 = fmaxf(tm1, __shfl_xor_sync(0xffffffffu, tm1, 1));
        tm1 = fmaxf(tm1, __shfl_xor_sync(0xffffffffu, tm1, 2));
        float nm0 = fmaxf(m0, tm0), nm1 = fmaxf(m1, tm1);
        float c0 = exp2f(m0 - nm0), c1 = exp2f(m1 - nm1);
        float ps0 = 0.f, ps1 = 0.f;
#pragma unroll
        for (int i = 0; i < 8; i++) {
            S[i][0] = exp2f(S[i][0] - nm0); S[i][1] = exp2f(S[i][1] - nm0);
            S[i][2] = exp2f(S[i][2] - nm1); S[i][3] = exp2f(S[i][3] - nm1);
            ps0 += S[i][0] + S[i][1];
            ps1 += S[i][2] + S[i][3];
        }
        ps0 += __shfl_xor_sync(0xffffffffu, ps0, 1);
        ps0 += __shfl_xor_sync(0xffffffffu, ps0, 2);
        ps1 += __shfl_xor_sync(0xffffffffu, ps1, 1);
        ps1 += __shfl_xor_sync(0xffffffffu, ps1, 2);
        l0 = l0 * c0 + ps0; l1 = l1 * c1 + ps1;
        m0 = nm0; m1 = nm1;
#pragma unroll
        for (int i = 0; i < 8; i++) {
            o[i][0] *= c0; o[i][1] *= c0; o[i][2] *= c1; o[i][3] *= c1;
        }

        uint32_t pH[4][4], pL[4][4];
#pragma unroll
        for (int j = 0; j < 4; j++) {
            split2u(S[2*j][0],   S[2*j][1],   pH[j][0], pL[j][0]);
            split2u(S[2*j][2],   S[2*j][3],   pH[j][1], pL[j][1]);
            split2u(S[2*j+1][0], S[2*j+1][1], pH[j][2], pL[j][2]);
            split2u(S[2*j+1][2], S[2*j+1][3], pH[j][3], pL[j][3]);
        }

#pragma unroll
        for (int j = 0; j < 4; j++) {
            int r = j * 16 + lrow;
#pragma unroll
            for (int dp = 0; dp < 4; dp++) {
                uint32_t cc = (uint32_t)(dp * 2 + lchunk);
                uint32_t off = r * 128 + ((cc ^ (r & 7)) << 4);
                uint32_t tH[4], tL[4];
                ldsm4t(tH, st + 16384 + off);
                ldsm4t(tL, st + 24576 + off);
                uint32_t b0h[2] = { tH[0], tH[1] }, b1h[2] = { tH[2], tH[3] };
                uint32_t b0l[2] = { tL[0], tL[1] }, b1l[2] = { tL[2], tL[3] };
                mma16816(o[2*dp],   pH[j], b0h);
                mma16816(o[2*dp+1], pH[j], b1h);
                mma16816(o[2*dp],   pH[j], b0l);
                mma16816(o[2*dp+1], pH[j], b1l);
                mma16816(o[2*dp],   pL[j], b0h);
                mma16816(o[2*dp+1], pL[j], b1h);
            }
        }
        __syncthreads();
    }

    // epilogue: normalize, write ctx as single fp16 plane
    float il0 = 1.f / l0, il1 = 1.f / l1;
    int srow = qt * 64 + wid * 16 + g;
#pragma unroll
    for (int nt = 0; nt < 8; nt++) {
        int col = h * HDD + nt * 8 + tc * 2;
        float v0 = o[nt][0] * il0, v1 = o[nt][1] * il0;
        float v2 = o[nt][2] * il1, v3 = o[nt][3] * il1;
        size_t r0 = (size_t)(b * SS + srow) * DD + col;
        size_t r1 = (size_t)(b * SS + srow + 8) * DD + col;
        *(__half2*)&g_cxf[r0] = __floats2half2_rn(v0, v1);
        *(__half2*)&g_cxf[r1] = __floats2half2_rn(v2, v3);
    }
}

// ================= fused split + normsum =================
__device__ __forceinline__ float2 blockReduce2(float s1, float s2, float* sh) {
    const unsigned FULL = 0xffffffffu;
#pragma unroll
    for (int o = 16; o; o >>= 1) {
        s1 += __shfl_xor_sync(FULL, s1, o);
        s2 += __shfl_xor_sync(FULL, s2, o);
    }
    int lane = threadIdx.x & 31, w = threadIdx.x >> 5;
    if (lane == 0) { sh[w] = s1; sh[8 + w] = s2; }
    __syncthreads();
    float t1 = 0.f, t2 = 0.f;
#pragma unroll
    for (int i = 0; i < 8; i++) { t1 += sh[i]; t2 += sh[8 + i]; }
    __syncthreads();
    return make_float2(t1, t2);
}

// one pass over lo: emit fp16 plane AND sum-of-LN-cores
__global__ __launch_bounds__(256) void split_normsum_kernel(const float* __restrict__ lo,
                                                            fp16* __restrict__ of) {
    __shared__ float sh[16];
    int row = blockIdx.x;
    int b = row / SS, s = row % SS;
    int t = threadIdx.x;
    float4 acc = make_float4(0.f, 0.f, 0.f, 0.f);
    for (int l = 0; l < LL; l++) {
        size_t ridx = ((size_t)((b*LL + l)*SS + s))*DD;
        float4 v = ((const float4*)(lo + ridx))[t];
        ((__half2*)(of + ridx))[2*t]     = __floats2half2_rn(v.x, v.y);
        ((__half2*)(of + ridx))[2*t + 1] = __floats2half2_rn(v.z, v.w);
        float s1 = v.x + v.y + v.z + v.w;
        float s2 = v.x*v.x + v.y*v.y + v.z*v.z + v.w*v.w;
        float2 tot = blockReduce2(s1, s2, sh);
        float mu = tot.x * (1.f/DD);
        float var = tot.y * (1.f/DD) - mu*mu;
        float r = rsqrtf(var + EPSV);
        acc.x += (v.x - mu)*r; acc.y += (v.y - mu)*r;
        acc.z += (v.z - mu)*r; acc.w += (v.w - mu)*r;
    }
    ((float4*)(g_normsum + (size_t)row*DD))[t] = acc;
}

// ================= weight prep: W [K,N] fp32 -> [N,K] fp16 hi/lo =================
__global__ __launch_bounds__(256) void wsplit_kernel(const float* __restrict__ W,
                                                     fp16* __restrict__ oh, fp16* __restrict__ ol,
                                                     int K, int N) {
    __shared__ float tile[32][33];
    int n0 = blockIdx.x * 32, k0 = blockIdx.y * 32;
    int tx = threadIdx.x & 31, ty = threadIdx.x >> 5;
#pragma unroll
    for (int i = 0; i < 4; i++)
        tile[ty + 8 * i][tx] = W[(size_t)(k0 + ty + 8 * i) * N + n0 + tx];
    __syncthreads();
#pragma unroll
    for (int i = 0; i < 4; i++) {
        float v = tile[tx][ty + 8 * i];
        fp16 hh, ll; hsplit1(v, hh, ll);
        size_t o = (size_t)(n0 + ty + 8 * i) * K + k0 + tx;
        oh[o] = hh; ol[o] = ll;
    }
}

// residual + LN; SPLIT=1 additionally emits fp16 plane
template<int SPLIT>
__global__ __launch_bounds__(256) void ln_residual_kernel(
        const float* __restrict__ resid, const float* __restrict__ pre,
        const float* __restrict__ bias, const float* __restrict__ gam,
        const float* __restrict__ bet, float* __restrict__ out,
        fp16* __restrict__ of) {
    __shared__ float sh[16];
    int row = blockIdx.x, t = threadIdx.x;
    float4 p = ((const float4*)(pre + (size_t)row*DD))[t];
    float4 bb = ((const float4*)bias)[t];
    p.x += bb.x; p.y += bb.y; p.z += bb.z; p.w += bb.w;
    float s1 = p.x + p.y + p.z + p.w;
    float s2 = p.x*p.x + p.y*p.y + p.z*p.z + p.w*p.w;
    float2 tot = blockReduce2(s1, s2, sh);
    float mu = tot.x * (1.f/DD);
    float var = tot.y * (1.f/DD) - mu*mu;
    float r = rsqrtf(var + EPSV);
    float4 gg = ((const float4*)gam)[t];
    float4 ee = ((const float4*)bet)[t];
    float4 rr = ((const float4*)(resid + (size_t)row*DD))[t];
    float4 o;
    o.x = rr.x + (p.x - mu)*r*gg.x + ee.x;
    o.y = rr.y + (p.y - mu)*r*gg.y + ee.y;
    o.z = rr.z + (p.z - mu)*r*gg.z + ee.z;
    o.w = rr.w + (p.w - mu)*r*gg.w + ee.w;
    ((float4*)(out + (size_t)row*DD))[t] = o;
    if (SPLIT) {
        size_t i = (size_t)row * (DD/4) + t;
        ((__half2*)of)[2 * i]     = __floats2half2_rn(o.x, o.y);
        ((__half2*)of)[2 * i + 1] = __floats2half2_rn(o.z, o.w);
    }
}

// ================= host =================
static void* symaddr(const void* sym) { void* p; cudaGetSymbolAddress(&p, sym); return p; }

extern "C" void kernel_launch(void* const* d_in, const int* in_sizes, int n_in,
                              void* d_out, int out_size) {
    const float* x   = (const float*)d_in[0];
    const float* lo  = (const float*)d_in[1];
    const float* qW  = (const float*)d_in[2];
    const float* qb  = (const float*)d_in[3];
    const float* qg  = (const float*)d_in[4];
    const float* qbe = (const float*)d_in[5];
    const float* kW  = (const float*)d_in[6];
    const float* kb  = (const float*)d_in[7];
    const float* kg  = (const float*)d_in[8];
    const float* kbe = (const float*)d_in[9];
    const float* vW  = (const float*)d_in[10];
    const float* vb  = (const float*)d_in[11];
    const float* vg  = (const float*)d_in[12];
    const float* vbe = (const float*)d_in[13];
    const float* oW  = (const float*)d_in[14];
    const float* ob  = (const float*)d_in[15];
    const float* ang = (const float*)d_in[16];
    const float* anb = (const float*)d_in[17];
    const float* W1  = (const float*)d_in[18];
    const float* b1  = (const float*)d_in[19];
    const float* W2  = (const float*)d_in[20];
    const float* b2  = (const float*)d_in[21];
    const float* fng = (const float*)d_in[22];
    const float* fnb = (const float*)d_in[23];
    float* out = (float*)d_out;

    float* proj = (float*)symaddr(g_proj);
    float* out1 = (float*)symaddr(g_out1);
    float* ffn2 = (float*)symaddr(g_ffn2);
    fp16* qkvp = (fp16*)symaddr(g_qkvp);
    fp16* lof = (fp16*)symaddr(g_lof);
    fp16* cxf = (fp16*)symaddr(g_cxf);
    fp16* o1f = (fp16*)symaddr(g_o1f);
    fp16* f1f = (fp16*)symaddr(g_f1f);
    fp16 *wqh = (fp16*)symaddr(g_wqh), *wql = (fp16*)symaddr(g_wql);
    fp16 *wkh = (fp16*)symaddr(g_wkh), *wkl = (fp16*)symaddr(g_wkl);
    fp16 *wvh = (fp16*)symaddr(g_wvh), *wvl = (fp16*)symaddr(g_wvl);
    fp16 *woh = (fp16*)symaddr(g_woh), *wol = (fp16*)symaddr(g_wol);
    fp16 *w1h = (fp16*)symaddr(g_w1h), *w1l = (fp16*)symaddr(g_w1l);
    fp16 *w2h = (fp16*)symaddr(g_w2h), *w2l = (fp16*)symaddr(g_w2l);

    cudaFuncSetAttribute(gemm_mma<0>, cudaFuncAttributeMaxDynamicSharedMemorySize, GEMM_SMEM);
    cudaFuncSetAttribute(gemm_mma<1>, cudaFuncAttributeMaxDynamicSharedMemorySize, GEMM_SMEM);
    cudaFuncSetAttribute(gemm_qkvp,   cudaFuncAttributeMaxDynamicSharedMemorySize, GEMM_SMEM);
    cudaFuncSetAttribute(attn_mma,    cudaFuncAttributeMaxDynamicSharedMemorySize, AT_SMEM);

    // weight prep
    wsplit_kernel<<<dim3(DD/32, DD/32), 256>>>(qW, wqh, wql, DD, DD);
    wsplit_kernel<<<dim3(DD/32, DD/32), 256>>>(kW, wkh, wkl, DD, DD);
    wsplit_kernel<<<dim3(DD/32, DD/32), 256>>>(vW, wvh, wvl, DD, DD);
    wsplit_kernel<<<dim3(DD/32, DD/32), 256>>>(oW, woh, wol, DD, DD);
    wsplit_kernel<<<dim3(MLPD/32, DD/32), 256>>>(W1, w1h, w1l, DD, MLPD);
    wsplit_kernel<<<dim3(DD/32, MLPD/32), 256>>>(W2, w2h, w2l, MLPD, DD);

    // fused activation fp16 convert + norm-core sum (one pass over lo)
    split_normsum_kernel<<<BSR, 256>>>(lo, lof);

    // QKV partial GEMMs (z = ch*4 + l), then combine
    {
        QkvpArgs a;
        a.A = lof;
        a.Bh[0] = wqh; a.Bl[0] = wql; a.bias[0] = qb;
        a.Bh[1] = wkh; a.Bl[1] = wkl; a.bias[1] = kb;
        a.Bh[2] = wvh; a.Bl[2] = wvl; a.bias[2] = vb;
        a.P = qkvp;
        gemm_qkvp<<<dim3(DD/128, BSR/128, 12), 256, GEMM_SMEM>>>(a);
    }
    qkv_combine<<<BSR, 256>>>(qg, qbe, kg, kbe, vg, vbe,
        (bf16*)symaddr(g_qph), (bf16*)symaddr(g_qpl),
        (bf16*)symaddr(g_kph), (bf16*)symaddr(g_kpl),
        (bf16*)symaddr(g_vph), (bf16*)symaddr(g_vpl));

    attn_mma<<<dim3(SS/64, BB*HH), 128, AT_SMEM>>>();

    // attn out projection (fp16 A = ctx)
    {
        GArgs a = {};
        a.A = cxf; a.Bh = woh; a.Bl = wol;
        a.C = proj; a.N = DD; a.K = DD;
        gemm_mma<0><<<dim3(DD/128, BSR/128), 256, GEMM_SMEM>>>(a);
    }
    ln_residual_kernel<1><<<BSR, 256>>>(x, proj, ob, ang, anb, out1, o1f);

    // FFN1 with fused bias+gelu -> fp16 plane
    {
        GArgs a = {};
        a.A = o1f; a.Bh = w1h; a.Bl = w1l;
        a.bias = b1; a.Cf = f1f; a.N = MLPD; a.K = DD;
        gemm_mma<1><<<dim3(MLPD/128, BSR/128), 256, GEMM_SMEM>>>(a);
    }
    // FFN2
    {
        GArgs a = {};
        a.A = f1f; a.Bh = w2h; a.Bl = w2l;
        a.C = ffn2; a.N = DD; a.K = MLPD;
        gemm_mma<0><<<dim3(DD/128, BSR/128), 256, GEMM_SMEM>>>(a);
    }
    ln_residual_kernel<0><<<BSR, 256>>>(out1, ffn2, b2, fng, fnb, out, nullptr);
}